// round 2
// baseline (speedup 1.0000x reference)
#include <cuda_runtime.h>
#include <cstdint>

// Problem constants
#define BB 2
#define SS 2048
#define DD 1024
#define HH 16
#define DHD 64
#define MTOT (BB*SS)   // 4096

// Scratch (allocation-free rule: __device__ globals)
__device__ float g_Q[BB*SS*DD];
__device__ float g_K[BB*SS*DD];
__device__ float g_V[BB*SS*DD];
__device__ float g_O[BB*SS*DD];
__device__ float g_maskadd[BB*SS];

// ---------------------------------------------------------------------------
// Mask conversion: robust to mask being int32 (expected: harness upcasts bool)
// or packed uint8. Detection: scan first 64 words; int32 0/1 data never has a
// word value > 1, packed-uint8 random bools do with overwhelming probability.
// ---------------------------------------------------------------------------
__global__ void mask_convert(const void* __restrict__ mask_raw,
                             float* __restrict__ madd)
{
    const unsigned* mw = (const unsigned*)mask_raw;
    bool is_int32 = true;
    #pragma unroll
    for (int i = 0; i < 64; i++)         // 256 bytes, safe under both layouts
        if (mw[i] > 1u) is_int32 = false;

    const int idx = blockIdx.x * blockDim.x + threadIdx.x;
    if (idx < BB * SS) {
        int m = is_int32 ? (int)mw[idx]
                         : (int)((const unsigned char*)mask_raw)[idx];
        madd[idx] = m ? 0.0f : -1e9f;
    }
}

// ---------------------------------------------------------------------------
// SGEMM: C[M,N] = A[M,K] @ W[N,K]^T + bias[N],  M=4096, N=1024, K=1024 fixed.
// 128x128 block tile, K-chunk 8, 256 threads, 8x8 per thread.
// ---------------------------------------------------------------------------
__global__ __launch_bounds__(256) void sgemm_bias(
    const float* __restrict__ A, const float* __restrict__ Wt,
    const float* __restrict__ bias, float* __restrict__ C)
{
    const int K = 1024, N = 1024;
    __shared__ float As[8][132];
    __shared__ float Bs[8][132];

    const int m0 = blockIdx.y * 128;
    const int n0 = blockIdx.x * 128;
    const int t  = threadIdx.x;
    const int tx = t & 15;          // 0..15  -> n micro
    const int ty = t >> 4;          // 0..15  -> m micro
    const int lrow = t >> 1;        // 0..127 (load row)
    const int lk4  = (t & 1) * 4;   // 0 or 4 (load k offset)

    float acc[8][8];
    #pragma unroll
    for (int i = 0; i < 8; i++)
        #pragma unroll
        for (int j = 0; j < 8; j++) acc[i][j] = 0.0f;

    for (int k0 = 0; k0 < K; k0 += 8) {
        float4 av = *(const float4*)&A [((size_t)(m0 + lrow))*K + k0 + lk4];
        float4 bv = *(const float4*)&Wt[((size_t)(n0 + lrow))*K + k0 + lk4];
        __syncthreads();          // protect previous iteration's reads
        As[lk4+0][lrow] = av.x; As[lk4+1][lrow] = av.y;
        As[lk4+2][lrow] = av.z; As[lk4+3][lrow] = av.w;
        Bs[lk4+0][lrow] = bv.x; Bs[lk4+1][lrow] = bv.y;
        Bs[lk4+2][lrow] = bv.z; Bs[lk4+3][lrow] = bv.w;
        __syncthreads();

        #pragma unroll
        for (int kk = 0; kk < 8; kk++) {
            float a[8], b[8];
            *(float4*)(a)   = *(const float4*)&As[kk][ty*8];
            *(float4*)(a+4) = *(const float4*)&As[kk][ty*8+4];
            *(float4*)(b)   = *(const float4*)&Bs[kk][tx*8];
            *(float4*)(b+4) = *(const float4*)&Bs[kk][tx*8+4];
            #pragma unroll
            for (int i = 0; i < 8; i++)
                #pragma unroll
                for (int j = 0; j < 8; j++)
                    acc[i][j] = fmaf(a[i], b[j], acc[i][j]);
        }
    }

    float bvals[8];
    #pragma unroll
    for (int j = 0; j < 8; j++) bvals[j] = bias[n0 + tx*8 + j];

    #pragma unroll
    for (int i = 0; i < 8; i++) {
        const size_t row = (size_t)(m0 + ty*8 + i);
        float4 o0, o1;
        o0.x = acc[i][0] + bvals[0]; o0.y = acc[i][1] + bvals[1];
        o0.z = acc[i][2] + bvals[2]; o0.w = acc[i][3] + bvals[3];
        o1.x = acc[i][4] + bvals[4]; o1.y = acc[i][5] + bvals[5];
        o1.z = acc[i][6] + bvals[6]; o1.w = acc[i][7] + bvals[7];
        *(float4*)&C[row*N + n0 + tx*8 + 0] = o0;
        *(float4*)&C[row*N + n0 + tx*8 + 4] = o1;
    }
}

// ---------------------------------------------------------------------------
// Flash attention: one block = 64 queries of one (batch, head).
// Online softmax over key tiles of 64. All fp32.
// Thread layout: 16x16; each thread owns q-rows ty*4..+3, cols tx*4..+3.
// ---------------------------------------------------------------------------
#define PITCH 68
#define ATT_SMEM (4*64*PITCH*4)

__global__ __launch_bounds__(256) void attn_kernel(
    const float* __restrict__ madd,
    const float* __restrict__ Q, const float* __restrict__ Kg,
    const float* __restrict__ Vg, float* __restrict__ O)
{
    extern __shared__ float sm[];
    float* Qs = sm;
    float* Ks = Qs + 64*PITCH;
    float* Vs = Ks + 64*PITCH;
    float* Pt = Vs + 64*PITCH;

    const int b  = blockIdx.z;
    const int h  = blockIdx.y;
    const int q0 = blockIdx.x * 64;
    const int t  = threadIdx.x;
    const int tx = t & 15;
    const int ty = t >> 4;

    const size_t headoff = (size_t)h * DHD;
    const float* Qg = Q  + (size_t)b*SS*DD + headoff;
    const float* Kb = Kg + (size_t)b*SS*DD + headoff;
    const float* Vb = Vg + (size_t)b*SS*DD + headoff;

    // Load Q tile, transposed -> Qs[d][q]
    {
        const int qr = t >> 2;          // 0..63
        const int d0 = (t & 3) * 16;    // 0,16,32,48
        #pragma unroll
        for (int i = 0; i < 4; i++) {
            const int d = d0 + i*4;
            float4 v = *(const float4*)&Qg[(size_t)(q0 + qr)*DD + d];
            Qs[(d+0)*PITCH + qr] = v.x;
            Qs[(d+1)*PITCH + qr] = v.y;
            Qs[(d+2)*PITCH + qr] = v.z;
            Qs[(d+3)*PITCH + qr] = v.w;
        }
    }

    float m_i[4], l_i[4], acc[4][4];
    #pragma unroll
    for (int i = 0; i < 4; i++) {
        m_i[i] = -1e30f; l_i[i] = 0.0f;
        #pragma unroll
        for (int c = 0; c < 4; c++) acc[i][c] = 0.0f;
    }

    for (int j0 = 0; j0 < SS; j0 += 64) {
        // ---- load K (transposed) and V (direct) tiles ----
        const int jr = t >> 2;
        const int d0 = (t & 3) * 16;
        __syncthreads();   // protect previous iteration's smem reads
        #pragma unroll
        for (int i = 0; i < 4; i++) {
            const int d = d0 + i*4;
            float4 kv = *(const float4*)&Kb[(size_t)(j0 + jr)*DD + d];
            Ks[(d+0)*PITCH + jr] = kv.x;
            Ks[(d+1)*PITCH + jr] = kv.y;
            Ks[(d+2)*PITCH + jr] = kv.z;
            Ks[(d+3)*PITCH + jr] = kv.w;
            float4 vv = *(const float4*)&Vb[(size_t)(j0 + jr)*DD + d];
            *(float4*)&Vs[jr*PITCH + d] = vv;
        }
        __syncthreads();

        // ---- scores s[q][j] = (Q . K) / 8 + maskterm ----
        float s[4][4];
        #pragma unroll
        for (int i = 0; i < 4; i++)
            #pragma unroll
            for (int j = 0; j < 4; j++) s[i][j] = 0.0f;

        #pragma unroll 8
        for (int d = 0; d < 64; d++) {
            float4 qv = *(const float4*)&Qs[d*PITCH + ty*4];
            float4 kv = *(const float4*)&Ks[d*PITCH + tx*4];
            const float qa[4] = {qv.x, qv.y, qv.z, qv.w};
            const float ka[4] = {kv.x, kv.y, kv.z, kv.w};
            #pragma unroll
            for (int i = 0; i < 4; i++)
                #pragma unroll
                for (int j = 0; j < 4; j++)
                    s[i][j] = fmaf(qa[i], ka[j], s[i][j]);
        }

        float mterm[4];
        #pragma unroll
        for (int j = 0; j < 4; j++)
            mterm[j] = madd[b*SS + j0 + tx*4 + j];

        #pragma unroll
        for (int i = 0; i < 4; i++)
            #pragma unroll
            for (int j = 0; j < 4; j++)
                s[i][j] = s[i][j] * 0.125f + mterm[j];

        // ---- online softmax: reduce over the 16 threads sharing each q-row
        float p[4][4];
        #pragma unroll
        for (int i = 0; i < 4; i++) {
            float mx = fmaxf(fmaxf(s[i][0], s[i][1]), fmaxf(s[i][2], s[i][3]));
            #pragma unroll
            for (int w = 1; w < 16; w <<= 1)
                mx = fmaxf(mx, __shfl_xor_sync(0xffffffffu, mx, w));
            const float m_new = fmaxf(m_i[i], mx);
            const float scale = __expf(m_i[i] - m_new);
            m_i[i] = m_new;
            float sum = 0.0f;
            #pragma unroll
            for (int j = 0; j < 4; j++) {
                p[i][j] = __expf(s[i][j] - m_new);
                sum += p[i][j];
            }
            #pragma unroll
            for (int w = 1; w < 16; w <<= 1)
                sum += __shfl_xor_sync(0xffffffffu, sum, w);
            l_i[i] = l_i[i] * scale + sum;
            #pragma unroll
            for (int c = 0; c < 4; c++) acc[i][c] *= scale;
        }

        // ---- write P transposed: Pt[j][q] ----
        #pragma unroll
        for (int j = 0; j < 4; j++) {
            float4 pv;
            pv.x = p[0][j]; pv.y = p[1][j]; pv.z = p[2][j]; pv.w = p[3][j];
            *(float4*)&Pt[(tx*4 + j)*PITCH + ty*4] = pv;
        }
        __syncthreads();

        // ---- PV: acc[q][c] += sum_j Pt[j][q] * Vs[j][c] ----
        #pragma unroll 8
        for (int j = 0; j < 64; j++) {
            float4 pv = *(const float4*)&Pt[j*PITCH + ty*4];
            float4 vv = *(const float4*)&Vs[j*PITCH + tx*4];
            const float pa[4] = {pv.x, pv.y, pv.z, pv.w};
            const float va[4] = {vv.x, vv.y, vv.z, vv.w};
            #pragma unroll
            for (int i = 0; i < 4; i++)
                #pragma unroll
                for (int c = 0; c < 4; c++)
                    acc[i][c] = fmaf(pa[i], va[c], acc[i][c]);
        }
    }

    // ---- epilogue: O[b, q, h*64 + c] = acc / l ----
    #pragma unroll
    for (int i = 0; i < 4; i++) {
        const float inv_l = 1.0f / l_i[i];
        float4 o;
        o.x = acc[i][0] * inv_l; o.y = acc[i][1] * inv_l;
        o.z = acc[i][2] * inv_l; o.w = acc[i][3] * inv_l;
        const size_t row = (size_t)b*SS + q0 + ty*4 + i;
        *(float4*)&O[row*DD + h*DHD + tx*4] = o;
    }
}

// ---------------------------------------------------------------------------
// Launch
// ---------------------------------------------------------------------------
extern "C" void kernel_launch(void* const* d_in, const int* in_sizes, int n_in,
                              void* d_out, int out_size)
{
    const float* x_q = (const float*)d_in[0];
    const float* x_k = (const float*)d_in[1];
    const float* x_v = (const float*)d_in[2];
    const void*  mask = d_in[3];
    const float* Wq = (const float*)d_in[4];
    const float* bq = (const float*)d_in[5];
    const float* Wk = (const float*)d_in[6];
    const float* bk = (const float*)d_in[7];
    const float* Wv = (const float*)d_in[8];
    const float* bv = (const float*)d_in[9];
    const float* Wo = (const float*)d_in[10];
    const float* bo = (const float*)d_in[11];
    float* out = (float*)d_out;

    float *Qp, *Kp, *Vp, *Op, *Mp;
    cudaGetSymbolAddress((void**)&Qp, g_Q);
    cudaGetSymbolAddress((void**)&Kp, g_K);
    cudaGetSymbolAddress((void**)&Vp, g_V);
    cudaGetSymbolAddress((void**)&Op, g_O);
    cudaGetSymbolAddress((void**)&Mp, g_maskadd);

    cudaFuncSetAttribute(attn_kernel,
                         cudaFuncAttributeMaxDynamicSharedMemorySize, ATT_SMEM);

    dim3 ggrid(1024/128, MTOT/128);   // (8, 32)

    mask_convert<<<(BB*SS + 255)/256, 256>>>(mask, Mp);

    sgemm_bias<<<ggrid, 256>>>(x_q, Wq, bq, Qp);
    sgemm_bias<<<ggrid, 256>>>(x_k, Wk, bk, Kp);
    sgemm_bias<<<ggrid, 256>>>(x_v, Wv, bv, Vp);

    attn_kernel<<<dim3(SS/64, HH, BB), 256, ATT_SMEM>>>(Mp, Qp, Kp, Vp, Op);

    sgemm_bias<<<ggrid, 256>>>(Op, Wo, bo, out);
}

// round 4
// speedup vs baseline: 2.2279x; 2.2279x over previous
#include <cuda_runtime.h>
#include <cuda_bf16.h>
#include <cstdint>

// Problem constants
#define BB 2
#define SS 2048
#define DD 1024
#define HH 16
#define DHD 64
#define MTOT (BB*SS)   // 4096
#define GK 1024        // GEMM K
#define TKC 32         // GEMM K chunk
#define NCH (GK/TKC)   // 32 chunks

// Scratch (allocation-free rule: __device__ globals)
__device__ float g_Q[BB*SS*DD];
__device__ float g_K[BB*SS*DD];
__device__ float g_V[BB*SS*DD];
__device__ float g_O[BB*SS*DD];
__device__ float g_maskadd[BB*SS];

// ---------------------------------------------------------------------------
// helpers
// ---------------------------------------------------------------------------
__device__ __forceinline__ uint32_t smem_u32(const void* p) {
    uint32_t a;
    asm("{ .reg .u64 t; cvta.to.shared.u64 t, %1; cvt.u32.u64 %0, t; }"
        : "=r"(a) : "l"(p));
    return a;
}
__device__ __forceinline__ void ldsm4(uint32_t* r, uint32_t addr) {
    asm volatile("ldmatrix.sync.aligned.m8n8.x4.shared.b16 {%0,%1,%2,%3}, [%4];"
                 : "=r"(r[0]), "=r"(r[1]), "=r"(r[2]), "=r"(r[3]) : "r"(addr));
}
__device__ __forceinline__ void mma_bf16(float* c, const uint32_t* a,
                                         const uint32_t* b) {
    asm volatile(
        "mma.sync.aligned.m16n8k16.row.col.f32.bf16.bf16.f32 "
        "{%0,%1,%2,%3}, {%4,%5,%6,%7}, {%8,%9}, {%0,%1,%2,%3};"
        : "+f"(c[0]), "+f"(c[1]), "+f"(c[2]), "+f"(c[3])
        : "r"(a[0]), "r"(a[1]), "r"(a[2]), "r"(a[3]), "r"(b[0]), "r"(b[1]));
}
__device__ __forceinline__ uint32_t pack_bf16(__nv_bfloat16 x, __nv_bfloat16 y) {
    __nv_bfloat162 t(x, y);            // .x = low half
    return *reinterpret_cast<uint32_t*>(&t);
}
__device__ __forceinline__ uint32_t sw128(uint32_t off) {
    return off ^ ((off >> 3) & 0x70);
}

// ---------------------------------------------------------------------------
// Mask conversion (mask arrives as int32 0/1; keep uint8 fallback detection)
// ---------------------------------------------------------------------------
__global__ void mask_convert(const void* __restrict__ mask_raw,
                             float* __restrict__ madd)
{
    const unsigned* mw = (const unsigned*)mask_raw;
    bool is_int32 = true;
    #pragma unroll
    for (int i = 0; i < 64; i++)
        if (mw[i] > 1u) is_int32 = false;

    const int idx = blockIdx.x * blockDim.x + threadIdx.x;
    if (idx < BB * SS) {
        int m = is_int32 ? (int)mw[idx]
                         : (int)((const unsigned char*)mask_raw)[idx];
        madd[idx] = m ? 0.0f : -1e9f;
    }
}

// ---------------------------------------------------------------------------
// bf16-split tensor GEMM: C[M,N] = A[M,K] @ W[N,K]^T + bias
// fp32 inputs split in-kernel to bf16 hi/lo; 3-term mma.sync accumulation.
// CTA tile 128x128, warp tile 32x64 (8 warps), K chunks of 32, double buffer.
// Smem row layout (128B): [hi: 64B (32 bf16) | lo: 64B], XOR-swizzled per 16B.
// ---------------------------------------------------------------------------
#define SA_OFF(buf) ((buf) * 16384u)
#define SB_OFF(buf) (32768u + (buf) * 16384u)
#define GEMM_SMEM 65536

__global__ __launch_bounds__(256, 1) void gemm_bf16s(
    const float* __restrict__ A, const float* __restrict__ W,
    const float* __restrict__ bias, float* __restrict__ C)
{
    extern __shared__ char smem[];
    const uint32_t sb = smem_u32(smem);
    const int t    = threadIdx.x;
    const int lane = t & 31;
    const int wid  = t >> 5;
    const int m0 = blockIdx.y * 128;
    const int n0 = blockIdx.x * 128;
    const int mw = (wid >> 1) * 32;   // warp m offset in tile
    const int nw = (wid & 1) * 64;    // warp n offset in tile

    // loader indices: 4 iterations, each thread loads one float4 per tile
    int lrow[4], lkq[4];
    #pragma unroll
    for (int i = 0; i < 4; i++) {
        const int v = t + i * 256;
        lrow[i] = v >> 3;
        lkq[i]  = v & 7;
    }

    float4 ra[4], rb[4];
    #pragma unroll
    for (int i = 0; i < 4; i++) {
        ra[i] = *(const float4*)&A[(size_t)(m0 + lrow[i]) * GK + lkq[i] * 4];
        rb[i] = *(const float4*)&W[(size_t)(n0 + lrow[i]) * GK + lkq[i] * 4];
    }

    // ldmatrix lane-address components
    const int g = lane >> 3, r8 = lane & 7;
    // A: groups 0,1 -> rows 0-7/8-15 chunk k0-7 ; groups 2,3 -> chunk k8-15
    const uint32_t baseA_off = (uint32_t)(mw + (g & 1) * 8 + r8) * 128
                             + (uint32_t)(g >> 1) * 16;
    // B: groups 0,1 -> rows n0-7 chunks k0-7,k8-15 ; groups 2,3 -> rows n8-15
    const uint32_t baseB_off = (uint32_t)(nw + (g >> 1) * 8 + r8) * 128
                             + (uint32_t)(g & 1) * 16;

    float acc[2][8][4];
    #pragma unroll
    for (int mt = 0; mt < 2; mt++)
        #pragma unroll
        for (int nt = 0; nt < 8; nt++)
            #pragma unroll
            for (int c = 0; c < 4; c++) acc[mt][nt][c] = 0.0f;

    // store a staged chunk (registers -> smem buf) with hi/lo split
    auto store_chunk = [&](int buf) {
        #pragma unroll
        for (int i = 0; i < 4; i++) {
            const uint32_t offh = (uint32_t)lrow[i] * 128 + (uint32_t)lkq[i] * 8;
            {
                float4 v = ra[i];
                __nv_bfloat16 h0 = __float2bfloat16(v.x), h1 = __float2bfloat16(v.y);
                __nv_bfloat16 h2 = __float2bfloat16(v.z), h3 = __float2bfloat16(v.w);
                uint2 hp{pack_bf16(h0, h1), pack_bf16(h2, h3)};
                uint2 lp{pack_bf16(__float2bfloat16(v.x - __bfloat162float(h0)),
                                   __float2bfloat16(v.y - __bfloat162float(h1))),
                         pack_bf16(__float2bfloat16(v.z - __bfloat162float(h2)),
                                   __float2bfloat16(v.w - __bfloat162float(h3)))};
                *(uint2*)(smem + SA_OFF(buf) + sw128(offh))      = hp;
                *(uint2*)(smem + SA_OFF(buf) + sw128(offh + 64)) = lp;
            }
            {
                float4 v = rb[i];
                __nv_bfloat16 h0 = __float2bfloat16(v.x), h1 = __float2bfloat16(v.y);
                __nv_bfloat16 h2 = __float2bfloat16(v.z), h3 = __float2bfloat16(v.w);
                uint2 hp{pack_bf16(h0, h1), pack_bf16(h2, h3)};
                uint2 lp{pack_bf16(__float2bfloat16(v.x - __bfloat162float(h0)),
                                   __float2bfloat16(v.y - __bfloat162float(h1))),
                         pack_bf16(__float2bfloat16(v.z - __bfloat162float(h2)),
                                   __float2bfloat16(v.w - __bfloat162float(h3)))};
                *(uint2*)(smem + SB_OFF(buf) + sw128(offh))      = hp;
                *(uint2*)(smem + SB_OFF(buf) + sw128(offh + 64)) = lp;
            }
        }
    };

    store_chunk(0);

    for (int ch = 0; ch < NCH; ch++) {
        __syncthreads();
        // prefetch next chunk into registers (overlaps with mma below)
        if (ch + 1 < NCH) {
            const int k0 = (ch + 1) * TKC;
            #pragma unroll
            for (int i = 0; i < 4; i++) {
                ra[i] = *(const float4*)&A[(size_t)(m0 + lrow[i]) * GK + k0 + lkq[i] * 4];
                rb[i] = *(const float4*)&W[(size_t)(n0 + lrow[i]) * GK + k0 + lkq[i] * 4];
            }
        }

        const uint32_t sA = sb + SA_OFF(ch & 1);
        const uint32_t sB = sb + SB_OFF(ch & 1);

        #pragma unroll
        for (int ks = 0; ks < 2; ks++) {
            uint32_t af[2][2][4];   // [mt][prec][4]
            #pragma unroll
            for (int mt = 0; mt < 2; mt++)
                #pragma unroll
                for (int p = 0; p < 2; p++) {
                    const uint32_t off = baseA_off + (uint32_t)mt * 2048
                                       + (uint32_t)p * 64 + (uint32_t)ks * 32;
                    ldsm4(af[mt][p], sA + sw128(off));
                }
            uint32_t bf_[2][8][2];  // [prec][nt][2]
            #pragma unroll
            for (int np = 0; np < 4; np++)
                #pragma unroll
                for (int p = 0; p < 2; p++) {
                    uint32_t q[4];
                    const uint32_t off = baseB_off + (uint32_t)np * 2048
                                       + (uint32_t)p * 64 + (uint32_t)ks * 32;
                    ldsm4(q, sB + sw128(off));
                    bf_[p][np*2][0]   = q[0]; bf_[p][np*2][1]   = q[1];
                    bf_[p][np*2+1][0] = q[2]; bf_[p][np*2+1][1] = q[3];
                }
            #pragma unroll
            for (int mt = 0; mt < 2; mt++)
                #pragma unroll
                for (int nt = 0; nt < 8; nt++) {
                    mma_bf16(acc[mt][nt], af[mt][0], bf_[0][nt]);
                    mma_bf16(acc[mt][nt], af[mt][0], bf_[1][nt]);
                    mma_bf16(acc[mt][nt], af[mt][1], bf_[0][nt]);
                }
        }

        if (ch + 1 < NCH) store_chunk((ch + 1) & 1);
    }

    // epilogue
    float bb[8][2];
    #pragma unroll
    for (int nt = 0; nt < 8; nt++) {
        const int col = n0 + nw + nt * 8 + (lane & 3) * 2;
        bb[nt][0] = bias[col];
        bb[nt][1] = bias[col + 1];
    }
    #pragma unroll
    for (int mt = 0; mt < 2; mt++) {
        const int row0 = m0 + mw + mt * 16 + (lane >> 2);
        #pragma unroll
        for (int nt = 0; nt < 8; nt++) {
            const int col = n0 + nw + nt * 8 + (lane & 3) * 2;
            float2 s0{acc[mt][nt][0] + bb[nt][0], acc[mt][nt][1] + bb[nt][1]};
            float2 s1{acc[mt][nt][2] + bb[nt][0], acc[mt][nt][3] + bb[nt][1]};
            *(float2*)&C[(size_t)row0 * DD + col]       = s0;
            *(float2*)&C[(size_t)(row0 + 8) * DD + col] = s1;
        }
    }
}

// ---------------------------------------------------------------------------
// Flash attention (unchanged, passing version): one block = 64 queries, (b,h)
// ---------------------------------------------------------------------------
#define PITCH 68
#define ATT_SMEM (4*64*PITCH*4)

__global__ __launch_bounds__(256) void attn_kernel(
    const float* __restrict__ madd,
    const float* __restrict__ Q, const float* __restrict__ Kg,
    const float* __restrict__ Vg, float* __restrict__ O)
{
    extern __shared__ float sm[];
    float* Qs = sm;
    float* Ks = Qs + 64*PITCH;
    float* Vs = Ks + 64*PITCH;
    float* Pt = Vs + 64*PITCH;

    const int b  = blockIdx.z;
    const int h  = blockIdx.y;
    const int q0 = blockIdx.x * 64;
    const int t  = threadIdx.x;
    const int tx = t & 15;
    const int ty = t >> 4;

    const size_t headoff = (size_t)h * DHD;
    const float* Qg = Q  + (size_t)b*SS*DD + headoff;
    const float* Kb = Kg + (size_t)b*SS*DD + headoff;
    const float* Vb = Vg + (size_t)b*SS*DD + headoff;

    {
        const int qr = t >> 2;
        const int d0 = (t & 3) * 16;
        #pragma unroll
        for (int i = 0; i < 4; i++) {
            const int d = d0 + i*4;
            float4 v = *(const float4*)&Qg[(size_t)(q0 + qr)*DD + d];
            Qs[(d+0)*PITCH + qr] = v.x;
            Qs[(d+1)*PITCH + qr] = v.y;
            Qs[(d+2)*PITCH + qr] = v.z;
            Qs[(d+3)*PITCH + qr] = v.w;
        }
    }

    float m_i[4], l_i[4], acc[4][4];
    #pragma unroll
    for (int i = 0; i < 4; i++) {
        m_i[i] = -1e30f; l_i[i] = 0.0f;
        #pragma unroll
        for (int c = 0; c < 4; c++) acc[i][c] = 0.0f;
    }

    for (int j0 = 0; j0 < SS; j0 += 64) {
        const int jr = t >> 2;
        const int d0 = (t & 3) * 16;
        __syncthreads();
        #pragma unroll
        for (int i = 0; i < 4; i++) {
            const int d = d0 + i*4;
            float4 kv = *(const float4*)&Kb[(size_t)(j0 + jr)*DD + d];
            Ks[(d+0)*PITCH + jr] = kv.x;
            Ks[(d+1)*PITCH + jr] = kv.y;
            Ks[(d+2)*PITCH + jr] = kv.z;
            Ks[(d+3)*PITCH + jr] = kv.w;
            float4 vv = *(const float4*)&Vb[(size_t)(j0 + jr)*DD + d];
            *(float4*)&Vs[jr*PITCH + d] = vv;
        }
        __syncthreads();

        float s[4][4];
        #pragma unroll
        for (int i = 0; i < 4; i++)
            #pragma unroll
            for (int j = 0; j < 4; j++) s[i][j] = 0.0f;

        #pragma unroll 8
        for (int d = 0; d < 64; d++) {
            float4 qv = *(const float4*)&Qs[d*PITCH + ty*4];
            float4 kv = *(const float4*)&Ks[d*PITCH + tx*4];
            const float qa[4] = {qv.x, qv.y, qv.z, qv.w};
            const float ka[4] = {kv.x, kv.y, kv.z, kv.w};
            #pragma unroll
            for (int i = 0; i < 4; i++)
                #pragma unroll
                for (int j = 0; j < 4; j++)
                    s[i][j] = fmaf(qa[i], ka[j], s[i][j]);
        }

        float mterm[4];
        #pragma unroll
        for (int j = 0; j < 4; j++)
            mterm[j] = madd[b*SS + j0 + tx*4 + j];

        #pragma unroll
        for (int i = 0; i < 4; i++)
            #pragma unroll
            for (int j = 0; j < 4; j++)
                s[i][j] = s[i][j] * 0.125f + mterm[j];

        float p[4][4];
        #pragma unroll
        for (int i = 0; i < 4; i++) {
            float mx = fmaxf(fmaxf(s[i][0], s[i][1]), fmaxf(s[i][2], s[i][3]));
            #pragma unroll
            for (int w = 1; w < 16; w <<= 1)
                mx = fmaxf(mx, __shfl_xor_sync(0xffffffffu, mx, w));
            const float m_new = fmaxf(m_i[i], mx);
            const float scale = __expf(m_i[i] - m_new);
            m_i[i] = m_new;
            float sum = 0.0f;
            #pragma unroll
            for (int j = 0; j < 4; j++) {
                p[i][j] = __expf(s[i][j] - m_new);
                sum += p[i][j];
            }
            #pragma unroll
            for (int w = 1; w < 16; w <<= 1)
                sum += __shfl_xor_sync(0xffffffffu, sum, w);
            l_i[i] = l_i[i] * scale + sum;
            #pragma unroll
            for (int c = 0; c < 4; c++) acc[i][c] *= scale;
        }

        #pragma unroll
        for (int j = 0; j < 4; j++) {
            float4 pv;
            pv.x = p[0][j]; pv.y = p[1][j]; pv.z = p[2][j]; pv.w = p[3][j];
            *(float4*)&Pt[(tx*4 + j)*PITCH + ty*4] = pv;
        }
        __syncthreads();

        #pragma unroll 8
        for (int j = 0; j < 64; j++) {
            float4 pv = *(const float4*)&Pt[j*PITCH + ty*4];
            float4 vv = *(const float4*)&Vs[j*PITCH + tx*4];
            const float pa[4] = {pv.x, pv.y, pv.z, pv.w};
            const float va[4] = {vv.x, vv.y, vv.z, vv.w};
            #pragma unroll
            for (int i = 0; i < 4; i++)
                #pragma unroll
                for (int c = 0; c < 4; c++)
                    acc[i][c] = fmaf(pa[i], va[c], acc[i][c]);
        }
    }

    #pragma unroll
    for (int i = 0; i < 4; i++) {
        const float inv_l = 1.0f / l_i[i];
        float4 o;
        o.x = acc[i][0] * inv_l; o.y = acc[i][1] * inv_l;
        o.z = acc[i][2] * inv_l; o.w = acc[i][3] * inv_l;
        const size_t row = (size_t)b*SS + q0 + ty*4 + i;
        *(float4*)&O[row*DD + h*DHD + tx*4] = o;
    }
}

// ---------------------------------------------------------------------------
// Launch
// ---------------------------------------------------------------------------
extern "C" void kernel_launch(void* const* d_in, const int* in_sizes, int n_in,
                              void* d_out, int out_size)
{
    const float* x_q = (const float*)d_in[0];
    const float* x_k = (const float*)d_in[1];
    const float* x_v = (const float*)d_in[2];
    const void*  mask = d_in[3];
    const float* Wq = (const float*)d_in[4];
    const float* bq = (const float*)d_in[5];
    const float* Wk = (const float*)d_in[6];
    const float* bk = (const float*)d_in[7];
    const float* Wv = (const float*)d_in[8];
    const float* bv = (const float*)d_in[9];
    const float* Wo = (const float*)d_in[10];
    const float* bo = (const float*)d_in[11];
    float* out = (float*)d_out;

    float *Qp, *Kp, *Vp, *Op, *Mp;
    cudaGetSymbolAddress((void**)&Qp, g_Q);
    cudaGetSymbolAddress((void**)&Kp, g_K);
    cudaGetSymbolAddress((void**)&Vp, g_V);
    cudaGetSymbolAddress((void**)&Op, g_O);
    cudaGetSymbolAddress((void**)&Mp, g_maskadd);

    cudaFuncSetAttribute(attn_kernel,
                         cudaFuncAttributeMaxDynamicSharedMemorySize, ATT_SMEM);
    cudaFuncSetAttribute(gemm_bf16s,
                         cudaFuncAttributeMaxDynamicSharedMemorySize, GEMM_SMEM);

    dim3 ggrid(DD/128, MTOT/128);   // (8, 32)

    mask_convert<<<(BB*SS + 255)/256, 256>>>(mask, Mp);

    gemm_bf16s<<<ggrid, 256, GEMM_SMEM>>>(x_q, Wq, bq, Qp);
    gemm_bf16s<<<ggrid, 256, GEMM_SMEM>>>(x_k, Wk, bk, Kp);
    gemm_bf16s<<<ggrid, 256, GEMM_SMEM>>>(x_v, Wv, bv, Vp);

    attn_kernel<<<dim3(SS/64, HH, BB), 256, ATT_SMEM>>>(Mp, Qp, Kp, Vp, Op);

    gemm_bf16s<<<ggrid, 256, GEMM_SMEM>>>(Op, Wo, bo, out);
}

// round 5
// speedup vs baseline: 4.5666x; 2.0497x over previous
#include <cuda_runtime.h>
#include <cuda_bf16.h>
#include <cstdint>

// Problem constants
#define BB 2
#define SS 2048
#define DD 1024
#define HH 16
#define DHD 64
#define MTOT (BB*SS)   // 4096
#define GK 1024        // GEMM K
#define TKC 32         // GEMM K chunk
#define NCH (GK/TKC)   // 32 chunks

// Scratch (allocation-free rule: __device__ globals)
__device__ float g_Q[BB*SS*DD];
__device__ float g_K[BB*SS*DD];
__device__ float g_V[BB*SS*DD];
__device__ float g_O[BB*SS*DD];
__device__ float g_maskadd[BB*SS];

// ---------------------------------------------------------------------------
// helpers
// ---------------------------------------------------------------------------
__device__ __forceinline__ uint32_t smem_u32(const void* p) {
    uint32_t a;
    asm("{ .reg .u64 t; cvta.to.shared.u64 t, %1; cvt.u32.u64 %0, t; }"
        : "=r"(a) : "l"(p));
    return a;
}
__device__ __forceinline__ void ldsm4(uint32_t* r, uint32_t addr) {
    asm volatile("ldmatrix.sync.aligned.m8n8.x4.shared.b16 {%0,%1,%2,%3}, [%4];"
                 : "=r"(r[0]), "=r"(r[1]), "=r"(r[2]), "=r"(r[3]) : "r"(addr));
}
__device__ __forceinline__ void ldsm4t(uint32_t* r, uint32_t addr) {
    asm volatile("ldmatrix.sync.aligned.m8n8.x4.trans.shared.b16 {%0,%1,%2,%3}, [%4];"
                 : "=r"(r[0]), "=r"(r[1]), "=r"(r[2]), "=r"(r[3]) : "r"(addr));
}
__device__ __forceinline__ void mma_bf16(float* c, const uint32_t* a,
                                         const uint32_t* b) {
    asm volatile(
        "mma.sync.aligned.m16n8k16.row.col.f32.bf16.bf16.f32 "
        "{%0,%1,%2,%3}, {%4,%5,%6,%7}, {%8,%9}, {%0,%1,%2,%3};"
        : "+f"(c[0]), "+f"(c[1]), "+f"(c[2]), "+f"(c[3])
        : "r"(a[0]), "r"(a[1]), "r"(a[2]), "r"(a[3]), "r"(b[0]), "r"(b[1]));
}
__device__ __forceinline__ uint32_t pack_bf16(__nv_bfloat16 x, __nv_bfloat16 y) {
    __nv_bfloat162 t(x, y);            // .x = low half
    return *reinterpret_cast<uint32_t*>(&t);
}
// pack two fp32 -> bf16x2 (lo = even-k element, hi = odd-k element)
__device__ __forceinline__ uint32_t cvt_bf16x2(float lo, float hi) {
    uint32_t d;
    asm("cvt.rn.bf16x2.f32 %0, %1, %2;" : "=r"(d) : "f"(hi), "f"(lo));
    return d;
}
__device__ __forceinline__ uint32_t sw128(uint32_t off) {
    return off ^ ((off >> 3) & 0x70);
}

// ---------------------------------------------------------------------------
// Mask conversion (mask arrives as int32 0/1; keep uint8 fallback detection)
// ---------------------------------------------------------------------------
__global__ void mask_convert(const void* __restrict__ mask_raw,
                             float* __restrict__ madd)
{
    const unsigned* mw = (const unsigned*)mask_raw;
    bool is_int32 = true;
    #pragma unroll
    for (int i = 0; i < 64; i++)
        if (mw[i] > 1u) is_int32 = false;

    const int idx = blockIdx.x * blockDim.x + threadIdx.x;
    if (idx < BB * SS) {
        int m = is_int32 ? (int)mw[idx]
                         : (int)((const unsigned char*)mask_raw)[idx];
        madd[idx] = m ? 0.0f : -1e9f;
    }
}

// ---------------------------------------------------------------------------
// bf16-split tensor GEMM (unchanged, passing): C = A @ W^T + bias
// ---------------------------------------------------------------------------
#define SA_OFF(buf) ((buf) * 16384u)
#define SB_OFF(buf) (32768u + (buf) * 16384u)
#define GEMM_SMEM 65536

__global__ __launch_bounds__(256, 1) void gemm_bf16s(
    const float* __restrict__ A, const float* __restrict__ W,
    const float* __restrict__ bias, float* __restrict__ C)
{
    extern __shared__ char smem[];
    const uint32_t sb = smem_u32(smem);
    const int t    = threadIdx.x;
    const int lane = t & 31;
    const int wid  = t >> 5;
    const int m0 = blockIdx.y * 128;
    const int n0 = blockIdx.x * 128;
    const int mw = (wid >> 1) * 32;
    const int nw = (wid & 1) * 64;

    int lrow[4], lkq[4];
    #pragma unroll
    for (int i = 0; i < 4; i++) {
        const int v = t + i * 256;
        lrow[i] = v >> 3;
        lkq[i]  = v & 7;
    }

    float4 ra[4], rb[4];
    #pragma unroll
    for (int i = 0; i < 4; i++) {
        ra[i] = *(const float4*)&A[(size_t)(m0 + lrow[i]) * GK + lkq[i] * 4];
        rb[i] = *(const float4*)&W[(size_t)(n0 + lrow[i]) * GK + lkq[i] * 4];
    }

    const int g = lane >> 3, r8 = lane & 7;
    const uint32_t baseA_off = (uint32_t)(mw + (g & 1) * 8 + r8) * 128
                             + (uint32_t)(g >> 1) * 16;
    const uint32_t baseB_off = (uint32_t)(nw + (g >> 1) * 8 + r8) * 128
                             + (uint32_t)(g & 1) * 16;

    float acc[2][8][4];
    #pragma unroll
    for (int mt = 0; mt < 2; mt++)
        #pragma unroll
        for (int nt = 0; nt < 8; nt++)
            #pragma unroll
            for (int c = 0; c < 4; c++) acc[mt][nt][c] = 0.0f;

    auto store_chunk = [&](int buf) {
        #pragma unroll
        for (int i = 0; i < 4; i++) {
            const uint32_t offh = (uint32_t)lrow[i] * 128 + (uint32_t)lkq[i] * 8;
            {
                float4 v = ra[i];
                __nv_bfloat16 h0 = __float2bfloat16(v.x), h1 = __float2bfloat16(v.y);
                __nv_bfloat16 h2 = __float2bfloat16(v.z), h3 = __float2bfloat16(v.w);
                uint2 hp{pack_bf16(h0, h1), pack_bf16(h2, h3)};
                uint2 lp{pack_bf16(__float2bfloat16(v.x - __bfloat162float(h0)),
                                   __float2bfloat16(v.y - __bfloat162float(h1))),
                         pack_bf16(__float2bfloat16(v.z - __bfloat162float(h2)),
                                   __float2bfloat16(v.w - __bfloat162float(h3)))};
                *(uint2*)(smem + SA_OFF(buf) + sw128(offh))      = hp;
                *(uint2*)(smem + SA_OFF(buf) + sw128(offh + 64)) = lp;
            }
            {
                float4 v = rb[i];
                __nv_bfloat16 h0 = __float2bfloat16(v.x), h1 = __float2bfloat16(v.y);
                __nv_bfloat16 h2 = __float2bfloat16(v.z), h3 = __float2bfloat16(v.w);
                uint2 hp{pack_bf16(h0, h1), pack_bf16(h2, h3)};
                uint2 lp{pack_bf16(__float2bfloat16(v.x - __bfloat162float(h0)),
                                   __float2bfloat16(v.y - __bfloat162float(h1))),
                         pack_bf16(__float2bfloat16(v.z - __bfloat162float(h2)),
                                   __float2bfloat16(v.w - __bfloat162float(h3)))};
                *(uint2*)(smem + SB_OFF(buf) + sw128(offh))      = hp;
                *(uint2*)(smem + SB_OFF(buf) + sw128(offh + 64)) = lp;
            }
        }
    };

    store_chunk(0);

    for (int ch = 0; ch < NCH; ch++) {
        __syncthreads();
        if (ch + 1 < NCH) {
            const int k0 = (ch + 1) * TKC;
            #pragma unroll
            for (int i = 0; i < 4; i++) {
                ra[i] = *(const float4*)&A[(size_t)(m0 + lrow[i]) * GK + k0 + lkq[i] * 4];
                rb[i] = *(const float4*)&W[(size_t)(n0 + lrow[i]) * GK + k0 + lkq[i] * 4];
            }
        }

        const uint32_t sA = sb + SA_OFF(ch & 1);
        const uint32_t sB = sb + SB_OFF(ch & 1);

        #pragma unroll
        for (int ks = 0; ks < 2; ks++) {
            uint32_t af[2][2][4];
            #pragma unroll
            for (int mt = 0; mt < 2; mt++)
                #pragma unroll
                for (int p = 0; p < 2; p++) {
                    const uint32_t off = baseA_off + (uint32_t)mt * 2048
                                       + (uint32_t)p * 64 + (uint32_t)ks * 32;
                    ldsm4(af[mt][p], sA + sw128(off));
                }
            uint32_t bf_[2][8][2];
            #pragma unroll
            for (int np = 0; np < 4; np++)
                #pragma unroll
                for (int p = 0; p < 2; p++) {
                    uint32_t q[4];
                    const uint32_t off = baseB_off + (uint32_t)np * 2048
                                       + (uint32_t)p * 64 + (uint32_t)ks * 32;
                    ldsm4(q, sB + sw128(off));
                    bf_[p][np*2][0]   = q[0]; bf_[p][np*2][1]   = q[1];
                    bf_[p][np*2+1][0] = q[2]; bf_[p][np*2+1][1] = q[3];
                }
            #pragma unroll
            for (int mt = 0; mt < 2; mt++)
                #pragma unroll
                for (int nt = 0; nt < 8; nt++) {
                    mma_bf16(acc[mt][nt], af[mt][0], bf_[0][nt]);
                    mma_bf16(acc[mt][nt], af[mt][0], bf_[1][nt]);
                    mma_bf16(acc[mt][nt], af[mt][1], bf_[0][nt]);
                }
        }

        if (ch + 1 < NCH) store_chunk((ch + 1) & 1);
    }

    float bb[8][2];
    #pragma unroll
    for (int nt = 0; nt < 8; nt++) {
        const int col = n0 + nw + nt * 8 + (lane & 3) * 2;
        bb[nt][0] = bias[col];
        bb[nt][1] = bias[col + 1];
    }
    #pragma unroll
    for (int mt = 0; mt < 2; mt++) {
        const int row0 = m0 + mw + mt * 16 + (lane >> 2);
        #pragma unroll
        for (int nt = 0; nt < 8; nt++) {
            const int col = n0 + nw + nt * 8 + (lane & 3) * 2;
            float2 s0{acc[mt][nt][0] + bb[nt][0], acc[mt][nt][1] + bb[nt][1]};
            float2 s1{acc[mt][nt][2] + bb[nt][0], acc[mt][nt][3] + bb[nt][1]};
            *(float2*)&C[(size_t)row0 * DD + col]       = s0;
            *(float2*)&C[(size_t)(row0 + 8) * DD + col] = s1;
        }
    }
}

// ---------------------------------------------------------------------------
// Tensor-core flash attention, bf16 hi/lo split both stages.
// CTA: 128 queries x one (b,h); 8 warps x 16 rows. K/V tiles of 64 keys,
// double-buffered smem + register prefetch.
// Buffer layout (32KB each): Kh 8K | Kl 8K | Vh 8K | Vl 8K. Rows=128B, sw128.
// ---------------------------------------------------------------------------
#define AT_BUF 32768u
#define AT_SMEM (2*AT_BUF + 512)

__global__ __launch_bounds__(256, 1) void attn_mma(
    const float* __restrict__ madd,
    const float* __restrict__ Qg, const float* __restrict__ Kg,
    const float* __restrict__ Vg, float* __restrict__ Og)
{
    extern __shared__ char smem[];
    const uint32_t sb = smem_u32(smem);
    float* maskS = (float*)(smem + 2*AT_BUF);
    const int t = threadIdx.x, lane = t & 31, wid = t >> 5;
    const int b = blockIdx.z, h = blockIdx.y, q0 = blockIdx.x * 128;
    const int g = lane >> 3, r8 = lane & 7;

    const float* Qb = Qg + (size_t)b*SS*DD + h*DHD;
    const float* Kb = Kg + (size_t)b*SS*DD + h*DHD;
    const float* Vb = Vg + (size_t)b*SS*DD + h*DHD;

    // ---- stage Q (128x64) split into smem (Qh @0, Ql @16384), then to regs
    #pragma unroll
    for (int i = 0; i < 8; i++) {
        const int v = t + i * 256;
        const int row = v >> 4, c4 = v & 15;
        float4 q = *(const float4*)&Qb[(size_t)(q0 + row) * DD + c4 * 4];
        __nv_bfloat16 h0 = __float2bfloat16(q.x), h1 = __float2bfloat16(q.y);
        __nv_bfloat16 h2 = __float2bfloat16(q.z), h3 = __float2bfloat16(q.w);
        uint2 hp{pack_bf16(h0, h1), pack_bf16(h2, h3)};
        uint2 lp{pack_bf16(__float2bfloat16(q.x - __bfloat162float(h0)),
                           __float2bfloat16(q.y - __bfloat162float(h1))),
                 pack_bf16(__float2bfloat16(q.z - __bfloat162float(h2)),
                           __float2bfloat16(q.w - __bfloat162float(h3)))};
        const uint32_t off = sw128((uint32_t)row * 128 + (uint32_t)c4 * 8);
        *(uint2*)(smem + off)          = hp;
        *(uint2*)(smem + 16384u + off) = lp;
    }
    __syncthreads();

    uint32_t qf[2][4][4];   // [prec][kstep(dh)][4]
    {
        const uint32_t aoff = (uint32_t)(wid*16 + (g & 1)*8 + r8) * 128
                            + (uint32_t)(g >> 1) * 16;
        #pragma unroll
        for (int ks = 0; ks < 4; ks++) {
            ldsm4(qf[0][ks], sb + sw128(aoff + ks*32));
            ldsm4(qf[1][ks], sb + 16384u + sw128(aoff + ks*32));
        }
    }
    __syncthreads();   // done reading staged Q; buffers now reusable

    // loader indices: 4 float4 per thread per tensor (64 rows x 16 float4)
    int lr[4], lc[4];
    #pragma unroll
    for (int i = 0; i < 4; i++) {
        const int v = t + i * 256;
        lr[i] = v >> 4; lc[i] = v & 15;
    }

    float4 rk[4], rv[4];
    float mreg = 0.0f;
    #pragma unroll
    for (int i = 0; i < 4; i++) {
        rk[i] = *(const float4*)&Kb[(size_t)lr[i] * DD + lc[i] * 4];
        rv[i] = *(const float4*)&Vb[(size_t)lr[i] * DD + lc[i] * 4];
    }
    if (t < 64) mreg = madd[b*SS + t];

    auto store_kv = [&](int buf) {
        const uint32_t base = buf * AT_BUF;
        #pragma unroll
        for (int i = 0; i < 4; i++) {
            const uint32_t off = sw128((uint32_t)lr[i] * 128 + (uint32_t)lc[i] * 8);
            {
                float4 v = rk[i];
                __nv_bfloat16 h0 = __float2bfloat16(v.x), h1 = __float2bfloat16(v.y);
                __nv_bfloat16 h2 = __float2bfloat16(v.z), h3 = __float2bfloat16(v.w);
                uint2 hp{pack_bf16(h0, h1), pack_bf16(h2, h3)};
                uint2 lp{pack_bf16(__float2bfloat16(v.x - __bfloat162float(h0)),
                                   __float2bfloat16(v.y - __bfloat162float(h1))),
                         pack_bf16(__float2bfloat16(v.z - __bfloat162float(h2)),
                                   __float2bfloat16(v.w - __bfloat162float(h3)))};
                *(uint2*)(smem + base + off)         = hp;
                *(uint2*)(smem + base + 8192u + off) = lp;
            }
            {
                float4 v = rv[i];
                __nv_bfloat16 h0 = __float2bfloat16(v.x), h1 = __float2bfloat16(v.y);
                __nv_bfloat16 h2 = __float2bfloat16(v.z), h3 = __float2bfloat16(v.w);
                uint2 hp{pack_bf16(h0, h1), pack_bf16(h2, h3)};
                uint2 lp{pack_bf16(__float2bfloat16(v.x - __bfloat162float(h0)),
                                   __float2bfloat16(v.y - __bfloat162float(h1))),
                         pack_bf16(__float2bfloat16(v.z - __bfloat162float(h2)),
                                   __float2bfloat16(v.w - __bfloat162float(h3)))};
                *(uint2*)(smem + base + 16384u + off) = hp;
                *(uint2*)(smem + base + 24576u + off) = lp;
            }
        }
        if (t < 64) maskS[buf*64 + t] = mreg;
    };

    store_kv(0);

    float o[8][4];
    #pragma unroll
    for (int nt = 0; nt < 8; nt++)
        #pragma unroll
        for (int c = 0; c < 4; c++) o[nt][c] = 0.0f;
    float mA = -1e30f, mB = -1e30f, lA = 0.0f, lB = 0.0f;

    const uint32_t kboff = (uint32_t)((g >> 1)*8 + r8) * 128 + (uint32_t)(g & 1)*16;
    const uint32_t vboff = (uint32_t)((g & 1)*8 + r8) * 128 + (uint32_t)(g >> 1)*16;

    const int NKT = SS / 64;   // 32
    for (int ch = 0; ch < NKT; ch++) {
        __syncthreads();
        if (ch + 1 < NKT) {
            const int j0n = (ch + 1) * 64;
            #pragma unroll
            for (int i = 0; i < 4; i++) {
                rk[i] = *(const float4*)&Kb[(size_t)(j0n + lr[i]) * DD + lc[i] * 4];
                rv[i] = *(const float4*)&Vb[(size_t)(j0n + lr[i]) * DD + lc[i] * 4];
            }
            if (t < 64) mreg = madd[b*SS + j0n + t];
        }

        const uint32_t base = sb + (ch & 1) * AT_BUF;
        const uint32_t sKh = base, sKl = base + 8192u;
        const uint32_t sVh = base + 16384u, sVl = base + 24576u;

        // ---- QK^T: s[nt][4], nt = key octets
        float s[8][4];
        #pragma unroll
        for (int nt = 0; nt < 8; nt++)
            #pragma unroll
            for (int c = 0; c < 4; c++) s[nt][c] = 0.0f;

        #pragma unroll
        for (int ks = 0; ks < 4; ks++) {
            #pragma unroll
            for (int nq = 0; nq < 4; nq++) {
                uint32_t bh[4], bl[4];
                const uint32_t off = kboff + (uint32_t)nq*2048 + (uint32_t)ks*32;
                ldsm4(bh, sKh + sw128(off));
                ldsm4(bl, sKl + sw128(off));
                mma_bf16(s[nq*2],   qf[0][ks], bh);
                mma_bf16(s[nq*2],   qf[0][ks], bl);
                mma_bf16(s[nq*2],   qf[1][ks], bh);
                mma_bf16(s[nq*2+1], qf[0][ks], bh + 2);
                mma_bf16(s[nq*2+1], qf[0][ks], bl + 2);
                mma_bf16(s[nq*2+1], qf[1][ks], bh + 2);
            }
        }

        // ---- scale + mask
        const int mbase = (ch & 1) * 64 + (lane & 3) * 2;
        #pragma unroll
        for (int nt = 0; nt < 8; nt++) {
            float2 mk = *(float2*)&maskS[mbase + nt*8];
            s[nt][0] = s[nt][0]*0.125f + mk.x;
            s[nt][1] = s[nt][1]*0.125f + mk.y;
            s[nt][2] = s[nt][2]*0.125f + mk.x;
            s[nt][3] = s[nt][3]*0.125f + mk.y;
        }

        // ---- online softmax (rows A = lane>>2, B = +8)
        float mxA = s[0][0], mxB = s[0][2];
        #pragma unroll
        for (int nt = 0; nt < 8; nt++) {
            mxA = fmaxf(mxA, fmaxf(s[nt][0], s[nt][1]));
            mxB = fmaxf(mxB, fmaxf(s[nt][2], s[nt][3]));
        }
        mxA = fmaxf(mxA, __shfl_xor_sync(0xffffffffu, mxA, 1));
        mxA = fmaxf(mxA, __shfl_xor_sync(0xffffffffu, mxA, 2));
        mxB = fmaxf(mxB, __shfl_xor_sync(0xffffffffu, mxB, 1));
        mxB = fmaxf(mxB, __shfl_xor_sync(0xffffffffu, mxB, 2));
        const float mnA = fmaxf(mA, mxA), mnB = fmaxf(mB, mxB);
        const float scA = __expf(mA - mnA), scB = __expf(mB - mnB);
        mA = mnA; mB = mnB;

        float sumA = 0.0f, sumB = 0.0f;
        #pragma unroll
        for (int nt = 0; nt < 8; nt++) {
            s[nt][0] = __expf(s[nt][0] - mnA);
            s[nt][1] = __expf(s[nt][1] - mnA);
            s[nt][2] = __expf(s[nt][2] - mnB);
            s[nt][3] = __expf(s[nt][3] - mnB);
            sumA += s[nt][0] + s[nt][1];
            sumB += s[nt][2] + s[nt][3];
        }
        sumA += __shfl_xor_sync(0xffffffffu, sumA, 1);
        sumA += __shfl_xor_sync(0xffffffffu, sumA, 2);
        sumB += __shfl_xor_sync(0xffffffffu, sumB, 1);
        sumB += __shfl_xor_sync(0xffffffffu, sumB, 2);
        lA = lA * scA + sumA;
        lB = lB * scB + sumB;
        #pragma unroll
        for (int nt = 0; nt < 8; nt++) {
            o[nt][0] *= scA; o[nt][1] *= scA;
            o[nt][2] *= scB; o[nt][3] *= scB;
        }

        // ---- pack P hi/lo into A-frags (kstep = 16 keys = ntiles 2ks,2ks+1)
        uint32_t ph[4][4], pl[4][4];
        #pragma unroll
        for (int ks = 0; ks < 4; ks++) {
            #pragma unroll
            for (int half = 0; half < 2; half++) {
                const int nt = ks*2 + half;
                uint32_t u0 = cvt_bf16x2(s[nt][0], s[nt][1]);
                uint32_t u1 = cvt_bf16x2(s[nt][2], s[nt][3]);
                ph[ks][half*2]   = u0;
                ph[ks][half*2+1] = u1;
                float r0 = s[nt][0] - __uint_as_float(u0 << 16);
                float r1 = s[nt][1] - __uint_as_float(u0 & 0xffff0000u);
                float r2 = s[nt][2] - __uint_as_float(u1 << 16);
                float r3 = s[nt][3] - __uint_as_float(u1 & 0xffff0000u);
                pl[ks][half*2]   = cvt_bf16x2(r0, r1);
                pl[ks][half*2+1] = cvt_bf16x2(r2, r3);
            }
        }

        // ---- PV: o[nt(dh)][4] += P @ V
        #pragma unroll
        for (int nq = 0; nq < 4; nq++) {
            #pragma unroll
            for (int ks = 0; ks < 4; ks++) {
                uint32_t vh[4], vl[4];
                const uint32_t off = vboff + (uint32_t)ks*2048 + (uint32_t)nq*32;
                ldsm4t(vh, sVh + sw128(off));
                ldsm4t(vl, sVl + sw128(off));
                mma_bf16(o[nq*2],   ph[ks], vh);
                mma_bf16(o[nq*2],   ph[ks], vl);
                mma_bf16(o[nq*2],   pl[ks], vh);
                mma_bf16(o[nq*2+1], ph[ks], vh + 2);
                mma_bf16(o[nq*2+1], ph[ks], vl + 2);
                mma_bf16(o[nq*2+1], pl[ks], vh + 2);
            }
        }

        if (ch + 1 < NKT) store_kv((ch + 1) & 1);
    }

    // ---- epilogue
    const float invA = 1.0f / lA, invB = 1.0f / lB;
    const int rowA = q0 + wid*16 + (lane >> 2);
    #pragma unroll
    for (int nt = 0; nt < 8; nt++) {
        const int col = h*DHD + nt*8 + (lane & 3)*2;
        float2 oA{o[nt][0]*invA, o[nt][1]*invA};
        float2 oB{o[nt][2]*invB, o[nt][3]*invB};
        *(float2*)&Og[((size_t)b*SS + rowA)     * DD + col] = oA;
        *(float2*)&Og[((size_t)b*SS + rowA + 8) * DD + col] = oB;
    }
}

// ---------------------------------------------------------------------------
// Launch
// ---------------------------------------------------------------------------
extern "C" void kernel_launch(void* const* d_in, const int* in_sizes, int n_in,
                              void* d_out, int out_size)
{
    const float* x_q = (const float*)d_in[0];
    const float* x_k = (const float*)d_in[1];
    const float* x_v = (const float*)d_in[2];
    const void*  mask = d_in[3];
    const float* Wq = (const float*)d_in[4];
    const float* bq = (const float*)d_in[5];
    const float* Wk = (const float*)d_in[6];
    const float* bk = (const float*)d_in[7];
    const float* Wv = (const float*)d_in[8];
    const float* bv = (const float*)d_in[9];
    const float* Wo = (const float*)d_in[10];
    const float* bo = (const float*)d_in[11];
    float* out = (float*)d_out;

    float *Qp, *Kp, *Vp, *Op, *Mp;
    cudaGetSymbolAddress((void**)&Qp, g_Q);
    cudaGetSymbolAddress((void**)&Kp, g_K);
    cudaGetSymbolAddress((void**)&Vp, g_V);
    cudaGetSymbolAddress((void**)&Op, g_O);
    cudaGetSymbolAddress((void**)&Mp, g_maskadd);

    cudaFuncSetAttribute(attn_mma,
                         cudaFuncAttributeMaxDynamicSharedMemorySize, AT_SMEM);
    cudaFuncSetAttribute(gemm_bf16s,
                         cudaFuncAttributeMaxDynamicSharedMemorySize, GEMM_SMEM);

    dim3 ggrid(DD/128, MTOT/128);   // (8, 32)

    mask_convert<<<(BB*SS + 255)/256, 256>>>(mask, Mp);

    gemm_bf16s<<<ggrid, 256, GEMM_SMEM>>>(x_q, Wq, bq, Qp);
    gemm_bf16s<<<ggrid, 256, GEMM_SMEM>>>(x_k, Wk, bk, Kp);
    gemm_bf16s<<<ggrid, 256, GEMM_SMEM>>>(x_v, Wv, bv, Vp);

    attn_mma<<<dim3(SS/128, HH, BB), 256, AT_SMEM>>>(Mp, Qp, Kp, Vp, Op);

    gemm_bf16s<<<ggrid, 256, GEMM_SMEM>>>(Op, Wo, bo, out);
}

// round 6
// speedup vs baseline: 4.7916x; 1.0493x over previous
#include <cuda_runtime.h>
#include <cuda_bf16.h>
#include <cstdint>

// Problem constants
#define BB 2
#define SS 2048
#define DD 1024
#define HH 16
#define DHD 64
#define MTOT (BB*SS)   // 4096
#define GK 1024        // GEMM K
#define TKC 32         // GEMM K chunk
#define NCH (GK/TKC)   // 32 chunks

// Scratch (allocation-free rule: __device__ globals)
__device__ float g_maskadd[BB*SS];
__device__ __nv_bfloat16 g_Xh[MTOT*GK], g_Xl[MTOT*GK];     // split input (reused)
__device__ __nv_bfloat16 g_Wh[DD*GK],  g_Wl[DD*GK];        // split weight (reused)
__device__ __nv_bfloat16 g_Qh[MTOT*DD], g_Ql[MTOT*DD];
__device__ __nv_bfloat16 g_Kh[MTOT*DD], g_Kl[MTOT*DD];
__device__ __nv_bfloat16 g_Vh[MTOT*DD], g_Vl[MTOT*DD];
__device__ __nv_bfloat16 g_Oh[MTOT*DD], g_Ol[MTOT*DD];

// ---------------------------------------------------------------------------
// helpers
// ---------------------------------------------------------------------------
__device__ __forceinline__ uint32_t smem_u32(const void* p) {
    uint32_t a;
    asm("{ .reg .u64 t; cvta.to.shared.u64 t, %1; cvt.u32.u64 %0, t; }"
        : "=r"(a) : "l"(p));
    return a;
}
__device__ __forceinline__ void ldsm4(uint32_t* r, uint32_t addr) {
    asm volatile("ldmatrix.sync.aligned.m8n8.x4.shared.b16 {%0,%1,%2,%3}, [%4];"
                 : "=r"(r[0]), "=r"(r[1]), "=r"(r[2]), "=r"(r[3]) : "r"(addr));
}
__device__ __forceinline__ void ldsm4t(uint32_t* r, uint32_t addr) {
    asm volatile("ldmatrix.sync.aligned.m8n8.x4.trans.shared.b16 {%0,%1,%2,%3}, [%4];"
                 : "=r"(r[0]), "=r"(r[1]), "=r"(r[2]), "=r"(r[3]) : "r"(addr));
}
__device__ __forceinline__ void mma_bf16(float* c, const uint32_t* a,
                                         const uint32_t* b) {
    asm volatile(
        "mma.sync.aligned.m16n8k16.row.col.f32.bf16.bf16.f32 "
        "{%0,%1,%2,%3}, {%4,%5,%6,%7}, {%8,%9}, {%0,%1,%2,%3};"
        : "+f"(c[0]), "+f"(c[1]), "+f"(c[2]), "+f"(c[3])
        : "r"(a[0]), "r"(a[1]), "r"(a[2]), "r"(a[3]), "r"(b[0]), "r"(b[1]));
}
__device__ __forceinline__ uint32_t pack_bf16(__nv_bfloat16 x, __nv_bfloat16 y) {
    __nv_bfloat162 t(x, y);
    return *reinterpret_cast<uint32_t*>(&t);
}
__device__ __forceinline__ uint32_t cvt_bf16x2(float lo, float hi) {
    uint32_t d;
    asm("cvt.rn.bf16x2.f32 %0, %1, %2;" : "=r"(d) : "f"(hi), "f"(lo));
    return d;
}
__device__ __forceinline__ uint32_t sw128(uint32_t off) {
    return off ^ ((off >> 3) & 0x70);
}
__device__ __forceinline__ void cp16(uint32_t dst, const void* src) {
    asm volatile("cp.async.cg.shared.global [%0], [%1], 16;"
                 :: "r"(dst), "l"(src) : "memory");
}
#define CP_COMMIT() asm volatile("cp.async.commit_group;" ::: "memory")
#define CP_WAIT(n)  asm volatile("cp.async.wait_group %0;" :: "n"(n) : "memory")

// ---------------------------------------------------------------------------
// Mask conversion
// ---------------------------------------------------------------------------
__global__ void mask_convert(const void* __restrict__ mask_raw,
                             float* __restrict__ madd)
{
    const unsigned* mw = (const unsigned*)mask_raw;
    bool is_int32 = true;
    #pragma unroll
    for (int i = 0; i < 64; i++)
        if (mw[i] > 1u) is_int32 = false;

    const int idx = blockIdx.x * blockDim.x + threadIdx.x;
    if (idx < BB * SS) {
        int m = is_int32 ? (int)mw[idx]
                         : (int)((const unsigned char*)mask_raw)[idx];
        madd[idx] = m ? 0.0f : -1e9f;
    }
}

// ---------------------------------------------------------------------------
// fp32 -> bf16 hi/lo split prepass
// ---------------------------------------------------------------------------
__global__ void split_pair(const float* __restrict__ x,
                           __nv_bfloat16* __restrict__ hi,
                           __nv_bfloat16* __restrict__ lo, int n4)
{
    const int i = blockIdx.x * blockDim.x + threadIdx.x;
    if (i >= n4) return;
    float4 v = ((const float4*)x)[i];
    __nv_bfloat16 h0 = __float2bfloat16(v.x), h1 = __float2bfloat16(v.y);
    __nv_bfloat16 h2 = __float2bfloat16(v.z), h3 = __float2bfloat16(v.w);
    uint2 hp{pack_bf16(h0, h1), pack_bf16(h2, h3)};
    uint2 lp{pack_bf16(__float2bfloat16(v.x - __bfloat162float(h0)),
                       __float2bfloat16(v.y - __bfloat162float(h1))),
             pack_bf16(__float2bfloat16(v.z - __bfloat162float(h2)),
                       __float2bfloat16(v.w - __bfloat162float(h3)))};
    ((uint2*)hi)[i] = hp;
    ((uint2*)lo)[i] = lp;
}

// ---------------------------------------------------------------------------
// Pre-split tensor GEMM: C = (Ah+Al) @ (Bh+Bl)^T + bias
// CTA tile 128x128, warp tile 32x64, K chunk 32, cp.async 4-stage pipeline.
// Stage layout (32KB): A-tile 16KB [row(128B) = hi 64B | lo 64B], B-tile 16KB.
// wantf: 1 -> write fp32 C; 0 -> write bf16 hi/lo pair (Ch, Cl).
// ---------------------------------------------------------------------------
#define GST 4
#define GSTAGE 32768u
#define GEMM_SMEM (GST*GSTAGE)

__global__ __launch_bounds__(256, 1) void gemm_pre(
    const __nv_bfloat16* __restrict__ Ah, const __nv_bfloat16* __restrict__ Al,
    const __nv_bfloat16* __restrict__ Bh, const __nv_bfloat16* __restrict__ Bl,
    const float* __restrict__ bias, float* __restrict__ Cf,
    __nv_bfloat16* __restrict__ Ch, __nv_bfloat16* __restrict__ Cl, int wantf)
{
    extern __shared__ char smem[];
    const uint32_t sb = smem_u32(smem);
    const int t = threadIdx.x, lane = t & 31, wid = t >> 5;
    const int m0 = blockIdx.y * 128, n0 = blockIdx.x * 128;
    const int mw = (wid >> 1) * 32, nw = (wid & 1) * 64;
    const int g = lane >> 3, r8 = lane & 7;

    auto issue = [&](int ch) {
        const int k0 = ch * TKC;
        const uint32_t abase = sb + (uint32_t)(ch % GST) * GSTAGE;
        const uint32_t bbase = abase + 16384u;
        #pragma unroll
        for (int i = 0; i < 4; i++) {
            const int idx = t + i * 256;
            const int row = idx >> 3, sub = idx & 7;
            const int s3 = sub & 3;
            const uint32_t doff = sw128((uint32_t)row * 128
                                        + (sub < 4 ? 0u : 64u) + (uint32_t)s3 * 16);
            cp16(abase + doff,
                 (sub < 4 ? Ah : Al) + (size_t)(m0 + row) * GK + k0 + s3 * 8);
            cp16(bbase + doff,
                 (sub < 4 ? Bh : Bl) + (size_t)(n0 + row) * GK + k0 + s3 * 8);
        }
        CP_COMMIT();
    };

    issue(0); issue(1); issue(2);

    const uint32_t baseA_off = (uint32_t)(mw + (g & 1) * 8 + r8) * 128
                             + (uint32_t)(g >> 1) * 16;
    const uint32_t baseB_off = (uint32_t)(nw + (g >> 1) * 8 + r8) * 128
                             + (uint32_t)(g & 1) * 16;

    float acc[2][8][4];
    #pragma unroll
    for (int mt = 0; mt < 2; mt++)
        #pragma unroll
        for (int nt = 0; nt < 8; nt++)
            #pragma unroll
            for (int c = 0; c < 4; c++) acc[mt][nt][c] = 0.0f;

    for (int ch = 0; ch < NCH; ch++) {
        CP_WAIT(GST - 2);
        __syncthreads();
        if (ch + GST - 1 < NCH) issue(ch + GST - 1);

        const uint32_t sA = sb + (uint32_t)(ch % GST) * GSTAGE;
        const uint32_t sB = sA + 16384u;

        #pragma unroll
        for (int ks = 0; ks < 2; ks++) {
            uint32_t af[2][2][4];
            #pragma unroll
            for (int mt = 0; mt < 2; mt++)
                #pragma unroll
                for (int p = 0; p < 2; p++) {
                    const uint32_t off = baseA_off + (uint32_t)mt * 2048
                                       + (uint32_t)p * 64 + (uint32_t)ks * 32;
                    ldsm4(af[mt][p], sA + sw128(off));
                }
            uint32_t bf_[2][8][2];
            #pragma unroll
            for (int np = 0; np < 4; np++)
                #pragma unroll
                for (int p = 0; p < 2; p++) {
                    uint32_t q[4];
                    const uint32_t off = baseB_off + (uint32_t)np * 2048
                                       + (uint32_t)p * 64 + (uint32_t)ks * 32;
                    ldsm4(q, sB + sw128(off));
                    bf_[p][np*2][0]   = q[0]; bf_[p][np*2][1]   = q[1];
                    bf_[p][np*2+1][0] = q[2]; bf_[p][np*2+1][1] = q[3];
                }
            #pragma unroll
            for (int mt = 0; mt < 2; mt++)
                #pragma unroll
                for (int nt = 0; nt < 8; nt++) {
                    mma_bf16(acc[mt][nt], af[mt][0], bf_[0][nt]);
                    mma_bf16(acc[mt][nt], af[mt][0], bf_[1][nt]);
                    mma_bf16(acc[mt][nt], af[mt][1], bf_[0][nt]);
                }
        }
        __syncthreads();
    }

    float bb[8][2];
    #pragma unroll
    for (int nt = 0; nt < 8; nt++) {
        const int col = n0 + nw + nt * 8 + (lane & 3) * 2;
        bb[nt][0] = bias[col];
        bb[nt][1] = bias[col + 1];
    }
    #pragma unroll
    for (int mt = 0; mt < 2; mt++) {
        const int row0 = m0 + mw + mt * 16 + (lane >> 2);
        #pragma unroll
        for (int nt = 0; nt < 8; nt++) {
            const int col = n0 + nw + nt * 8 + (lane & 3) * 2;
            float v0 = acc[mt][nt][0] + bb[nt][0];
            float v1 = acc[mt][nt][1] + bb[nt][1];
            float v2 = acc[mt][nt][2] + bb[nt][0];
            float v3 = acc[mt][nt][3] + bb[nt][1];
            if (wantf) {
                *(float2*)&Cf[(size_t)row0 * DD + col]       = float2{v0, v1};
                *(float2*)&Cf[(size_t)(row0 + 8) * DD + col] = float2{v2, v3};
            } else {
                uint32_t h0 = cvt_bf16x2(v0, v1), h1 = cvt_bf16x2(v2, v3);
                float r0 = v0 - __uint_as_float(h0 << 16);
                float r1 = v1 - __uint_as_float(h0 & 0xffff0000u);
                float r2 = v2 - __uint_as_float(h1 << 16);
                float r3 = v3 - __uint_as_float(h1 & 0xffff0000u);
                *(uint32_t*)&Ch[(size_t)row0 * DD + col]       = h0;
                *(uint32_t*)&Ch[(size_t)(row0 + 8) * DD + col] = h1;
                *(uint32_t*)&Cl[(size_t)row0 * DD + col]       = cvt_bf16x2(r0, r1);
                *(uint32_t*)&Cl[(size_t)(row0 + 8) * DD + col] = cvt_bf16x2(r2, r3);
            }
        }
    }
}

// ---------------------------------------------------------------------------
// Tensor flash attention, pre-split bf16 Q/K/V, cp.async 3-stage K/V pipeline.
// CTA: 128 queries x one (b,h). Q region: Qh 16KB | Ql 16KB.
// Stage (33792B): Kh 8K | Kl 8K | Vh 8K | Vl 8K | mask 256B | pad.
// Epilogue writes O as bf16 hi/lo pair for the final GEMM.
// ---------------------------------------------------------------------------
#define AST 3
#define ASTAGE 33792u
#define AQ_SZ 32768u
#define AT_SMEM (AQ_SZ + AST*ASTAGE)

__global__ __launch_bounds__(256, 1) void attn_mma(
    const float* __restrict__ madd,
    const __nv_bfloat16* __restrict__ Qh_g, const __nv_bfloat16* __restrict__ Ql_g,
    const __nv_bfloat16* __restrict__ Kh_g, const __nv_bfloat16* __restrict__ Kl_g,
    const __nv_bfloat16* __restrict__ Vh_g, const __nv_bfloat16* __restrict__ Vl_g,
    __nv_bfloat16* __restrict__ Oh_g, __nv_bfloat16* __restrict__ Ol_g)
{
    extern __shared__ char smem[];
    const uint32_t sb = smem_u32(smem);
    const int t = threadIdx.x, lane = t & 31, wid = t >> 5;
    const int b = blockIdx.z, h = blockIdx.y, q0 = blockIdx.x * 128;
    const int g = lane >> 3, r8 = lane & 7;

    const size_t boff = (size_t)b * SS * DD + (size_t)h * DHD;
    const __nv_bfloat16* Qhb = Qh_g + boff;
    const __nv_bfloat16* Qlb = Ql_g + boff;
    const __nv_bfloat16* Khb = Kh_g + boff;
    const __nv_bfloat16* Klb = Kl_g + boff;
    const __nv_bfloat16* Vhb = Vh_g + boff;
    const __nv_bfloat16* Vlb = Vl_g + boff;

    // ---- Q load (group 0)
    #pragma unroll
    for (int i = 0; i < 8; i++) {
        const int prec = i >> 2;
        const int idx = t + (i & 3) * 256;
        const int row = idx >> 3, sub = idx & 7;
        const uint32_t doff = (prec ? 16384u : 0u)
                            + sw128((uint32_t)row * 128 + (uint32_t)sub * 16);
        cp16(sb + doff,
             (prec ? Qlb : Qhb) + (size_t)(q0 + row) * DD + sub * 8);
    }
    CP_COMMIT();

    auto issue_kv = [&](int ch) {
        const int j0 = ch * 64;
        const uint32_t base = sb + AQ_SZ + (uint32_t)(ch % AST) * ASTAGE;
        #pragma unroll
        for (int i = 0; i < 8; i++) {
            const int tile = i >> 1;
            const int idx = t + (i & 1) * 256;
            const int row = idx >> 3, sub = idx & 7;
            const __nv_bfloat16* src =
                (tile == 0 ? Khb : tile == 1 ? Klb : tile == 2 ? Vhb : Vlb)
                + (size_t)(j0 + row) * DD + sub * 8;
            cp16(base + (uint32_t)tile * 8192u
                      + sw128((uint32_t)row * 128 + (uint32_t)sub * 16), src);
        }
        if (t < 16)
            cp16(base + 32768u + (uint32_t)t * 16, madd + b * SS + j0 + t * 4);
        CP_COMMIT();
    };

    issue_kv(0);
    issue_kv(1);
    CP_WAIT(2);        // Q group complete
    __syncthreads();

    uint32_t qf[2][4][4];
    {
        const uint32_t aoff = (uint32_t)(wid*16 + (g & 1)*8 + r8) * 128
                            + (uint32_t)(g >> 1) * 16;
        #pragma unroll
        for (int ks = 0; ks < 4; ks++) {
            ldsm4(qf[0][ks], sb + sw128(aoff + ks*32));
            ldsm4(qf[1][ks], sb + 16384u + sw128(aoff + ks*32));
        }
    }

    float o[8][4];
    #pragma unroll
    for (int nt = 0; nt < 8; nt++)
        #pragma unroll
        for (int c = 0; c < 4; c++) o[nt][c] = 0.0f;
    float mA = -1e30f, mB = -1e30f, lA = 0.0f, lB = 0.0f;

    const uint32_t kboff = (uint32_t)((g >> 1)*8 + r8) * 128 + (uint32_t)(g & 1)*16;
    const uint32_t vboff = (uint32_t)((g & 1)*8 + r8) * 128 + (uint32_t)(g >> 1)*16;

    const int NKT = SS / 64;   // 32
    for (int ch = 0; ch < NKT; ch++) {
        CP_WAIT(1);
        __syncthreads();
        if (ch + 2 < NKT) issue_kv(ch + 2);

        const uint32_t base = sb + AQ_SZ + (uint32_t)(ch % AST) * ASTAGE;
        const uint32_t sKh = base, sKl = base + 8192u;
        const uint32_t sVh = base + 16384u, sVl = base + 24576u;
        const float* maskS = (const float*)(smem + AQ_SZ
                             + (uint32_t)(ch % AST) * ASTAGE + 32768u);

        // ---- QK^T
        float s[8][4];
        #pragma unroll
        for (int nt = 0; nt < 8; nt++)
            #pragma unroll
            for (int c = 0; c < 4; c++) s[nt][c] = 0.0f;

        #pragma unroll
        for (int ks = 0; ks < 4; ks++) {
            #pragma unroll
            for (int nq = 0; nq < 4; nq++) {
                uint32_t bh[4], bl[4];
                const uint32_t off = kboff + (uint32_t)nq*2048 + (uint32_t)ks*32;
                ldsm4(bh, sKh + sw128(off));
                ldsm4(bl, sKl + sw128(off));
                mma_bf16(s[nq*2],   qf[0][ks], bh);
                mma_bf16(s[nq*2],   qf[0][ks], bl);
                mma_bf16(s[nq*2],   qf[1][ks], bh);
                mma_bf16(s[nq*2+1], qf[0][ks], bh + 2);
                mma_bf16(s[nq*2+1], qf[0][ks], bl + 2);
                mma_bf16(s[nq*2+1], qf[1][ks], bh + 2);
            }
        }

        // ---- scale + mask
        const int mbase = (lane & 3) * 2;
        #pragma unroll
        for (int nt = 0; nt < 8; nt++) {
            float2 mk = *(float2*)&maskS[mbase + nt*8];
            s[nt][0] = s[nt][0]*0.125f + mk.x;
            s[nt][1] = s[nt][1]*0.125f + mk.y;
            s[nt][2] = s[nt][2]*0.125f + mk.x;
            s[nt][3] = s[nt][3]*0.125f + mk.y;
        }

        // ---- online softmax
        float mxA = s[0][0], mxB = s[0][2];
        #pragma unroll
        for (int nt = 0; nt < 8; nt++) {
            mxA = fmaxf(mxA, fmaxf(s[nt][0], s[nt][1]));
            mxB = fmaxf(mxB, fmaxf(s[nt][2], s[nt][3]));
        }
        mxA = fmaxf(mxA, __shfl_xor_sync(0xffffffffu, mxA, 1));
        mxA = fmaxf(mxA, __shfl_xor_sync(0xffffffffu, mxA, 2));
        mxB = fmaxf(mxB, __shfl_xor_sync(0xffffffffu, mxB, 1));
        mxB = fmaxf(mxB, __shfl_xor_sync(0xffffffffu, mxB, 2));
        const float mnA = fmaxf(mA, mxA), mnB = fmaxf(mB, mxB);
        const float scA = __expf(mA - mnA), scB = __expf(mB - mnB);
        mA = mnA; mB = mnB;

        float sumA = 0.0f, sumB = 0.0f;
        #pragma unroll
        for (int nt = 0; nt < 8; nt++) {
            s[nt][0] = __expf(s[nt][0] - mnA);
            s[nt][1] = __expf(s[nt][1] - mnA);
            s[nt][2] = __expf(s[nt][2] - mnB);
            s[nt][3] = __expf(s[nt][3] - mnB);
            sumA += s[nt][0] + s[nt][1];
            sumB += s[nt][2] + s[nt][3];
        }
        sumA += __shfl_xor_sync(0xffffffffu, sumA, 1);
        sumA += __shfl_xor_sync(0xffffffffu, sumA, 2);
        sumB += __shfl_xor_sync(0xffffffffu, sumB, 1);
        sumB += __shfl_xor_sync(0xffffffffu, sumB, 2);
        lA = lA * scA + sumA;
        lB = lB * scB + sumB;
        #pragma unroll
        for (int nt = 0; nt < 8; nt++) {
            o[nt][0] *= scA; o[nt][1] *= scA;
            o[nt][2] *= scB; o[nt][3] *= scB;
        }

        // ---- pack P hi/lo into A-frags
        uint32_t ph[4][4], pl[4][4];
        #pragma unroll
        for (int ks = 0; ks < 4; ks++) {
            #pragma unroll
            for (int half = 0; half < 2; half++) {
                const int nt = ks*2 + half;
                uint32_t u0 = cvt_bf16x2(s[nt][0], s[nt][1]);
                uint32_t u1 = cvt_bf16x2(s[nt][2], s[nt][3]);
                ph[ks][half*2]   = u0;
                ph[ks][half*2+1] = u1;
                float r0 = s[nt][0] - __uint_as_float(u0 << 16);
                float r1 = s[nt][1] - __uint_as_float(u0 & 0xffff0000u);
                float r2 = s[nt][2] - __uint_as_float(u1 << 16);
                float r3 = s[nt][3] - __uint_as_float(u1 & 0xffff0000u);
                pl[ks][half*2]   = cvt_bf16x2(r0, r1);
                pl[ks][half*2+1] = cvt_bf16x2(r2, r3);
            }
        }

        // ---- PV
        #pragma unroll
        for (int nq = 0; nq < 4; nq++) {
            #pragma unroll
            for (int ks = 0; ks < 4; ks++) {
                uint32_t vh[4], vl[4];
                const uint32_t off = vboff + (uint32_t)ks*2048 + (uint32_t)nq*32;
                ldsm4t(vh, sVh + sw128(off));
                ldsm4t(vl, sVl + sw128(off));
                mma_bf16(o[nq*2],   ph[ks], vh);
                mma_bf16(o[nq*2],   ph[ks], vl);
                mma_bf16(o[nq*2],   pl[ks], vh);
                mma_bf16(o[nq*2+1], ph[ks], vh + 2);
                mma_bf16(o[nq*2+1], ph[ks], vl + 2);
                mma_bf16(o[nq*2+1], pl[ks], vh + 2);
            }
        }
        __syncthreads();
    }

    // ---- epilogue: O as hi/lo bf16
    const float invA = 1.0f / lA, invB = 1.0f / lB;
    const int rowA = q0 + wid*16 + (lane >> 2);
    #pragma unroll
    for (int nt = 0; nt < 8; nt++) {
        const int col = h*DHD + nt*8 + (lane & 3)*2;
        float a0 = o[nt][0]*invA, a1 = o[nt][1]*invA;
        float b0 = o[nt][2]*invB, b1 = o[nt][3]*invB;
        uint32_t hA = cvt_bf16x2(a0, a1), hB = cvt_bf16x2(b0, b1);
        float rA0 = a0 - __uint_as_float(hA << 16);
        float rA1 = a1 - __uint_as_float(hA & 0xffff0000u);
        float rB0 = b0 - __uint_as_float(hB << 16);
        float rB1 = b1 - __uint_as_float(hB & 0xffff0000u);
        const size_t r0 = ((size_t)b*SS + rowA) * DD + col;
        const size_t r1 = ((size_t)b*SS + rowA + 8) * DD + col;
        *(uint32_t*)&Oh_g[r0] = hA;
        *(uint32_t*)&Oh_g[r1] = hB;
        *(uint32_t*)&Ol_g[r0] = cvt_bf16x2(rA0, rA1);
        *(uint32_t*)&Ol_g[r1] = cvt_bf16x2(rB0, rB1);
    }
}

// ---------------------------------------------------------------------------
// Launch
// ---------------------------------------------------------------------------
extern "C" void kernel_launch(void* const* d_in, const int* in_sizes, int n_in,
                              void* d_out, int out_size)
{
    const float* x_q = (const float*)d_in[0];
    const float* x_k = (const float*)d_in[1];
    const float* x_v = (const float*)d_in[2];
    const void*  mask = d_in[3];
    const float* Wq = (const float*)d_in[4];
    const float* bq = (const float*)d_in[5];
    const float* Wk = (const float*)d_in[6];
    const float* bk = (const float*)d_in[7];
    const float* Wv = (const float*)d_in[8];
    const float* bv = (const float*)d_in[9];
    const float* Wo = (const float*)d_in[10];
    const float* bo = (const float*)d_in[11];
    float* out = (float*)d_out;

    float* Mp;
    __nv_bfloat16 *Xh, *Xl, *Wh, *Wl, *Qh, *Ql, *Kh, *Kl, *Vh, *Vl, *Oh, *Ol;
    cudaGetSymbolAddress((void**)&Mp, g_maskadd);
    cudaGetSymbolAddress((void**)&Xh, g_Xh); cudaGetSymbolAddress((void**)&Xl, g_Xl);
    cudaGetSymbolAddress((void**)&Wh, g_Wh); cudaGetSymbolAddress((void**)&Wl, g_Wl);
    cudaGetSymbolAddress((void**)&Qh, g_Qh); cudaGetSymbolAddress((void**)&Ql, g_Ql);
    cudaGetSymbolAddress((void**)&Kh, g_Kh); cudaGetSymbolAddress((void**)&Kl, g_Kl);
    cudaGetSymbolAddress((void**)&Vh, g_Vh); cudaGetSymbolAddress((void**)&Vl, g_Vl);
    cudaGetSymbolAddress((void**)&Oh, g_Oh); cudaGetSymbolAddress((void**)&Ol, g_Ol);

    cudaFuncSetAttribute(attn_mma,
                         cudaFuncAttributeMaxDynamicSharedMemorySize, AT_SMEM);
    cudaFuncSetAttribute(gemm_pre,
                         cudaFuncAttributeMaxDynamicSharedMemorySize, GEMM_SMEM);

    const int nX4 = MTOT * GK / 4;
    const int nW4 = DD * GK / 4;
    dim3 ggrid(DD/128, MTOT/128);   // (8, 32)

    mask_convert<<<(BB*SS + 255)/256, 256>>>(mask, Mp);

    // Q projection
    split_pair<<<nX4/256, 256>>>(x_q, Xh, Xl, nX4);
    split_pair<<<nW4/256, 256>>>(Wq, Wh, Wl, nW4);
    gemm_pre<<<ggrid, 256, GEMM_SMEM>>>(Xh, Xl, Wh, Wl, bq, nullptr, Qh, Ql, 0);
    // K projection
    split_pair<<<nX4/256, 256>>>(x_k, Xh, Xl, nX4);
    split_pair<<<nW4/256, 256>>>(Wk, Wh, Wl, nW4);
    gemm_pre<<<ggrid, 256, GEMM_SMEM>>>(Xh, Xl, Wh, Wl, bk, nullptr, Kh, Kl, 0);
    // V projection
    split_pair<<<nX4/256, 256>>>(x_v, Xh, Xl, nX4);
    split_pair<<<nW4/256, 256>>>(Wv, Wh, Wl, nW4);
    gemm_pre<<<ggrid, 256, GEMM_SMEM>>>(Xh, Xl, Wh, Wl, bv, nullptr, Vh, Vl, 0);

    attn_mma<<<dim3(SS/128, HH, BB), 256, AT_SMEM>>>(Mp, Qh, Ql, Kh, Kl,
                                                     Vh, Vl, Oh, Ol);

    // Output projection
    split_pair<<<nW4/256, 256>>>(Wo, Wh, Wl, nW4);
    gemm_pre<<<ggrid, 256, GEMM_SMEM>>>(Oh, Ol, Wh, Wl, bo, out, nullptr, nullptr, 1);
}

// round 7
// speedup vs baseline: 4.9555x; 1.0342x over previous
#include <cuda_runtime.h>
#include <cuda_bf16.h>
#include <cstdint>

// Problem constants
#define BB 2
#define SS 2048
#define DD 1024
#define HH 16
#define DHD 64
#define MTOT (BB*SS)   // 4096
#define GK 1024        // GEMM K
#define TKC 32         // GEMM K chunk
#define NCH (GK/TKC)   // 32 chunks

// Scratch (allocation-free rule: __device__ globals)
__device__ float g_maskadd[BB*SS];
__device__ __nv_bfloat16 g_Xh[MTOT*GK], g_Xl[MTOT*GK];
__device__ __nv_bfloat16 g_Wh[DD*GK],  g_Wl[DD*GK];
__device__ __nv_bfloat16 g_Qh[MTOT*DD], g_Ql[MTOT*DD];
__device__ __nv_bfloat16 g_Kh[MTOT*DD], g_Kl[MTOT*DD];
__device__ __nv_bfloat16 g_Vh[MTOT*DD], g_Vl[MTOT*DD];
__device__ __nv_bfloat16 g_Oh[MTOT*DD], g_Ol[MTOT*DD];

// ---------------------------------------------------------------------------
// helpers
// ---------------------------------------------------------------------------
__device__ __forceinline__ uint32_t smem_u32(const void* p) {
    uint32_t a;
    asm("{ .reg .u64 t; cvta.to.shared.u64 t, %1; cvt.u32.u64 %0, t; }"
        : "=r"(a) : "l"(p));
    return a;
}
__device__ __forceinline__ void ldsm4(uint32_t* r, uint32_t addr) {
    asm volatile("ldmatrix.sync.aligned.m8n8.x4.shared.b16 {%0,%1,%2,%3}, [%4];"
                 : "=r"(r[0]), "=r"(r[1]), "=r"(r[2]), "=r"(r[3]) : "r"(addr));
}
__device__ __forceinline__ void ldsm4t(uint32_t* r, uint32_t addr) {
    asm volatile("ldmatrix.sync.aligned.m8n8.x4.trans.shared.b16 {%0,%1,%2,%3}, [%4];"
                 : "=r"(r[0]), "=r"(r[1]), "=r"(r[2]), "=r"(r[3]) : "r"(addr));
}
__device__ __forceinline__ void mma_bf16(float* c, const uint32_t* a,
                                         const uint32_t* b) {
    asm volatile(
        "mma.sync.aligned.m16n8k16.row.col.f32.bf16.bf16.f32 "
        "{%0,%1,%2,%3}, {%4,%5,%6,%7}, {%8,%9}, {%0,%1,%2,%3};"
        : "+f"(c[0]), "+f"(c[1]), "+f"(c[2]), "+f"(c[3])
        : "r"(a[0]), "r"(a[1]), "r"(a[2]), "r"(a[3]), "r"(b[0]), "r"(b[1]));
}
__device__ __forceinline__ uint32_t pack_bf16(__nv_bfloat16 x, __nv_bfloat16 y) {
    __nv_bfloat162 t(x, y);
    return *reinterpret_cast<uint32_t*>(&t);
}
__device__ __forceinline__ uint32_t cvt_bf16x2(float lo, float hi) {
    uint32_t d;
    asm("cvt.rn.bf16x2.f32 %0, %1, %2;" : "=r"(d) : "f"(hi), "f"(lo));
    return d;
}
__device__ __forceinline__ uint32_t sw128(uint32_t off) {
    return off ^ ((off >> 3) & 0x70);
}
__device__ __forceinline__ void cp16(uint32_t dst, const void* src) {
    asm volatile("cp.async.cg.shared.global [%0], [%1], 16;"
                 :: "r"(dst), "l"(src) : "memory");
}
#define CP_COMMIT() asm volatile("cp.async.commit_group;" ::: "memory")
#define CP_WAIT(n)  asm volatile("cp.async.wait_group %0;" :: "n"(n) : "memory")

// ---------------------------------------------------------------------------
// Mask conversion
// ---------------------------------------------------------------------------
__global__ void mask_convert(const void* __restrict__ mask_raw,
                             float* __restrict__ madd)
{
    const unsigned* mw = (const unsigned*)mask_raw;
    bool is_int32 = true;
    #pragma unroll
    for (int i = 0; i < 64; i++)
        if (mw[i] > 1u) is_int32 = false;

    const int idx = blockIdx.x * blockDim.x + threadIdx.x;
    if (idx < BB * SS) {
        int m = is_int32 ? (int)mw[idx]
                         : (int)((const unsigned char*)mask_raw)[idx];
        madd[idx] = m ? 0.0f : -1e9f;
    }
}

// ---------------------------------------------------------------------------
// fp32 -> bf16 hi/lo split prepass
// ---------------------------------------------------------------------------
__global__ void split_pair(const float* __restrict__ x,
                           __nv_bfloat16* __restrict__ hi,
                           __nv_bfloat16* __restrict__ lo, int n4)
{
    const int i = blockIdx.x * blockDim.x + threadIdx.x;
    if (i >= n4) return;
    float4 v = ((const float4*)x)[i];
    __nv_bfloat16 h0 = __float2bfloat16(v.x), h1 = __float2bfloat16(v.y);
    __nv_bfloat16 h2 = __float2bfloat16(v.z), h3 = __float2bfloat16(v.w);
    uint2 hp{pack_bf16(h0, h1), pack_bf16(h2, h3)};
    uint2 lp{pack_bf16(__float2bfloat16(v.x - __bfloat162float(h0)),
                       __float2bfloat16(v.y - __bfloat162float(h1))),
             pack_bf16(__float2bfloat16(v.z - __bfloat162float(h2)),
                       __float2bfloat16(v.w - __bfloat162float(h3)))};
    ((uint2*)hi)[i] = hp;
    ((uint2*)lo)[i] = lp;
}

// ---------------------------------------------------------------------------
// Pre-split tensor GEMM: C = (Ah+Al) @ (Bh+Bl)^T + bias
// CTA tile 128x64, warp tile 32x32 (8 warps, 4m x 2n), K chunk 32,
// cp.async 3-stage. Stage 24KB: A 16KB [row = hi 64B | lo 64B], B 8KB.
// __launch_bounds__(256,2): 2 CTAs/SM for tensor-latency coverage.
// ---------------------------------------------------------------------------
#define GST 3
#define GSTAGE 24576u
#define GEMM_SMEM (GST*GSTAGE)

__global__ __launch_bounds__(256, 2) void gemm_pre(
    const __nv_bfloat16* __restrict__ Ah, const __nv_bfloat16* __restrict__ Al,
    const __nv_bfloat16* __restrict__ Bh, const __nv_bfloat16* __restrict__ Bl,
    const float* __restrict__ bias, float* __restrict__ Cf,
    __nv_bfloat16* __restrict__ Ch, __nv_bfloat16* __restrict__ Cl, int wantf)
{
    extern __shared__ char smem[];
    const uint32_t sb = smem_u32(smem);
    const int t = threadIdx.x, lane = t & 31, wid = t >> 5;
    const int m0 = blockIdx.y * 128, n0 = blockIdx.x * 64;
    const int mw = (wid & 3) * 32, nw = (wid >> 2) * 32;
    const int g = lane >> 3, r8 = lane & 7;

    auto issue = [&](int ch) {
        const int k0 = ch * TKC;
        const uint32_t abase = sb + (uint32_t)(ch % GST) * GSTAGE;
        const uint32_t bbase = abase + 16384u;
        #pragma unroll
        for (int i = 0; i < 4; i++) {           // A: 128 rows, hi+lo
            const int idx = t + i * 256;
            const int row = idx >> 3, sub = idx & 7;
            const int s3 = sub & 3;
            const uint32_t doff = sw128((uint32_t)row * 128
                                        + (sub < 4 ? 0u : 64u) + (uint32_t)s3 * 16);
            cp16(abase + doff,
                 (sub < 4 ? Ah : Al) + (size_t)(m0 + row) * GK + k0 + s3 * 8);
        }
        #pragma unroll
        for (int i = 0; i < 2; i++) {           // B: 64 rows, hi+lo
            const int idx = t + i * 256;
            const int row = idx >> 3, sub = idx & 7;
            const int s3 = sub & 3;
            const uint32_t doff = sw128((uint32_t)row * 128
                                        + (sub < 4 ? 0u : 64u) + (uint32_t)s3 * 16);
            cp16(bbase + doff,
                 (sub < 4 ? Bh : Bl) + (size_t)(n0 + row) * GK + k0 + s3 * 8);
        }
        CP_COMMIT();
    };

    issue(0); issue(1);

    const uint32_t baseA_off = (uint32_t)(mw + (g & 1) * 8 + r8) * 128
                             + (uint32_t)(g >> 1) * 16;
    const uint32_t baseB_off = (uint32_t)(nw + (g >> 1) * 8 + r8) * 128
                             + (uint32_t)(g & 1) * 16;

    float acc[2][4][4];
    #pragma unroll
    for (int mt = 0; mt < 2; mt++)
        #pragma unroll
        for (int nt = 0; nt < 4; nt++)
            #pragma unroll
            for (int c = 0; c < 4; c++) acc[mt][nt][c] = 0.0f;

    for (int ch = 0; ch < NCH; ch++) {
        CP_WAIT(1);
        __syncthreads();
        if (ch + 2 < NCH) issue(ch + 2);

        const uint32_t sA = sb + (uint32_t)(ch % GST) * GSTAGE;
        const uint32_t sB = sA + 16384u;

        #pragma unroll
        for (int ks = 0; ks < 2; ks++) {
            uint32_t af[2][2][4];
            #pragma unroll
            for (int mt = 0; mt < 2; mt++)
                #pragma unroll
                for (int p = 0; p < 2; p++) {
                    const uint32_t off = baseA_off + (uint32_t)mt * 2048
                                       + (uint32_t)p * 64 + (uint32_t)ks * 32;
                    ldsm4(af[mt][p], sA + sw128(off));
                }
            uint32_t bf_[2][4][2];
            #pragma unroll
            for (int np = 0; np < 2; np++)
                #pragma unroll
                for (int p = 0; p < 2; p++) {
                    uint32_t q[4];
                    const uint32_t off = baseB_off + (uint32_t)np * 2048
                                       + (uint32_t)p * 64 + (uint32_t)ks * 32;
                    ldsm4(q, sB + sw128(off));
                    bf_[p][np*2][0]   = q[0]; bf_[p][np*2][1]   = q[1];
                    bf_[p][np*2+1][0] = q[2]; bf_[p][np*2+1][1] = q[3];
                }
            #pragma unroll
            for (int mt = 0; mt < 2; mt++)
                #pragma unroll
                for (int nt = 0; nt < 4; nt++) {
                    mma_bf16(acc[mt][nt], af[mt][0], bf_[0][nt]);
                    mma_bf16(acc[mt][nt], af[mt][0], bf_[1][nt]);
                    mma_bf16(acc[mt][nt], af[mt][1], bf_[0][nt]);
                }
        }
        __syncthreads();
    }

    float bb[4][2];
    #pragma unroll
    for (int nt = 0; nt < 4; nt++) {
        const int col = n0 + nw + nt * 8 + (lane & 3) * 2;
        bb[nt][0] = bias[col];
        bb[nt][1] = bias[col + 1];
    }
    #pragma unroll
    for (int mt = 0; mt < 2; mt++) {
        const int row0 = m0 + mw + mt * 16 + (lane >> 2);
        #pragma unroll
        for (int nt = 0; nt < 4; nt++) {
            const int col = n0 + nw + nt * 8 + (lane & 3) * 2;
            float v0 = acc[mt][nt][0] + bb[nt][0];
            float v1 = acc[mt][nt][1] + bb[nt][1];
            float v2 = acc[mt][nt][2] + bb[nt][0];
            float v3 = acc[mt][nt][3] + bb[nt][1];
            if (wantf) {
                *(float2*)&Cf[(size_t)row0 * DD + col]       = float2{v0, v1};
                *(float2*)&Cf[(size_t)(row0 + 8) * DD + col] = float2{v2, v3};
            } else {
                uint32_t h0 = cvt_bf16x2(v0, v1), h1 = cvt_bf16x2(v2, v3);
                float r0 = v0 - __uint_as_float(h0 << 16);
                float r1 = v1 - __uint_as_float(h0 & 0xffff0000u);
                float r2 = v2 - __uint_as_float(h1 << 16);
                float r3 = v3 - __uint_as_float(h1 & 0xffff0000u);
                *(uint32_t*)&Ch[(size_t)row0 * DD + col]       = h0;
                *(uint32_t*)&Ch[(size_t)(row0 + 8) * DD + col] = h1;
                *(uint32_t*)&Cl[(size_t)row0 * DD + col]       = cvt_bf16x2(r0, r1);
                *(uint32_t*)&Cl[(size_t)(row0 + 8) * DD + col] = cvt_bf16x2(r2, r3);
            }
        }
    }
}

// ---------------------------------------------------------------------------
// Tensor flash attention (unchanged, passing): pre-split Q/K/V, 3-stage pipe.
// ---------------------------------------------------------------------------
#define AST 3
#define ASTAGE 33792u
#define AQ_SZ 32768u
#define AT_SMEM (AQ_SZ + AST*ASTAGE)

__global__ __launch_bounds__(256, 1) void attn_mma(
    const float* __restrict__ madd,
    const __nv_bfloat16* __restrict__ Qh_g, const __nv_bfloat16* __restrict__ Ql_g,
    const __nv_bfloat16* __restrict__ Kh_g, const __nv_bfloat16* __restrict__ Kl_g,
    const __nv_bfloat16* __restrict__ Vh_g, const __nv_bfloat16* __restrict__ Vl_g,
    __nv_bfloat16* __restrict__ Oh_g, __nv_bfloat16* __restrict__ Ol_g)
{
    extern __shared__ char smem[];
    const uint32_t sb = smem_u32(smem);
    const int t = threadIdx.x, lane = t & 31, wid = t >> 5;
    const int b = blockIdx.z, h = blockIdx.y, q0 = blockIdx.x * 128;
    const int g = lane >> 3, r8 = lane & 7;

    const size_t boff = (size_t)b * SS * DD + (size_t)h * DHD;
    const __nv_bfloat16* Qhb = Qh_g + boff;
    const __nv_bfloat16* Qlb = Ql_g + boff;
    const __nv_bfloat16* Khb = Kh_g + boff;
    const __nv_bfloat16* Klb = Kl_g + boff;
    const __nv_bfloat16* Vhb = Vh_g + boff;
    const __nv_bfloat16* Vlb = Vl_g + boff;

    #pragma unroll
    for (int i = 0; i < 8; i++) {
        const int prec = i >> 2;
        const int idx = t + (i & 3) * 256;
        const int row = idx >> 3, sub = idx & 7;
        const uint32_t doff = (prec ? 16384u : 0u)
                            + sw128((uint32_t)row * 128 + (uint32_t)sub * 16);
        cp16(sb + doff,
             (prec ? Qlb : Qhb) + (size_t)(q0 + row) * DD + sub * 8);
    }
    CP_COMMIT();

    auto issue_kv = [&](int ch) {
        const int j0 = ch * 64;
        const uint32_t base = sb + AQ_SZ + (uint32_t)(ch % AST) * ASTAGE;
        #pragma unroll
        for (int i = 0; i < 8; i++) {
            const int tile = i >> 1;
            const int idx = t + (i & 1) * 256;
            const int row = idx >> 3, sub = idx & 7;
            const __nv_bfloat16* src =
                (tile == 0 ? Khb : tile == 1 ? Klb : tile == 2 ? Vhb : Vlb)
                + (size_t)(j0 + row) * DD + sub * 8;
            cp16(base + (uint32_t)tile * 8192u
                      + sw128((uint32_t)row * 128 + (uint32_t)sub * 16), src);
        }
        if (t < 16)
            cp16(base + 32768u + (uint32_t)t * 16, madd + b * SS + j0 + t * 4);
        CP_COMMIT();
    };

    issue_kv(0);
    issue_kv(1);
    CP_WAIT(2);
    __syncthreads();

    uint32_t qf[2][4][4];
    {
        const uint32_t aoff = (uint32_t)(wid*16 + (g & 1)*8 + r8) * 128
                            + (uint32_t)(g >> 1) * 16;
        #pragma unroll
        for (int ks = 0; ks < 4; ks++) {
            ldsm4(qf[0][ks], sb + sw128(aoff + ks*32));
            ldsm4(qf[1][ks], sb + 16384u + sw128(aoff + ks*32));
        }
    }

    float o[8][4];
    #pragma unroll
    for (int nt = 0; nt < 8; nt++)
        #pragma unroll
        for (int c = 0; c < 4; c++) o[nt][c] = 0.0f;
    float mA = -1e30f, mB = -1e30f, lA = 0.0f, lB = 0.0f;

    const uint32_t kboff = (uint32_t)((g >> 1)*8 + r8) * 128 + (uint32_t)(g & 1)*16;
    const uint32_t vboff = (uint32_t)((g & 1)*8 + r8) * 128 + (uint32_t)(g >> 1)*16;

    const int NKT = SS / 64;
    for (int ch = 0; ch < NKT; ch++) {
        CP_WAIT(1);
        __syncthreads();
        if (ch + 2 < NKT) issue_kv(ch + 2);

        const uint32_t base = sb + AQ_SZ + (uint32_t)(ch % AST) * ASTAGE;
        const uint32_t sKh = base, sKl = base + 8192u;
        const uint32_t sVh = base + 16384u, sVl = base + 24576u;
        const float* maskS = (const float*)(smem + AQ_SZ
                             + (uint32_t)(ch % AST) * ASTAGE + 32768u);

        float s[8][4];
        #pragma unroll
        for (int nt = 0; nt < 8; nt++)
            #pragma unroll
            for (int c = 0; c < 4; c++) s[nt][c] = 0.0f;

        #pragma unroll
        for (int ks = 0; ks < 4; ks++) {
            #pragma unroll
            for (int nq = 0; nq < 4; nq++) {
                uint32_t bh[4], bl[4];
                const uint32_t off = kboff + (uint32_t)nq*2048 + (uint32_t)ks*32;
                ldsm4(bh, sKh + sw128(off));
                ldsm4(bl, sKl + sw128(off));
                mma_bf16(s[nq*2],   qf[0][ks], bh);
                mma_bf16(s[nq*2],   qf[0][ks], bl);
                mma_bf16(s[nq*2],   qf[1][ks], bh);
                mma_bf16(s[nq*2+1], qf[0][ks], bh + 2);
                mma_bf16(s[nq*2+1], qf[0][ks], bl + 2);
                mma_bf16(s[nq*2+1], qf[1][ks], bh + 2);
            }
        }

        const int mbase = (lane & 3) * 2;
        #pragma unroll
        for (int nt = 0; nt < 8; nt++) {
            float2 mk = *(float2*)&maskS[mbase + nt*8];
            s[nt][0] = s[nt][0]*0.125f + mk.x;
            s[nt][1] = s[nt][1]*0.125f + mk.y;
            s[nt][2] = s[nt][2]*0.125f + mk.x;
            s[nt][3] = s[nt][3]*0.125f + mk.y;
        }

        float mxA = s[0][0], mxB = s[0][2];
        #pragma unroll
        for (int nt = 0; nt < 8; nt++) {
            mxA = fmaxf(mxA, fmaxf(s[nt][0], s[nt][1]));
            mxB = fmaxf(mxB, fmaxf(s[nt][2], s[nt][3]));
        }
        mxA = fmaxf(mxA, __shfl_xor_sync(0xffffffffu, mxA, 1));
        mxA = fmaxf(mxA, __shfl_xor_sync(0xffffffffu, mxA, 2));
        mxB = fmaxf(mxB, __shfl_xor_sync(0xffffffffu, mxB, 1));
        mxB = fmaxf(mxB, __shfl_xor_sync(0xffffffffu, mxB, 2));
        const float mnA = fmaxf(mA, mxA), mnB = fmaxf(mB, mxB);
        const float scA = __expf(mA - mnA), scB = __expf(mB - mnB);
        mA = mnA; mB = mnB;

        float sumA = 0.0f, sumB = 0.0f;
        #pragma unroll
        for (int nt = 0; nt < 8; nt++) {
            s[nt][0] = __expf(s[nt][0] - mnA);
            s[nt][1] = __expf(s[nt][1] - mnA);
            s[nt][2] = __expf(s[nt][2] - mnB);
            s[nt][3] = __expf(s[nt][3] - mnB);
            sumA += s[nt][0] + s[nt][1];
            sumB += s[nt][2] + s[nt][3];
        }
        sumA += __shfl_xor_sync(0xffffffffu, sumA, 1);
        sumA += __shfl_xor_sync(0xffffffffu, sumA, 2);
        sumB += __shfl_xor_sync(0xffffffffu, sumB, 1);
        sumB += __shfl_xor_sync(0xffffffffu, sumB, 2);
        lA = lA * scA + sumA;
        lB = lB * scB + sumB;
        #pragma unroll
        for (int nt = 0; nt < 8; nt++) {
            o[nt][0] *= scA; o[nt][1] *= scA;
            o[nt][2] *= scB; o[nt][3] *= scB;
        }

        uint32_t ph[4][4], pl[4][4];
        #pragma unroll
        for (int ks = 0; ks < 4; ks++) {
            #pragma unroll
            for (int half = 0; half < 2; half++) {
                const int nt = ks*2 + half;
                uint32_t u0 = cvt_bf16x2(s[nt][0], s[nt][1]);
                uint32_t u1 = cvt_bf16x2(s[nt][2], s[nt][3]);
                ph[ks][half*2]   = u0;
                ph[ks][half*2+1] = u1;
                float r0 = s[nt][0] - __uint_as_float(u0 << 16);
                float r1 = s[nt][1] - __uint_as_float(u0 & 0xffff0000u);
                float r2 = s[nt][2] - __uint_as_float(u1 << 16);
                float r3 = s[nt][3] - __uint_as_float(u1 & 0xffff0000u);
                pl[ks][half*2]   = cvt_bf16x2(r0, r1);
                pl[ks][half*2+1] = cvt_bf16x2(r2, r3);
            }
        }

        #pragma unroll
        for (int nq = 0; nq < 4; nq++) {
            #pragma unroll
            for (int ks = 0; ks < 4; ks++) {
                uint32_t vh[4], vl[4];
                const uint32_t off = vboff + (uint32_t)ks*2048 + (uint32_t)nq*32;
                ldsm4t(vh, sVh + sw128(off));
                ldsm4t(vl, sVl + sw128(off));
                mma_bf16(o[nq*2],   ph[ks], vh);
                mma_bf16(o[nq*2],   ph[ks], vl);
                mma_bf16(o[nq*2],   pl[ks], vh);
                mma_bf16(o[nq*2+1], ph[ks], vh + 2);
                mma_bf16(o[nq*2+1], ph[ks], vl + 2);
                mma_bf16(o[nq*2+1], pl[ks], vh + 2);
            }
        }
        __syncthreads();
    }

    const float invA = 1.0f / lA, invB = 1.0f / lB;
    const int rowA = q0 + wid*16 + (lane >> 2);
    #pragma unroll
    for (int nt = 0; nt < 8; nt++) {
        const int col = h*DHD + nt*8 + (lane & 3)*2;
        float a0 = o[nt][0]*invA, a1 = o[nt][1]*invA;
        float b0 = o[nt][2]*invB, b1 = o[nt][3]*invB;
        uint32_t hA = cvt_bf16x2(a0, a1), hB = cvt_bf16x2(b0, b1);
        float rA0 = a0 - __uint_as_float(hA << 16);
        float rA1 = a1 - __uint_as_float(hA & 0xffff0000u);
        float rB0 = b0 - __uint_as_float(hB << 16);
        float rB1 = b1 - __uint_as_float(hB & 0xffff0000u);
        const size_t r0 = ((size_t)b*SS + rowA) * DD + col;
        const size_t r1 = ((size_t)b*SS + rowA + 8) * DD + col;
        *(uint32_t*)&Oh_g[r0] = hA;
        *(uint32_t*)&Oh_g[r1] = hB;
        *(uint32_t*)&Ol_g[r0] = cvt_bf16x2(rA0, rA1);
        *(uint32_t*)&Ol_g[r1] = cvt_bf16x2(rB0, rB1);
    }
}

// ---------------------------------------------------------------------------
// Launch
// ---------------------------------------------------------------------------
extern "C" void kernel_launch(void* const* d_in, const int* in_sizes, int n_in,
                              void* d_out, int out_size)
{
    const float* x_q = (const float*)d_in[0];
    const float* x_k = (const float*)d_in[1];
    const float* x_v = (const float*)d_in[2];
    const void*  mask = d_in[3];
    const float* Wq = (const float*)d_in[4];
    const float* bq = (const float*)d_in[5];
    const float* Wk = (const float*)d_in[6];
    const float* bk = (const float*)d_in[7];
    const float* Wv = (const float*)d_in[8];
    const float* bv = (const float*)d_in[9];
    const float* Wo = (const float*)d_in[10];
    const float* bo = (const float*)d_in[11];
    float* out = (float*)d_out;

    float* Mp;
    __nv_bfloat16 *Xh, *Xl, *Wh, *Wl, *Qh, *Ql, *Kh, *Kl, *Vh, *Vl, *Oh, *Ol;
    cudaGetSymbolAddress((void**)&Mp, g_maskadd);
    cudaGetSymbolAddress((void**)&Xh, g_Xh); cudaGetSymbolAddress((void**)&Xl, g_Xl);
    cudaGetSymbolAddress((void**)&Wh, g_Wh); cudaGetSymbolAddress((void**)&Wl, g_Wl);
    cudaGetSymbolAddress((void**)&Qh, g_Qh); cudaGetSymbolAddress((void**)&Ql, g_Ql);
    cudaGetSymbolAddress((void**)&Kh, g_Kh); cudaGetSymbolAddress((void**)&Kl, g_Kl);
    cudaGetSymbolAddress((void**)&Vh, g_Vh); cudaGetSymbolAddress((void**)&Vl, g_Vl);
    cudaGetSymbolAddress((void**)&Oh, g_Oh); cudaGetSymbolAddress((void**)&Ol, g_Ol);

    cudaFuncSetAttribute(attn_mma,
                         cudaFuncAttributeMaxDynamicSharedMemorySize, AT_SMEM);
    cudaFuncSetAttribute(gemm_pre,
                         cudaFuncAttributeMaxDynamicSharedMemorySize, GEMM_SMEM);

    const int nX4 = MTOT * GK / 4;
    const int nW4 = DD * GK / 4;
    dim3 ggrid(DD/64, MTOT/128);    // (16, 32) = 512 CTAs

    mask_convert<<<(BB*SS + 255)/256, 256>>>(mask, Mp);

    // Q projection
    split_pair<<<nX4/256, 256>>>(x_q, Xh, Xl, nX4);
    split_pair<<<nW4/256, 256>>>(Wq, Wh, Wl, nW4);
    gemm_pre<<<ggrid, 256, GEMM_SMEM>>>(Xh, Xl, Wh, Wl, bq, nullptr, Qh, Ql, 0);
    // K projection
    split_pair<<<nX4/256, 256>>>(x_k, Xh, Xl, nX4);
    split_pair<<<nW4/256, 256>>>(Wk, Wh, Wl, nW4);
    gemm_pre<<<ggrid, 256, GEMM_SMEM>>>(Xh, Xl, Wh, Wl, bk, nullptr, Kh, Kl, 0);
    // V projection
    split_pair<<<nX4/256, 256>>>(x_v, Xh, Xl, nX4);
    split_pair<<<nW4/256, 256>>>(Wv, Wh, Wl, nW4);
    gemm_pre<<<ggrid, 256, GEMM_SMEM>>>(Xh, Xl, Wh, Wl, bv, nullptr, Vh, Vl, 0);

    attn_mma<<<dim3(SS/128, HH, BB), 256, AT_SMEM>>>(Mp, Qh, Ql, Kh, Kl,
                                                     Vh, Vl, Oh, Ol);

    // Output projection
    split_pair<<<nW4/256, 256>>>(Wo, Wh, Wl, nW4);
    gemm_pre<<<ggrid, 256, GEMM_SMEM>>>(Oh, Ol, Wh, Wl, bo, out, nullptr, nullptr, 1);
}

// round 9
// speedup vs baseline: 5.0544x; 1.0200x over previous
#include <cuda_runtime.h>
#include <cuda_bf16.h>
#include <cstdint>

// Problem constants
#define BB 2
#define SS 2048
#define DD 1024
#define HH 16
#define DHD 64
#define MTOT (BB*SS)   // 4096
#define GK 1024        // GEMM K
#define TKC 32         // GEMM K chunk
#define NCH (GK/TKC)   // 32 chunks

// Scratch (allocation-free rule: __device__ globals)
__device__ float g_maskadd[BB*SS];
__device__ __nv_bfloat16 g_Xqh[MTOT*GK], g_Xql[MTOT*GK];
__device__ __nv_bfloat16 g_Xkh[MTOT*GK], g_Xkl[MTOT*GK];
__device__ __nv_bfloat16 g_Xvh[MTOT*GK], g_Xvl[MTOT*GK];
__device__ __nv_bfloat16 g_Wqh[DD*GK], g_Wql[DD*GK];
__device__ __nv_bfloat16 g_Wkh[DD*GK], g_Wkl[DD*GK];
__device__ __nv_bfloat16 g_Wvh[DD*GK], g_Wvl[DD*GK];
__device__ __nv_bfloat16 g_Woh[DD*GK], g_Wol[DD*GK];
__device__ __nv_bfloat16 g_Qh[MTOT*DD], g_Ql[MTOT*DD];
__device__ __nv_bfloat16 g_Kh[MTOT*DD], g_Kl[MTOT*DD];
__device__ __nv_bfloat16 g_Vh[MTOT*DD], g_Vl[MTOT*DD];
__device__ __nv_bfloat16 g_Oh[MTOT*DD], g_Ol[MTOT*DD];

// ---------------------------------------------------------------------------
// helpers
// ---------------------------------------------------------------------------
__device__ __forceinline__ uint32_t smem_u32(const void* p) {
    uint32_t a;
    asm("{ .reg .u64 t; cvta.to.shared.u64 t, %1; cvt.u32.u64 %0, t; }"
        : "=r"(a) : "l"(p));
    return a;
}
__device__ __forceinline__ void ldsm4(uint32_t* r, uint32_t addr) {
    asm volatile("ldmatrix.sync.aligned.m8n8.x4.shared.b16 {%0,%1,%2,%3}, [%4];"
                 : "=r"(r[0]), "=r"(r[1]), "=r"(r[2]), "=r"(r[3]) : "r"(addr));
}
__device__ __forceinline__ void ldsm4t(uint32_t* r, uint32_t addr) {
    asm volatile("ldmatrix.sync.aligned.m8n8.x4.trans.shared.b16 {%0,%1,%2,%3}, [%4];"
                 : "=r"(r[0]), "=r"(r[1]), "=r"(r[2]), "=r"(r[3]) : "r"(addr));
}
__device__ __forceinline__ void mma_bf16(float* c, const uint32_t* a,
                                         const uint32_t* b) {
    asm volatile(
        "mma.sync.aligned.m16n8k16.row.col.f32.bf16.bf16.f32 "
        "{%0,%1,%2,%3}, {%4,%5,%6,%7}, {%8,%9}, {%0,%1,%2,%3};"
        : "+f"(c[0]), "+f"(c[1]), "+f"(c[2]), "+f"(c[3])
        : "r"(a[0]), "r"(a[1]), "r"(a[2]), "r"(a[3]), "r"(b[0]), "r"(b[1]));
}
__device__ __forceinline__ uint32_t pack_bf16(__nv_bfloat16 x, __nv_bfloat16 y) {
    __nv_bfloat162 t(x, y);
    return *reinterpret_cast<uint32_t*>(&t);
}
__device__ __forceinline__ uint32_t cvt_bf16x2(float lo, float hi) {
    uint32_t d;
    asm("cvt.rn.bf16x2.f32 %0, %1, %2;" : "=r"(d) : "f"(hi), "f"(lo));
    return d;
}
__device__ __forceinline__ uint32_t sw128(uint32_t off) {
    return off ^ ((off >> 3) & 0x70);
}
__device__ __forceinline__ void cp16(uint32_t dst, const void* src) {
    asm volatile("cp.async.cg.shared.global [%0], [%1], 16;"
                 :: "r"(dst), "l"(src) : "memory");
}
#define CP_COMMIT() asm volatile("cp.async.commit_group;" ::: "memory")
#define CP_WAIT(n)  asm volatile("cp.async.wait_group %0;" :: "n"(n) : "memory")

// ---------------------------------------------------------------------------
// Mask conversion
// ---------------------------------------------------------------------------
__global__ void mask_convert(const void* __restrict__ mask_raw,
                             float* __restrict__ madd)
{
    const unsigned* mw = (const unsigned*)mask_raw;
    bool is_int32 = true;
    #pragma unroll
    for (int i = 0; i < 64; i++)
        if (mw[i] > 1u) is_int32 = false;

    const int idx = blockIdx.x * blockDim.x + threadIdx.x;
    if (idx < BB * SS) {
        int m = is_int32 ? (int)mw[idx]
                         : (int)((const unsigned char*)mask_raw)[idx];
        madd[idx] = m ? 0.0f : -1e9f;
    }
}

// ---------------------------------------------------------------------------
// Fused fp32 -> bf16 hi/lo split of all 7 tensors in one launch.
// Job table passed BY VALUE (kernel params are snapshotted -> graph-safe).
// ---------------------------------------------------------------------------
struct SplitJobs7 {
    const float* src[7];
    __nv_bfloat16* hi[7];
    __nv_bfloat16* lo[7];
};

#define NX4 (MTOT*GK/4)   // 1048576
#define NW4 (DD*GK/4)     // 262144
#define NSPLIT4 (3*NX4 + 4*NW4)

__global__ void split_all(SplitJobs7 jobs)
{
    const int i = blockIdx.x * blockDim.x + threadIdx.x;
    if (i >= NSPLIT4) return;
    int j, off;
    if (i < 3*NX4) { j = i / NX4; off = i - j*NX4; }
    else { int w = i - 3*NX4; j = 3 + w / NW4; off = w - (j-3)*NW4; }
    float4 v = ((const float4*)jobs.src[j])[off];
    __nv_bfloat16 h0 = __float2bfloat16(v.x), h1 = __float2bfloat16(v.y);
    __nv_bfloat16 h2 = __float2bfloat16(v.z), h3 = __float2bfloat16(v.w);
    uint2 hp{pack_bf16(h0, h1), pack_bf16(h2, h3)};
    uint2 lp{pack_bf16(__float2bfloat16(v.x - __bfloat162float(h0)),
                       __float2bfloat16(v.y - __bfloat162float(h1))),
             pack_bf16(__float2bfloat16(v.z - __bfloat162float(h2)),
                       __float2bfloat16(v.w - __bfloat162float(h3)))};
    ((uint2*)jobs.hi[j])[off] = hp;
    ((uint2*)jobs.lo[j])[off] = lp;
}

// ---------------------------------------------------------------------------
// Pre-split tensor GEMM (unchanged, passing): C = (Ah+Al) @ (Bh+Bl)^T + bias
// ---------------------------------------------------------------------------
#define GST 3
#define GSTAGE 24576u
#define GEMM_SMEM (GST*GSTAGE)

__global__ __launch_bounds__(256, 2) void gemm_pre(
    const __nv_bfloat16* __restrict__ Ah, const __nv_bfloat16* __restrict__ Al,
    const __nv_bfloat16* __restrict__ Bh, const __nv_bfloat16* __restrict__ Bl,
    const float* __restrict__ bias, float* __restrict__ Cf,
    __nv_bfloat16* __restrict__ Ch, __nv_bfloat16* __restrict__ Cl, int wantf)
{
    extern __shared__ char smem[];
    const uint32_t sb = smem_u32(smem);
    const int t = threadIdx.x, lane = t & 31, wid = t >> 5;
    const int m0 = blockIdx.y * 128, n0 = blockIdx.x * 64;
    const int mw = (wid & 3) * 32, nw = (wid >> 2) * 32;
    const int g = lane >> 3, r8 = lane & 7;

    auto issue = [&](int ch) {
        const int k0 = ch * TKC;
        const uint32_t abase = sb + (uint32_t)(ch % GST) * GSTAGE;
        const uint32_t bbase = abase + 16384u;
        #pragma unroll
        for (int i = 0; i < 4; i++) {
            const int idx = t + i * 256;
            const int row = idx >> 3, sub = idx & 7;
            const int s3 = sub & 3;
            const uint32_t doff = sw128((uint32_t)row * 128
                                        + (sub < 4 ? 0u : 64u) + (uint32_t)s3 * 16);
            cp16(abase + doff,
                 (sub < 4 ? Ah : Al) + (size_t)(m0 + row) * GK + k0 + s3 * 8);
        }
        #pragma unroll
        for (int i = 0; i < 2; i++) {
            const int idx = t + i * 256;
            const int row = idx >> 3, sub = idx & 7;
            const int s3 = sub & 3;
            const uint32_t doff = sw128((uint32_t)row * 128
                                        + (sub < 4 ? 0u : 64u) + (uint32_t)s3 * 16);
            cp16(bbase + doff,
                 (sub < 4 ? Bh : Bl) + (size_t)(n0 + row) * GK + k0 + s3 * 8);
        }
        CP_COMMIT();
    };

    issue(0); issue(1);

    const uint32_t baseA_off = (uint32_t)(mw + (g & 1) * 8 + r8) * 128
                             + (uint32_t)(g >> 1) * 16;
    const uint32_t baseB_off = (uint32_t)(nw + (g >> 1) * 8 + r8) * 128
                             + (uint32_t)(g & 1) * 16;

    float acc[2][4][4];
    #pragma unroll
    for (int mt = 0; mt < 2; mt++)
        #pragma unroll
        for (int nt = 0; nt < 4; nt++)
            #pragma unroll
            for (int c = 0; c < 4; c++) acc[mt][nt][c] = 0.0f;

    for (int ch = 0; ch < NCH; ch++) {
        CP_WAIT(1);
        __syncthreads();
        if (ch + 2 < NCH) issue(ch + 2);

        const uint32_t sA = sb + (uint32_t)(ch % GST) * GSTAGE;
        const uint32_t sB = sA + 16384u;

        #pragma unroll
        for (int ks = 0; ks < 2; ks++) {
            uint32_t af[2][2][4];
            #pragma unroll
            for (int mt = 0; mt < 2; mt++)
                #pragma unroll
                for (int p = 0; p < 2; p++) {
                    const uint32_t off = baseA_off + (uint32_t)mt * 2048
                                       + (uint32_t)p * 64 + (uint32_t)ks * 32;
                    ldsm4(af[mt][p], sA + sw128(off));
                }
            uint32_t bf_[2][4][2];
            #pragma unroll
            for (int np = 0; np < 2; np++)
                #pragma unroll
                for (int p = 0; p < 2; p++) {
                    uint32_t q[4];
                    const uint32_t off = baseB_off + (uint32_t)np * 2048
                                       + (uint32_t)p * 64 + (uint32_t)ks * 32;
                    ldsm4(q, sB + sw128(off));
                    bf_[p][np*2][0]   = q[0]; bf_[p][np*2][1]   = q[1];
                    bf_[p][np*2+1][0] = q[2]; bf_[p][np*2+1][1] = q[3];
                }
            #pragma unroll
            for (int mt = 0; mt < 2; mt++)
                #pragma unroll
                for (int nt = 0; nt < 4; nt++) {
                    mma_bf16(acc[mt][nt], af[mt][0], bf_[0][nt]);
                    mma_bf16(acc[mt][nt], af[mt][0], bf_[1][nt]);
                    mma_bf16(acc[mt][nt], af[mt][1], bf_[0][nt]);
                }
        }
        __syncthreads();
    }

    float bb[4][2];
    #pragma unroll
    for (int nt = 0; nt < 4; nt++) {
        const int col = n0 + nw + nt * 8 + (lane & 3) * 2;
        bb[nt][0] = bias[col];
        bb[nt][1] = bias[col + 1];
    }
    #pragma unroll
    for (int mt = 0; mt < 2; mt++) {
        const int row0 = m0 + mw + mt * 16 + (lane >> 2);
        #pragma unroll
        for (int nt = 0; nt < 4; nt++) {
            const int col = n0 + nw + nt * 8 + (lane & 3) * 2;
            float v0 = acc[mt][nt][0] + bb[nt][0];
            float v1 = acc[mt][nt][1] + bb[nt][1];
            float v2 = acc[mt][nt][2] + bb[nt][0];
            float v3 = acc[mt][nt][3] + bb[nt][1];
            if (wantf) {
                *(float2*)&Cf[(size_t)row0 * DD + col]       = float2{v0, v1};
                *(float2*)&Cf[(size_t)(row0 + 8) * DD + col] = float2{v2, v3};
            } else {
                uint32_t h0 = cvt_bf16x2(v0, v1), h1 = cvt_bf16x2(v2, v3);
                float r0 = v0 - __uint_as_float(h0 << 16);
                float r1 = v1 - __uint_as_float(h0 & 0xffff0000u);
                float r2 = v2 - __uint_as_float(h1 << 16);
                float r3 = v3 - __uint_as_float(h1 & 0xffff0000u);
                *(uint32_t*)&Ch[(size_t)row0 * DD + col]       = h0;
                *(uint32_t*)&Ch[(size_t)(row0 + 8) * DD + col] = h1;
                *(uint32_t*)&Cl[(size_t)row0 * DD + col]       = cvt_bf16x2(r0, r1);
                *(uint32_t*)&Cl[(size_t)(row0 + 8) * DD + col] = cvt_bf16x2(r2, r3);
            }
        }
    }
}

// ---------------------------------------------------------------------------
// Tensor flash attention, 2 CTAs/SM: 2-stage K/V pipeline, register diet
// (Ql frags re-loaded per tile; P hi/lo packed inside the PV ks-loop).
// ---------------------------------------------------------------------------
#define AST 2
#define ASTAGE 33792u
#define AQ_SZ 32768u
#define AT_SMEM (AQ_SZ + AST*ASTAGE)   // 100352 -> 2 CTAs/SM fits 228KB

__global__ __launch_bounds__(256, 2) void attn_mma(
    const float* __restrict__ madd,
    const __nv_bfloat16* __restrict__ Qh_g, const __nv_bfloat16* __restrict__ Ql_g,
    const __nv_bfloat16* __restrict__ Kh_g, const __nv_bfloat16* __restrict__ Kl_g,
    const __nv_bfloat16* __restrict__ Vh_g, const __nv_bfloat16* __restrict__ Vl_g,
    __nv_bfloat16* __restrict__ Oh_g, __nv_bfloat16* __restrict__ Ol_g)
{
    extern __shared__ char smem[];
    const uint32_t sb = smem_u32(smem);
    const int t = threadIdx.x, lane = t & 31, wid = t >> 5;
    const int b = blockIdx.z, h = blockIdx.y, q0 = blockIdx.x * 128;
    const int g = lane >> 3, r8 = lane & 7;

    const size_t boff = (size_t)b * SS * DD + (size_t)h * DHD;
    const __nv_bfloat16* Qhb = Qh_g + boff;
    const __nv_bfloat16* Qlb = Ql_g + boff;
    const __nv_bfloat16* Khb = Kh_g + boff;
    const __nv_bfloat16* Klb = Kl_g + boff;
    const __nv_bfloat16* Vhb = Vh_g + boff;
    const __nv_bfloat16* Vlb = Vl_g + boff;

    // Q load (hi @0, lo @16384); persists all kernel
    #pragma unroll
    for (int i = 0; i < 8; i++) {
        const int prec = i >> 2;
        const int idx = t + (i & 3) * 256;
        const int row = idx >> 3, sub = idx & 7;
        const uint32_t doff = (prec ? 16384u : 0u)
                            + sw128((uint32_t)row * 128 + (uint32_t)sub * 16);
        cp16(sb + doff,
             (prec ? Qlb : Qhb) + (size_t)(q0 + row) * DD + sub * 8);
    }
    CP_COMMIT();

    auto issue_kv = [&](int ch) {
        const int j0 = ch * 64;
        const uint32_t base = sb + AQ_SZ + (uint32_t)(ch % AST) * ASTAGE;
        #pragma unroll
        for (int i = 0; i < 8; i++) {
            const int tile = i >> 1;
            const int idx = t + (i & 1) * 256;
            const int row = idx >> 3, sub = idx & 7;
            const __nv_bfloat16* src =
                (tile == 0 ? Khb : tile == 1 ? Klb : tile == 2 ? Vhb : Vlb)
                + (size_t)(j0 + row) * DD + sub * 8;
            cp16(base + (uint32_t)tile * 8192u
                      + sw128((uint32_t)row * 128 + (uint32_t)sub * 16), src);
        }
        if (t < 16)
            cp16(base + 32768u + (uint32_t)t * 16, madd + b * SS + j0 + t * 4);
        CP_COMMIT();
    };

    issue_kv(0);
    issue_kv(1);
    CP_WAIT(2);          // Q done
    __syncthreads();

    const uint32_t aoff = (uint32_t)(wid*16 + (g & 1)*8 + r8) * 128
                        + (uint32_t)(g >> 1) * 16;
    uint32_t qf[4][4];   // Qh frags only; Ql reloaded per tile
    #pragma unroll
    for (int ks = 0; ks < 4; ks++)
        ldsm4(qf[ks], sb + sw128(aoff + ks*32));

    float o[8][4];
    #pragma unroll
    for (int nt = 0; nt < 8; nt++)
        #pragma unroll
        for (int c = 0; c < 4; c++) o[nt][c] = 0.0f;
    float mA = -1e30f, mB = -1e30f, lA = 0.0f, lB = 0.0f;

    const uint32_t kboff = (uint32_t)((g >> 1)*8 + r8) * 128 + (uint32_t)(g & 1)*16;
    const uint32_t vboff = (uint32_t)((g & 1)*8 + r8) * 128 + (uint32_t)(g >> 1)*16;

    const int NKT = SS / 64;   // 32
    for (int ch = 0; ch < NKT; ch++) {
        CP_WAIT(1);
        __syncthreads();

        const uint32_t base = sb + AQ_SZ + (uint32_t)(ch % AST) * ASTAGE;
        const uint32_t sKh = base, sKl = base + 8192u;
        const uint32_t sVh = base + 16384u, sVl = base + 24576u;
        const float* maskS = (const float*)(smem + AQ_SZ
                             + (uint32_t)(ch % AST) * ASTAGE + 32768u);

        // ---- QK^T
        float s[8][4];
        #pragma unroll
        for (int nt = 0; nt < 8; nt++)
            #pragma unroll
            for (int c = 0; c < 4; c++) s[nt][c] = 0.0f;

        #pragma unroll
        for (int ks = 0; ks < 4; ks++) {
            uint32_t qlf[4];
            ldsm4(qlf, sb + 16384u + sw128(aoff + ks*32));
            #pragma unroll
            for (int nq = 0; nq < 4; nq++) {
                uint32_t bh[4], bl[4];
                const uint32_t off = kboff + (uint32_t)nq*2048 + (uint32_t)ks*32;
                ldsm4(bh, sKh + sw128(off));
                ldsm4(bl, sKl + sw128(off));
                mma_bf16(s[nq*2],   qf[ks], bh);
                mma_bf16(s[nq*2],   qf[ks], bl);
                mma_bf16(s[nq*2],   qlf,    bh);
                mma_bf16(s[nq*2+1], qf[ks], bh + 2);
                mma_bf16(s[nq*2+1], qf[ks], bl + 2);
                mma_bf16(s[nq*2+1], qlf,    bh + 2);
            }
        }

        // ---- scale + mask
        const int mbase = (lane & 3) * 2;
        #pragma unroll
        for (int nt = 0; nt < 8; nt++) {
            float2 mk = *(float2*)&maskS[mbase + nt*8];
            s[nt][0] = s[nt][0]*0.125f + mk.x;
            s[nt][1] = s[nt][1]*0.125f + mk.y;
            s[nt][2] = s[nt][2]*0.125f + mk.x;
            s[nt][3] = s[nt][3]*0.125f + mk.y;
        }

        // ---- online softmax
        float mxA = s[0][0], mxB = s[0][2];
        #pragma unroll
        for (int nt = 0; nt < 8; nt++) {
            mxA = fmaxf(mxA, fmaxf(s[nt][0], s[nt][1]));
            mxB = fmaxf(mxB, fmaxf(s[nt][2], s[nt][3]));
        }
        mxA = fmaxf(mxA, __shfl_xor_sync(0xffffffffu, mxA, 1));
        mxA = fmaxf(mxA, __shfl_xor_sync(0xffffffffu, mxA, 2));
        mxB = fmaxf(mxB, __shfl_xor_sync(0xffffffffu, mxB, 1));
        mxB = fmaxf(mxB, __shfl_xor_sync(0xffffffffu, mxB, 2));
        const float mnA = fmaxf(mA, mxA), mnB = fmaxf(mB, mxB);
        const float scA = __expf(mA - mnA), scB = __expf(mB - mnB);
        mA = mnA; mB = mnB;

        float sumA = 0.0f, sumB = 0.0f;
        #pragma unroll
        for (int nt = 0; nt < 8; nt++) {
            s[nt][0] = __expf(s[nt][0] - mnA);
            s[nt][1] = __expf(s[nt][1] - mnA);
            s[nt][2] = __expf(s[nt][2] - mnB);
            s[nt][3] = __expf(s[nt][3] - mnB);
            sumA += s[nt][0] + s[nt][1];
            sumB += s[nt][2] + s[nt][3];
        }
        sumA += __shfl_xor_sync(0xffffffffu, sumA, 1);
        sumA += __shfl_xor_sync(0xffffffffu, sumA, 2);
        sumB += __shfl_xor_sync(0xffffffffu, sumB, 1);
        sumB += __shfl_xor_sync(0xffffffffu, sumB, 2);
        lA = lA * scA + sumA;
        lB = lB * scB + sumB;
        #pragma unroll
        for (int nt = 0; nt < 8; nt++) {
            o[nt][0] *= scA; o[nt][1] *= scA;
            o[nt][2] *= scB; o[nt][3] *= scB;
        }

        // ---- PV with in-loop P hi/lo packing
        #pragma unroll
        for (int ks = 0; ks < 4; ks++) {
            uint32_t ph[4], pl[4];
            #pragma unroll
            for (int half = 0; half < 2; half++) {
                const int nt = ks*2 + half;
                uint32_t u0 = cvt_bf16x2(s[nt][0], s[nt][1]);
                uint32_t u1 = cvt_bf16x2(s[nt][2], s[nt][3]);
                ph[half*2]   = u0;
                ph[half*2+1] = u1;
                float r0 = s[nt][0] - __uint_as_float(u0 << 16);
                float r1 = s[nt][1] - __uint_as_float(u0 & 0xffff0000u);
                float r2 = s[nt][2] - __uint_as_float(u1 << 16);
                float r3 = s[nt][3] - __uint_as_float(u1 & 0xffff0000u);
                pl[half*2]   = cvt_bf16x2(r0, r1);
                pl[half*2+1] = cvt_bf16x2(r2, r3);
            }
            #pragma unroll
            for (int nq = 0; nq < 4; nq++) {
                uint32_t vh[4], vl[4];
                const uint32_t off = vboff + (uint32_t)ks*2048 + (uint32_t)nq*32;
                ldsm4t(vh, sVh + sw128(off));
                ldsm4t(vl, sVl + sw128(off));
                mma_bf16(o[nq*2],   ph, vh);
                mma_bf16(o[nq*2],   ph, vl);
                mma_bf16(o[nq*2],   pl, vh);
                mma_bf16(o[nq*2+1], ph, vh + 2);
                mma_bf16(o[nq*2+1], ph, vl + 2);
                mma_bf16(o[nq*2+1], pl, vh + 2);
            }
        }

        __syncthreads();                 // all warps done with stage ch
        if (ch + 2 < NKT) issue_kv(ch + 2);   // refill this buffer
    }

    // ---- epilogue: O as hi/lo bf16
    const float invA = 1.0f / lA, invB = 1.0f / lB;
    const int rowA = q0 + wid*16 + (lane >> 2);
    #pragma unroll
    for (int nt = 0; nt < 8; nt++) {
        const int col = h*DHD + nt*8 + (lane & 3)*2;
        float a0 = o[nt][0]*invA, a1 = o[nt][1]*invA;
        float b0 = o[nt][2]*invB, b1 = o[nt][3]*invB;
        uint32_t hA = cvt_bf16x2(a0, a1), hB = cvt_bf16x2(b0, b1);
        float rA0 = a0 - __uint_as_float(hA << 16);
        float rA1 = a1 - __uint_as_float(hA & 0xffff0000u);
        float rB0 = b0 - __uint_as_float(hB << 16);
        float rB1 = b1 - __uint_as_float(hB & 0xffff0000u);
        const size_t r0 = ((size_t)b*SS + rowA) * DD + col;
        const size_t r1 = ((size_t)b*SS + rowA + 8) * DD + col;
        *(uint32_t*)&Oh_g[r0] = hA;
        *(uint32_t*)&Oh_g[r1] = hB;
        *(uint32_t*)&Ol_g[r0] = cvt_bf16x2(rA0, rA1);
        *(uint32_t*)&Ol_g[r1] = cvt_bf16x2(rB0, rB1);
    }
}

// ---------------------------------------------------------------------------
// Launch
// ---------------------------------------------------------------------------
extern "C" void kernel_launch(void* const* d_in, const int* in_sizes, int n_in,
                              void* d_out, int out_size)
{
    const float* x_q = (const float*)d_in[0];
    const float* x_k = (const float*)d_in[1];
    const float* x_v = (const float*)d_in[2];
    const void*  mask = d_in[3];
    const float* Wq = (const float*)d_in[4];
    const float* bq = (const float*)d_in[5];
    const float* Wk = (const float*)d_in[6];
    const float* bk = (const float*)d_in[7];
    const float* Wv = (const float*)d_in[8];
    const float* bv = (const float*)d_in[9];
    const float* Wo = (const float*)d_in[10];
    const float* bo = (const float*)d_in[11];
    float* out = (float*)d_out;

    float* Mp;
    __nv_bfloat16 *Xqh,*Xql,*Xkh,*Xkl,*Xvh,*Xvl;
    __nv_bfloat16 *Wqh,*Wql,*Wkh,*Wkl,*Wvh,*Wvl,*Woh,*Wol;
    __nv_bfloat16 *Qh,*Ql,*Kh,*Kl,*Vh,*Vl,*Oh,*Ol;
    cudaGetSymbolAddress((void**)&Mp, g_maskadd);
    cudaGetSymbolAddress((void**)&Xqh, g_Xqh); cudaGetSymbolAddress((void**)&Xql, g_Xql);
    cudaGetSymbolAddress((void**)&Xkh, g_Xkh); cudaGetSymbolAddress((void**)&Xkl, g_Xkl);
    cudaGetSymbolAddress((void**)&Xvh, g_Xvh); cudaGetSymbolAddress((void**)&Xvl, g_Xvl);
    cudaGetSymbolAddress((void**)&Wqh, g_Wqh); cudaGetSymbolAddress((void**)&Wql, g_Wql);
    cudaGetSymbolAddress((void**)&Wkh, g_Wkh); cudaGetSymbolAddress((void**)&Wkl, g_Wkl);
    cudaGetSymbolAddress((void**)&Wvh, g_Wvh); cudaGetSymbolAddress((void**)&Wvl, g_Wvl);
    cudaGetSymbolAddress((void**)&Woh, g_Woh); cudaGetSymbolAddress((void**)&Wol, g_Wol);
    cudaGetSymbolAddress((void**)&Qh, g_Qh);   cudaGetSymbolAddress((void**)&Ql, g_Ql);
    cudaGetSymbolAddress((void**)&Kh, g_Kh);   cudaGetSymbolAddress((void**)&Kl, g_Kl);
    cudaGetSymbolAddress((void**)&Vh, g_Vh);   cudaGetSymbolAddress((void**)&Vl, g_Vl);
    cudaGetSymbolAddress((void**)&Oh, g_Oh);   cudaGetSymbolAddress((void**)&Ol, g_Ol);

    SplitJobs7 jobs;
    jobs.src[0] = x_q; jobs.hi[0] = Xqh; jobs.lo[0] = Xql;
    jobs.src[1] = x_k; jobs.hi[1] = Xkh; jobs.lo[1] = Xkl;
    jobs.src[2] = x_v; jobs.hi[2] = Xvh; jobs.lo[2] = Xvl;
    jobs.src[3] = Wq;  jobs.hi[3] = Wqh; jobs.lo[3] = Wql;
    jobs.src[4] = Wk;  jobs.hi[4] = Wkh; jobs.lo[4] = Wkl;
    jobs.src[5] = Wv;  jobs.hi[5] = Wvh; jobs.lo[5] = Wvl;
    jobs.src[6] = Wo;  jobs.hi[6] = Woh; jobs.lo[6] = Wol;

    cudaFuncSetAttribute(attn_mma,
                         cudaFuncAttributeMaxDynamicSharedMemorySize, AT_SMEM);
    cudaFuncSetAttribute(gemm_pre,
                         cudaFuncAttributeMaxDynamicSharedMemorySize, GEMM_SMEM);

    dim3 ggrid(DD/64, MTOT/128);    // (16, 32) = 512 CTAs

    mask_convert<<<(BB*SS + 255)/256, 256>>>(mask, Mp);
    split_all<<<(NSPLIT4 + 255)/256, 256>>>(jobs);

    gemm_pre<<<ggrid, 256, GEMM_SMEM>>>(Xqh, Xql, Wqh, Wql, bq, nullptr, Qh, Ql, 0);
    gemm_pre<<<ggrid, 256, GEMM_SMEM>>>(Xkh, Xkl, Wkh, Wkl, bk, nullptr, Kh, Kl, 0);
    gemm_pre<<<ggrid, 256, GEMM_SMEM>>>(Xvh, Xvl, Wvh, Wvl, bv, nullptr, Vh, Vl, 0);

    attn_mma<<<dim3(SS/128, HH, BB), 256, AT_SMEM>>>(Mp, Qh, Ql, Kh, Kl,
                                                     Vh, Vl, Oh, Ol);

    gemm_pre<<<ggrid, 256, GEMM_SMEM>>>(Oh, Ol, Woh, Wol, bo, out, nullptr, nullptr, 1);
}

// round 10
// speedup vs baseline: 5.3066x; 1.0499x over previous
#include <cuda_runtime.h>
#include <cuda_bf16.h>
#include <cstdint>

// Problem constants
#define BB 2
#define SS 2048
#define DD 1024
#define HH 16
#define DHD 64
#define MTOT (BB*SS)   // 4096
#define GK 1024        // GEMM K
#define TKC 32         // GEMM K chunk
#define NCH (GK/TKC)   // 32 chunks

// Scratch (allocation-free rule: __device__ globals)
__device__ float g_maskadd[BB*SS];
__device__ __nv_bfloat16 g_Xqh[MTOT*GK], g_Xql[MTOT*GK];
__device__ __nv_bfloat16 g_Xkh[MTOT*GK], g_Xkl[MTOT*GK];
__device__ __nv_bfloat16 g_Xvh[MTOT*GK], g_Xvl[MTOT*GK];
__device__ __nv_bfloat16 g_Wqh[DD*GK], g_Wql[DD*GK];
__device__ __nv_bfloat16 g_Wkh[DD*GK], g_Wkl[DD*GK];
__device__ __nv_bfloat16 g_Wvh[DD*GK], g_Wvl[DD*GK];
__device__ __nv_bfloat16 g_Woh[DD*GK], g_Wol[DD*GK];
__device__ __nv_bfloat16 g_Qh[MTOT*DD], g_Ql[MTOT*DD];
__device__ __nv_bfloat16 g_Kh[MTOT*DD], g_Kl[MTOT*DD];
__device__ __nv_bfloat16 g_Vh[MTOT*DD], g_Vl[MTOT*DD];
__device__ __nv_bfloat16 g_Oh[MTOT*DD], g_Ol[MTOT*DD];

// ---------------------------------------------------------------------------
// helpers
// ---------------------------------------------------------------------------
__device__ __forceinline__ uint32_t smem_u32(const void* p) {
    uint32_t a;
    asm("{ .reg .u64 t; cvta.to.shared.u64 t, %1; cvt.u32.u64 %0, t; }"
        : "=r"(a) : "l"(p));
    return a;
}
__device__ __forceinline__ void ldsm4(uint32_t* r, uint32_t addr) {
    asm volatile("ldmatrix.sync.aligned.m8n8.x4.shared.b16 {%0,%1,%2,%3}, [%4];"
                 : "=r"(r[0]), "=r"(r[1]), "=r"(r[2]), "=r"(r[3]) : "r"(addr));
}
__device__ __forceinline__ void ldsm4t(uint32_t* r, uint32_t addr) {
    asm volatile("ldmatrix.sync.aligned.m8n8.x4.trans.shared.b16 {%0,%1,%2,%3}, [%4];"
                 : "=r"(r[0]), "=r"(r[1]), "=r"(r[2]), "=r"(r[3]) : "r"(addr));
}
__device__ __forceinline__ void mma_bf16(float* c, const uint32_t* a,
                                         const uint32_t* b) {
    asm volatile(
        "mma.sync.aligned.m16n8k16.row.col.f32.bf16.bf16.f32 "
        "{%0,%1,%2,%3}, {%4,%5,%6,%7}, {%8,%9}, {%0,%1,%2,%3};"
        : "+f"(c[0]), "+f"(c[1]), "+f"(c[2]), "+f"(c[3])
        : "r"(a[0]), "r"(a[1]), "r"(a[2]), "r"(a[3]), "r"(b[0]), "r"(b[1]));
}
__device__ __forceinline__ uint32_t pack_bf16(__nv_bfloat16 x, __nv_bfloat16 y) {
    __nv_bfloat162 t(x, y);
    return *reinterpret_cast<uint32_t*>(&t);
}
__device__ __forceinline__ uint32_t cvt_bf16x2(float lo, float hi) {
    uint32_t d;
    asm("cvt.rn.bf16x2.f32 %0, %1, %2;" : "=r"(d) : "f"(hi), "f"(lo));
    return d;
}
__device__ __forceinline__ uint32_t sw128(uint32_t off) {
    return off ^ ((off >> 3) & 0x70);
}
__device__ __forceinline__ void cp16(uint32_t dst, const void* src) {
    asm volatile("cp.async.cg.shared.global [%0], [%1], 16;"
                 :: "r"(dst), "l"(src) : "memory");
}
#define CP_COMMIT() asm volatile("cp.async.commit_group;" ::: "memory")
#define CP_WAIT(n)  asm volatile("cp.async.wait_group %0;" :: "n"(n) : "memory")

// ---------------------------------------------------------------------------
// Mask conversion
// ---------------------------------------------------------------------------
__global__ void mask_convert(const void* __restrict__ mask_raw,
                             float* __restrict__ madd)
{
    const unsigned* mw = (const unsigned*)mask_raw;
    bool is_int32 = true;
    #pragma unroll
    for (int i = 0; i < 64; i++)
        if (mw[i] > 1u) is_int32 = false;

    const int idx = blockIdx.x * blockDim.x + threadIdx.x;
    if (idx < BB * SS) {
        int m = is_int32 ? (int)mw[idx]
                         : (int)((const unsigned char*)mask_raw)[idx];
        madd[idx] = m ? 0.0f : -1e9f;
    }
}

// ---------------------------------------------------------------------------
// Fused fp32 -> bf16 hi/lo split of all 7 tensors (job table by value).
// ---------------------------------------------------------------------------
struct SplitJobs7 {
    const float* src[7];
    __nv_bfloat16* hi[7];
    __nv_bfloat16* lo[7];
};

#define NX4 (MTOT*GK/4)   // 1048576
#define NW4 (DD*GK/4)     // 262144
#define NSPLIT4 (3*NX4 + 4*NW4)

__global__ void split_all(SplitJobs7 jobs)
{
    const int i = blockIdx.x * blockDim.x + threadIdx.x;
    if (i >= NSPLIT4) return;
    int j, off;
    if (i < 3*NX4) { j = i / NX4; off = i - j*NX4; }
    else { int w = i - 3*NX4; j = 3 + w / NW4; off = w - (j-3)*NW4; }
    float4 v = ((const float4*)jobs.src[j])[off];
    __nv_bfloat16 h0 = __float2bfloat16(v.x), h1 = __float2bfloat16(v.y);
    __nv_bfloat16 h2 = __float2bfloat16(v.z), h3 = __float2bfloat16(v.w);
    uint2 hp{pack_bf16(h0, h1), pack_bf16(h2, h3)};
    uint2 lp{pack_bf16(__float2bfloat16(v.x - __bfloat162float(h0)),
                       __float2bfloat16(v.y - __bfloat162float(h1))),
             pack_bf16(__float2bfloat16(v.z - __bfloat162float(h2)),
                       __float2bfloat16(v.w - __bfloat162float(h3)))};
    ((uint2*)jobs.hi[j])[off] = hp;
    ((uint2*)jobs.lo[j])[off] = lp;
}

// ---------------------------------------------------------------------------
// Pre-split tensor GEMM core (shared by single + fused-3 variants)
// CTA tile 128x64, warp tile 32x32, K chunk 32, cp.async 3-stage, occ 2.
// ---------------------------------------------------------------------------
#define GST 3
#define GSTAGE 24576u
#define GEMM_SMEM (GST*GSTAGE)

__device__ __forceinline__ void gemm_core(
    const __nv_bfloat16* __restrict__ Ah, const __nv_bfloat16* __restrict__ Al,
    const __nv_bfloat16* __restrict__ Bh, const __nv_bfloat16* __restrict__ Bl,
    const float* __restrict__ bias, float* __restrict__ Cf,
    __nv_bfloat16* __restrict__ Ch, __nv_bfloat16* __restrict__ Cl, int wantf,
    char* smem)
{
    const uint32_t sb = smem_u32(smem);
    const int t = threadIdx.x, lane = t & 31, wid = t >> 5;
    const int m0 = blockIdx.y * 128, n0 = blockIdx.x * 64;
    const int mw = (wid & 3) * 32, nw = (wid >> 2) * 32;
    const int g = lane >> 3, r8 = lane & 7;

    auto issue = [&](int ch) {
        const int k0 = ch * TKC;
        const uint32_t abase = sb + (uint32_t)(ch % GST) * GSTAGE;
        const uint32_t bbase = abase + 16384u;
        #pragma unroll
        for (int i = 0; i < 4; i++) {
            const int idx = t + i * 256;
            const int row = idx >> 3, sub = idx & 7;
            const int s3 = sub & 3;
            const uint32_t doff = sw128((uint32_t)row * 128
                                        + (sub < 4 ? 0u : 64u) + (uint32_t)s3 * 16);
            cp16(abase + doff,
                 (sub < 4 ? Ah : Al) + (size_t)(m0 + row) * GK + k0 + s3 * 8);
        }
        #pragma unroll
        for (int i = 0; i < 2; i++) {
            const int idx = t + i * 256;
            const int row = idx >> 3, sub = idx & 7;
            const int s3 = sub & 3;
            const uint32_t doff = sw128((uint32_t)row * 128
                                        + (sub < 4 ? 0u : 64u) + (uint32_t)s3 * 16);
            cp16(bbase + doff,
                 (sub < 4 ? Bh : Bl) + (size_t)(n0 + row) * GK + k0 + s3 * 8);
        }
        CP_COMMIT();
    };

    issue(0); issue(1);

    const uint32_t baseA_off = (uint32_t)(mw + (g & 1) * 8 + r8) * 128
                             + (uint32_t)(g >> 1) * 16;
    const uint32_t baseB_off = (uint32_t)(nw + (g >> 1) * 8 + r8) * 128
                             + (uint32_t)(g & 1) * 16;

    float acc[2][4][4];
    #pragma unroll
    for (int mt = 0; mt < 2; mt++)
        #pragma unroll
        for (int nt = 0; nt < 4; nt++)
            #pragma unroll
            for (int c = 0; c < 4; c++) acc[mt][nt][c] = 0.0f;

    for (int ch = 0; ch < NCH; ch++) {
        CP_WAIT(1);
        __syncthreads();
        if (ch + 2 < NCH) issue(ch + 2);

        const uint32_t sA = sb + (uint32_t)(ch % GST) * GSTAGE;
        const uint32_t sB = sA + 16384u;

        #pragma unroll
        for (int ks = 0; ks < 2; ks++) {
            uint32_t af[2][2][4];
            #pragma unroll
            for (int mt = 0; mt < 2; mt++)
                #pragma unroll
                for (int p = 0; p < 2; p++) {
                    const uint32_t off = baseA_off + (uint32_t)mt * 2048
                                       + (uint32_t)p * 64 + (uint32_t)ks * 32;
                    ldsm4(af[mt][p], sA + sw128(off));
                }
            uint32_t bf_[2][4][2];
            #pragma unroll
            for (int np = 0; np < 2; np++)
                #pragma unroll
                for (int p = 0; p < 2; p++) {
                    uint32_t q[4];
                    const uint32_t off = baseB_off + (uint32_t)np * 2048
                                       + (uint32_t)p * 64 + (uint32_t)ks * 32;
                    ldsm4(q, sB + sw128(off));
                    bf_[p][np*2][0]   = q[0]; bf_[p][np*2][1]   = q[1];
                    bf_[p][np*2+1][0] = q[2]; bf_[p][np*2+1][1] = q[3];
                }
            #pragma unroll
            for (int mt = 0; mt < 2; mt++)
                #pragma unroll
                for (int nt = 0; nt < 4; nt++) {
                    mma_bf16(acc[mt][nt], af[mt][0], bf_[0][nt]);
                    mma_bf16(acc[mt][nt], af[mt][0], bf_[1][nt]);
                    mma_bf16(acc[mt][nt], af[mt][1], bf_[0][nt]);
                }
        }
        __syncthreads();
    }

    float bb[4][2];
    #pragma unroll
    for (int nt = 0; nt < 4; nt++) {
        const int col = n0 + nw + nt * 8 + (lane & 3) * 2;
        bb[nt][0] = bias[col];
        bb[nt][1] = bias[col + 1];
    }
    #pragma unroll
    for (int mt = 0; mt < 2; mt++) {
        const int row0 = m0 + mw + mt * 16 + (lane >> 2);
        #pragma unroll
        for (int nt = 0; nt < 4; nt++) {
            const int col = n0 + nw + nt * 8 + (lane & 3) * 2;
            float v0 = acc[mt][nt][0] + bb[nt][0];
            float v1 = acc[mt][nt][1] + bb[nt][1];
            float v2 = acc[mt][nt][2] + bb[nt][0];
            float v3 = acc[mt][nt][3] + bb[nt][1];
            if (wantf) {
                *(float2*)&Cf[(size_t)row0 * DD + col]       = float2{v0, v1};
                *(float2*)&Cf[(size_t)(row0 + 8) * DD + col] = float2{v2, v3};
            } else {
                uint32_t h0 = cvt_bf16x2(v0, v1), h1 = cvt_bf16x2(v2, v3);
                float r0 = v0 - __uint_as_float(h0 << 16);
                float r1 = v1 - __uint_as_float(h0 & 0xffff0000u);
                float r2 = v2 - __uint_as_float(h1 << 16);
                float r3 = v3 - __uint_as_float(h1 & 0xffff0000u);
                *(uint32_t*)&Ch[(size_t)row0 * DD + col]       = h0;
                *(uint32_t*)&Ch[(size_t)(row0 + 8) * DD + col] = h1;
                *(uint32_t*)&Cl[(size_t)row0 * DD + col]       = cvt_bf16x2(r0, r1);
                *(uint32_t*)&Cl[(size_t)(row0 + 8) * DD + col] = cvt_bf16x2(r2, r3);
            }
        }
    }
}

// Output projection (fp32 out)
__global__ __launch_bounds__(256, 2) void gemm_pre(
    const __nv_bfloat16* __restrict__ Ah, const __nv_bfloat16* __restrict__ Al,
    const __nv_bfloat16* __restrict__ Bh, const __nv_bfloat16* __restrict__ Bl,
    const float* __restrict__ bias, float* __restrict__ Cf)
{
    extern __shared__ char smem[];
    gemm_core(Ah, Al, Bh, Bl, bias, Cf, nullptr, nullptr, 1, smem);
}

// Fused Q/K/V projections: blockIdx.z selects the job.
struct GemmJobs3 {
    const __nv_bfloat16 *Ah[3], *Al[3], *Bh[3], *Bl[3];
    const float* bias[3];
    __nv_bfloat16 *Ch[3], *Cl[3];
};
__global__ __launch_bounds__(256, 2) void gemm_pre3(GemmJobs3 j)
{
    extern __shared__ char smem[];
    const int z = blockIdx.z;
    gemm_core(j.Ah[z], j.Al[z], j.Bh[z], j.Bl[z], j.bias[z],
              nullptr, j.Ch[z], j.Cl[z], 0, smem);
}

// ---------------------------------------------------------------------------
// Tensor flash attention v2: warp Q-tile 32 rows (2 m-subtiles), CTA = 256
// queries. K/V fragments feed 2x the MMAs -> ~0.55x crossbar bytes/MMA.
// occ=1 (regs ~200). Q region 64KB (hi 32K @0, lo 32K @32768), 2-stage K/V.
// ---------------------------------------------------------------------------
#define AST 2
#define ASTAGE 33792u
#define AQ_SZ 65536u
#define AT_SMEM (AQ_SZ + AST*ASTAGE)   // 133120

__global__ __launch_bounds__(256, 1) void attn_mma(
    const float* __restrict__ madd,
    const __nv_bfloat16* __restrict__ Qh_g, const __nv_bfloat16* __restrict__ Ql_g,
    const __nv_bfloat16* __restrict__ Kh_g, const __nv_bfloat16* __restrict__ Kl_g,
    const __nv_bfloat16* __restrict__ Vh_g, const __nv_bfloat16* __restrict__ Vl_g,
    __nv_bfloat16* __restrict__ Oh_g, __nv_bfloat16* __restrict__ Ol_g)
{
    extern __shared__ char smem[];
    const uint32_t sb = smem_u32(smem);
    const int t = threadIdx.x, lane = t & 31, wid = t >> 5;
    const int b = blockIdx.z, h = blockIdx.y, q0 = blockIdx.x * 256;
    const int g = lane >> 3, r8 = lane & 7;

    const size_t boff = (size_t)b * SS * DD + (size_t)h * DHD;
    const __nv_bfloat16* Qhb = Qh_g + boff;
    const __nv_bfloat16* Qlb = Ql_g + boff;
    const __nv_bfloat16* Khb = Kh_g + boff;
    const __nv_bfloat16* Klb = Kl_g + boff;
    const __nv_bfloat16* Vhb = Vh_g + boff;
    const __nv_bfloat16* Vlb = Vl_g + boff;

    // Q load: 256 rows x 64 bf16, hi @0, lo @32768
    #pragma unroll
    for (int i = 0; i < 16; i++) {
        const int prec = i >> 3;
        const int idx = t + (i & 7) * 256;
        const int row = idx >> 3, sub = idx & 7;
        const uint32_t doff = (prec ? 32768u : 0u)
                            + sw128((uint32_t)row * 128 + (uint32_t)sub * 16);
        cp16(sb + doff,
             (prec ? Qlb : Qhb) + (size_t)(q0 + row) * DD + sub * 8);
    }
    CP_COMMIT();

    auto issue_kv = [&](int ch) {
        const int j0 = ch * 64;
        const uint32_t base = sb + AQ_SZ + (uint32_t)(ch % AST) * ASTAGE;
        #pragma unroll
        for (int i = 0; i < 8; i++) {
            const int tile = i >> 1;
            const int idx = t + (i & 1) * 256;
            const int row = idx >> 3, sub = idx & 7;
            const __nv_bfloat16* src =
                (tile == 0 ? Khb : tile == 1 ? Klb : tile == 2 ? Vhb : Vlb)
                + (size_t)(j0 + row) * DD + sub * 8;
            cp16(base + (uint32_t)tile * 8192u
                      + sw128((uint32_t)row * 128 + (uint32_t)sub * 16), src);
        }
        if (t < 16)
            cp16(base + 32768u + (uint32_t)t * 16, madd + b * SS + j0 + t * 4);
        CP_COMMIT();
    };

    issue_kv(0);
    issue_kv(1);
    CP_WAIT(2);          // Q done
    __syncthreads();

    uint32_t aoff[2];
    #pragma unroll
    for (int mt = 0; mt < 2; mt++)
        aoff[mt] = (uint32_t)(wid*32 + mt*16 + (g & 1)*8 + r8) * 128
                 + (uint32_t)(g >> 1) * 16;

    uint32_t qf[2][4][4];   // Qh frags for both m-subtiles; Ql reloaded per tile
    #pragma unroll
    for (int mt = 0; mt < 2; mt++)
        #pragma unroll
        for (int ks = 0; ks < 4; ks++)
            ldsm4(qf[mt][ks], sb + sw128(aoff[mt] + ks*32));

    float o[2][8][4];
    #pragma unroll
    for (int mt = 0; mt < 2; mt++)
        #pragma unroll
        for (int nt = 0; nt < 8; nt++)
            #pragma unroll
            for (int c = 0; c < 4; c++) o[mt][nt][c] = 0.0f;
    float mA[2] = {-1e30f, -1e30f}, mB[2] = {-1e30f, -1e30f};
    float lA[2] = {0.0f, 0.0f},     lB[2] = {0.0f, 0.0f};

    const uint32_t kboff = (uint32_t)((g >> 1)*8 + r8) * 128 + (uint32_t)(g & 1)*16;
    const uint32_t vboff = (uint32_t)((g & 1)*8 + r8) * 128 + (uint32_t)(g >> 1)*16;

    const int NKT = SS / 64;   // 32
    for (int ch = 0; ch < NKT; ch++) {
        CP_WAIT(1);
        __syncthreads();

        const uint32_t base = sb + AQ_SZ + (uint32_t)(ch % AST) * ASTAGE;
        const uint32_t sKh = base, sKl = base + 8192u;
        const uint32_t sVh = base + 16384u, sVl = base + 24576u;
        const float* maskS = (const float*)(smem + AQ_SZ
                             + (uint32_t)(ch % AST) * ASTAGE + 32768u);

        // ---- QK^T (K-frags shared across both m-subtiles)
        float s[2][8][4];
        #pragma unroll
        for (int mt = 0; mt < 2; mt++)
            #pragma unroll
            for (int nt = 0; nt < 8; nt++)
                #pragma unroll
                for (int c = 0; c < 4; c++) s[mt][nt][c] = 0.0f;

        #pragma unroll
        for (int ks = 0; ks < 4; ks++) {
            uint32_t qlf[2][4];
            ldsm4(qlf[0], sb + 32768u + sw128(aoff[0] + ks*32));
            ldsm4(qlf[1], sb + 32768u + sw128(aoff[1] + ks*32));
            #pragma unroll
            for (int nq = 0; nq < 4; nq++) {
                uint32_t bh[4], bl[4];
                const uint32_t off = kboff + (uint32_t)nq*2048 + (uint32_t)ks*32;
                ldsm4(bh, sKh + sw128(off));
                ldsm4(bl, sKl + sw128(off));
                #pragma unroll
                for (int mt = 0; mt < 2; mt++) {
                    mma_bf16(s[mt][nq*2],   qf[mt][ks], bh);
                    mma_bf16(s[mt][nq*2],   qf[mt][ks], bl);
                    mma_bf16(s[mt][nq*2],   qlf[mt],    bh);
                    mma_bf16(s[mt][nq*2+1], qf[mt][ks], bh + 2);
                    mma_bf16(s[mt][nq*2+1], qf[mt][ks], bl + 2);
                    mma_bf16(s[mt][nq*2+1], qlf[mt],    bh + 2);
                }
            }
        }

        // ---- scale + mask + online softmax (per m-subtile)
        const int mbase = (lane & 3) * 2;
        #pragma unroll
        for (int mt = 0; mt < 2; mt++) {
            #pragma unroll
            for (int nt = 0; nt < 8; nt++) {
                float2 mk = *(float2*)&maskS[mbase + nt*8];
                s[mt][nt][0] = s[mt][nt][0]*0.125f + mk.x;
                s[mt][nt][1] = s[mt][nt][1]*0.125f + mk.y;
                s[mt][nt][2] = s[mt][nt][2]*0.125f + mk.x;
                s[mt][nt][3] = s[mt][nt][3]*0.125f + mk.y;
            }

            float mxA = s[mt][0][0], mxB = s[mt][0][2];
            #pragma unroll
            for (int nt = 0; nt < 8; nt++) {
                mxA = fmaxf(mxA, fmaxf(s[mt][nt][0], s[mt][nt][1]));
                mxB = fmaxf(mxB, fmaxf(s[mt][nt][2], s[mt][nt][3]));
            }
            mxA = fmaxf(mxA, __shfl_xor_sync(0xffffffffu, mxA, 1));
            mxA = fmaxf(mxA, __shfl_xor_sync(0xffffffffu, mxA, 2));
            mxB = fmaxf(mxB, __shfl_xor_sync(0xffffffffu, mxB, 1));
            mxB = fmaxf(mxB, __shfl_xor_sync(0xffffffffu, mxB, 2));
            const float mnA = fmaxf(mA[mt], mxA), mnB = fmaxf(mB[mt], mxB);
            const float scA = __expf(mA[mt] - mnA), scB = __expf(mB[mt] - mnB);
            mA[mt] = mnA; mB[mt] = mnB;

            float sumA = 0.0f, sumB = 0.0f;
            #pragma unroll
            for (int nt = 0; nt < 8; nt++) {
                s[mt][nt][0] = __expf(s[mt][nt][0] - mnA);
                s[mt][nt][1] = __expf(s[mt][nt][1] - mnA);
                s[mt][nt][2] = __expf(s[mt][nt][2] - mnB);
                s[mt][nt][3] = __expf(s[mt][nt][3] - mnB);
                sumA += s[mt][nt][0] + s[mt][nt][1];
                sumB += s[mt][nt][2] + s[mt][nt][3];
            }
            sumA += __shfl_xor_sync(0xffffffffu, sumA, 1);
            sumA += __shfl_xor_sync(0xffffffffu, sumA, 2);
            sumB += __shfl_xor_sync(0xffffffffu, sumB, 1);
            sumB += __shfl_xor_sync(0xffffffffu, sumB, 2);
            lA[mt] = lA[mt] * scA + sumA;
            lB[mt] = lB[mt] * scB + sumB;
            #pragma unroll
            for (int nt = 0; nt < 8; nt++) {
                o[mt][nt][0] *= scA; o[mt][nt][1] *= scA;
                o[mt][nt][2] *= scB; o[mt][nt][3] *= scB;
            }
        }

        // ---- PV (V-frags shared across both m-subtiles; P packed in-loop)
        #pragma unroll
        for (int ks = 0; ks < 4; ks++) {
            uint32_t ph[2][4], pl[2][4];
            #pragma unroll
            for (int mt = 0; mt < 2; mt++)
                #pragma unroll
                for (int half = 0; half < 2; half++) {
                    const int nt = ks*2 + half;
                    uint32_t u0 = cvt_bf16x2(s[mt][nt][0], s[mt][nt][1]);
                    uint32_t u1 = cvt_bf16x2(s[mt][nt][2], s[mt][nt][3]);
                    ph[mt][half*2]   = u0;
                    ph[mt][half*2+1] = u1;
                    float r0 = s[mt][nt][0] - __uint_as_float(u0 << 16);
                    float r1 = s[mt][nt][1] - __uint_as_float(u0 & 0xffff0000u);
                    float r2 = s[mt][nt][2] - __uint_as_float(u1 << 16);
                    float r3 = s[mt][nt][3] - __uint_as_float(u1 & 0xffff0000u);
                    pl[mt][half*2]   = cvt_bf16x2(r0, r1);
                    pl[mt][half*2+1] = cvt_bf16x2(r2, r3);
                }
            #pragma unroll
            for (int nq = 0; nq < 4; nq++) {
                uint32_t vh[4], vl[4];
                const uint32_t off = vboff + (uint32_t)ks*2048 + (uint32_t)nq*32;
                ldsm4t(vh, sVh + sw128(off));
                ldsm4t(vl, sVl + sw128(off));
                #pragma unroll
                for (int mt = 0; mt < 2; mt++) {
                    mma_bf16(o[mt][nq*2],   ph[mt], vh);
                    mma_bf16(o[mt][nq*2],   ph[mt], vl);
                    mma_bf16(o[mt][nq*2],   pl[mt], vh);
                    mma_bf16(o[mt][nq*2+1], ph[mt], vh + 2);
                    mma_bf16(o[mt][nq*2+1], ph[mt], vl + 2);
                    mma_bf16(o[mt][nq*2+1], pl[mt], vh + 2);
                }
            }
        }

        __syncthreads();
        if (ch + 2 < NKT) issue_kv(ch + 2);
    }

    // ---- epilogue: O as hi/lo bf16
    #pragma unroll
    for (int mt = 0; mt < 2; mt++) {
        const float invA = 1.0f / lA[mt], invB = 1.0f / lB[mt];
        const int rowA = q0 + wid*32 + mt*16 + (lane >> 2);
        #pragma unroll
        for (int nt = 0; nt < 8; nt++) {
            const int col = h*DHD + nt*8 + (lane & 3)*2;
            float a0 = o[mt][nt][0]*invA, a1 = o[mt][nt][1]*invA;
            float b0 = o[mt][nt][2]*invB, b1 = o[mt][nt][3]*invB;
            uint32_t hA = cvt_bf16x2(a0, a1), hB = cvt_bf16x2(b0, b1);
            float rA0 = a0 - __uint_as_float(hA << 16);
            float rA1 = a1 - __uint_as_float(hA & 0xffff0000u);
            float rB0 = b0 - __uint_as_float(hB << 16);
            float rB1 = b1 - __uint_as_float(hB & 0xffff0000u);
            const size_t r0 = ((size_t)b*SS + rowA) * DD + col;
            const size_t r1 = ((size_t)b*SS + rowA + 8) * DD + col;
            *(uint32_t*)&Oh_g[r0] = hA;
            *(uint32_t*)&Oh_g[r1] = hB;
            *(uint32_t*)&Ol_g[r0] = cvt_bf16x2(rA0, rA1);
            *(uint32_t*)&Ol_g[r1] = cvt_bf16x2(rB0, rB1);
        }
    }
}

// ---------------------------------------------------------------------------
// Launch
// ---------------------------------------------------------------------------
extern "C" void kernel_launch(void* const* d_in, const int* in_sizes, int n_in,
                              void* d_out, int out_size)
{
    const float* x_q = (const float*)d_in[0];
    const float* x_k = (const float*)d_in[1];
    const float* x_v = (const float*)d_in[2];
    const void*  mask = d_in[3];
    const float* Wq = (const float*)d_in[4];
    const float* bq = (const float*)d_in[5];
    const float* Wk = (const float*)d_in[6];
    const float* bk = (const float*)d_in[7];
    const float* Wv = (const float*)d_in[8];
    const float* bv = (const float*)d_in[9];
    const float* Wo = (const float*)d_in[10];
    const float* bo = (const float*)d_in[11];
    float* out = (float*)d_out;

    float* Mp;
    __nv_bfloat16 *Xqh,*Xql,*Xkh,*Xkl,*Xvh,*Xvl;
    __nv_bfloat16 *Wqh,*Wql,*Wkh,*Wkl,*Wvh,*Wvl,*Woh,*Wol;
    __nv_bfloat16 *Qh,*Ql,*Kh,*Kl,*Vh,*Vl,*Oh,*Ol;
    cudaGetSymbolAddress((void**)&Mp, g_maskadd);
    cudaGetSymbolAddress((void**)&Xqh, g_Xqh); cudaGetSymbolAddress((void**)&Xql, g_Xql);
    cudaGetSymbolAddress((void**)&Xkh, g_Xkh); cudaGetSymbolAddress((void**)&Xkl, g_Xkl);
    cudaGetSymbolAddress((void**)&Xvh, g_Xvh); cudaGetSymbolAddress((void**)&Xvl, g_Xvl);
    cudaGetSymbolAddress((void**)&Wqh, g_Wqh); cudaGetSymbolAddress((void**)&Wql, g_Wql);
    cudaGetSymbolAddress((void**)&Wkh, g_Wkh); cudaGetSymbolAddress((void**)&Wkl, g_Wkl);
    cudaGetSymbolAddress((void**)&Wvh, g_Wvh); cudaGetSymbolAddress((void**)&Wvl, g_Wvl);
    cudaGetSymbolAddress((void**)&Woh, g_Woh); cudaGetSymbolAddress((void**)&Wol, g_Wol);
    cudaGetSymbolAddress((void**)&Qh, g_Qh);   cudaGetSymbolAddress((void**)&Ql, g_Ql);
    cudaGetSymbolAddress((void**)&Kh, g_Kh);   cudaGetSymbolAddress((void**)&Kl, g_Kl);
    cudaGetSymbolAddress((void**)&Vh, g_Vh);   cudaGetSymbolAddress((void**)&Vl, g_Vl);
    cudaGetSymbolAddress((void**)&Oh, g_Oh);   cudaGetSymbolAddress((void**)&Ol, g_Ol);

    SplitJobs7 jobs;
    jobs.src[0] = x_q; jobs.hi[0] = Xqh; jobs.lo[0] = Xql;
    jobs.src[1] = x_k; jobs.hi[1] = Xkh; jobs.lo[1] = Xkl;
    jobs.src[2] = x_v; jobs.hi[2] = Xvh; jobs.lo[2] = Xvl;
    jobs.src[3] = Wq;  jobs.hi[3] = Wqh; jobs.lo[3] = Wql;
    jobs.src[4] = Wk;  jobs.hi[4] = Wkh; jobs.lo[4] = Wkl;
    jobs.src[5] = Wv;  jobs.hi[5] = Wvh; jobs.lo[5] = Wvl;
    jobs.src[6] = Wo;  jobs.hi[6] = Woh; jobs.lo[6] = Wol;

    GemmJobs3 gj;
    gj.Ah[0] = Xqh; gj.Al[0] = Xql; gj.Bh[0] = Wqh; gj.Bl[0] = Wql;
    gj.bias[0] = bq; gj.Ch[0] = Qh; gj.Cl[0] = Ql;
    gj.Ah[1] = Xkh; gj.Al[1] = Xkl; gj.Bh[1] = Wkh; gj.Bl[1] = Wkl;
    gj.bias[1] = bk; gj.Ch[1] = Kh; gj.Cl[1] = Kl;
    gj.Ah[2] = Xvh; gj.Al[2] = Xvl; gj.Bh[2] = Wvh; gj.Bl[2] = Wvl;
    gj.bias[2] = bv; gj.Ch[2] = Vh; gj.Cl[2] = Vl;

    cudaFuncSetAttribute(attn_mma,
                         cudaFuncAttributeMaxDynamicSharedMemorySize, AT_SMEM);
    cudaFuncSetAttribute(gemm_pre,
                         cudaFuncAttributeMaxDynamicSharedMemorySize, GEMM_SMEM);
    cudaFuncSetAttribute(gemm_pre3,
                         cudaFuncAttributeMaxDynamicSharedMemorySize, GEMM_SMEM);

    mask_convert<<<(BB*SS + 255)/256, 256>>>(mask, Mp);
    split_all<<<(NSPLIT4 + 255)/256, 256>>>(jobs);

    gemm_pre3<<<dim3(DD/64, MTOT/128, 3), 256, GEMM_SMEM>>>(gj);

    attn_mma<<<dim3(SS/256, HH, BB), 256, AT_SMEM>>>(Mp, Qh, Ql, Kh, Kl,
                                                     Vh, Vl, Oh, Ol);

    gemm_pre<<<dim3(DD/64, MTOT/128), 256, GEMM_SMEM>>>(Oh, Ol, Woh, Wol, bo, out);
}

// round 11
// speedup vs baseline: 5.3501x; 1.0082x over previous
#include <cuda_runtime.h>
#include <cuda_bf16.h>
#include <cstdint>

// Problem constants
#define BB 2
#define SS 2048
#define DD 1024
#define HH 16
#define DHD 64
#define MTOT (BB*SS)   // 4096
#define GK 1024        // GEMM K
#define TKC 32         // GEMM K chunk
#define NCH (GK/TKC)   // 32 chunks

// Scratch (allocation-free rule: __device__ globals)
__device__ float g_maskadd[BB*SS];
__device__ __nv_bfloat16 g_Xqh[MTOT*GK], g_Xql[MTOT*GK];
__device__ __nv_bfloat16 g_Xkh[MTOT*GK], g_Xkl[MTOT*GK];
__device__ __nv_bfloat16 g_Xvh[MTOT*GK], g_Xvl[MTOT*GK];
__device__ __nv_bfloat16 g_Wqh[DD*GK], g_Wql[DD*GK];
__device__ __nv_bfloat16 g_Wkh[DD*GK], g_Wkl[DD*GK];
__device__ __nv_bfloat16 g_Wvh[DD*GK], g_Wvl[DD*GK];
__device__ __nv_bfloat16 g_Woh[DD*GK], g_Wol[DD*GK];
__device__ __nv_bfloat16 g_Qh[MTOT*DD], g_Ql[MTOT*DD];
__device__ __nv_bfloat16 g_Kh[MTOT*DD], g_Kl[MTOT*DD];
__device__ __nv_bfloat16 g_Vh[MTOT*DD], g_Vl[MTOT*DD];
__device__ __nv_bfloat16 g_Oh[MTOT*DD], g_Ol[MTOT*DD];

// ---------------------------------------------------------------------------
// helpers
// ---------------------------------------------------------------------------
__device__ __forceinline__ uint32_t smem_u32(const void* p) {
    uint32_t a;
    asm("{ .reg .u64 t; cvta.to.shared.u64 t, %1; cvt.u32.u64 %0, t; }"
        : "=r"(a) : "l"(p));
    return a;
}
__device__ __forceinline__ void ldsm4(uint32_t* r, uint32_t addr) {
    asm volatile("ldmatrix.sync.aligned.m8n8.x4.shared.b16 {%0,%1,%2,%3}, [%4];"
                 : "=r"(r[0]), "=r"(r[1]), "=r"(r[2]), "=r"(r[3]) : "r"(addr));
}
__device__ __forceinline__ void ldsm4t(uint32_t* r, uint32_t addr) {
    asm volatile("ldmatrix.sync.aligned.m8n8.x4.trans.shared.b16 {%0,%1,%2,%3}, [%4];"
                 : "=r"(r[0]), "=r"(r[1]), "=r"(r[2]), "=r"(r[3]) : "r"(addr));
}
__device__ __forceinline__ void mma_bf16(float* c, const uint32_t* a,
                                         const uint32_t* b) {
    asm volatile(
        "mma.sync.aligned.m16n8k16.row.col.f32.bf16.bf16.f32 "
        "{%0,%1,%2,%3}, {%4,%5,%6,%7}, {%8,%9}, {%0,%1,%2,%3};"
        : "+f"(c[0]), "+f"(c[1]), "+f"(c[2]), "+f"(c[3])
        : "r"(a[0]), "r"(a[1]), "r"(a[2]), "r"(a[3]), "r"(b[0]), "r"(b[1]));
}
__device__ __forceinline__ uint32_t pack_bf16(__nv_bfloat16 x, __nv_bfloat16 y) {
    __nv_bfloat162 t(x, y);
    return *reinterpret_cast<uint32_t*>(&t);
}
__device__ __forceinline__ uint32_t cvt_bf16x2(float lo, float hi) {
    uint32_t d;
    asm("cvt.rn.bf16x2.f32 %0, %1, %2;" : "=r"(d) : "f"(hi), "f"(lo));
    return d;
}
__device__ __forceinline__ uint32_t sw128(uint32_t off) {
    return off ^ ((off >> 3) & 0x70);
}
__device__ __forceinline__ void cp16(uint32_t dst, const void* src) {
    asm volatile("cp.async.cg.shared.global [%0], [%1], 16;"
                 :: "r"(dst), "l"(src) : "memory");
}
#define CP_COMMIT() asm volatile("cp.async.commit_group;" ::: "memory")
#define CP_WAIT(n)  asm volatile("cp.async.wait_group %0;" :: "n"(n) : "memory")

// ---------------------------------------------------------------------------
// Fused prepass: fp32 -> bf16 hi/lo split of all 7 tensors + mask convert.
// Job table passed by value (graph-safe).
// ---------------------------------------------------------------------------
struct SplitJobs7 {
    const float* src[7];
    __nv_bfloat16* hi[7];
    __nv_bfloat16* lo[7];
    const void* mask_raw;
    float* madd;
};

#define NX4 (MTOT*GK/4)   // 1048576
#define NW4 (DD*GK/4)     // 262144
#define NSPLIT4 (3*NX4 + 4*NW4)
#define NTOT (NSPLIT4 + BB*SS)

__global__ void split_all(SplitJobs7 jobs)
{
    const int i = blockIdx.x * blockDim.x + threadIdx.x;
    if (i >= NSPLIT4) {
        const int idx = i - NSPLIT4;
        if (idx < BB * SS) {
            const unsigned* mw = (const unsigned*)jobs.mask_raw;
            bool is_int32 = true;
            #pragma unroll
            for (int k = 0; k < 64; k++)
                if (mw[k] > 1u) is_int32 = false;
            int m = is_int32 ? (int)mw[idx]
                             : (int)((const unsigned char*)jobs.mask_raw)[idx];
            jobs.madd[idx] = m ? 0.0f : -1e9f;
        }
        return;
    }
    int j, off;
    if (i < 3*NX4) { j = i / NX4; off = i - j*NX4; }
    else { int w = i - 3*NX4; j = 3 + w / NW4; off = w - (j-3)*NW4; }
    float4 v = ((const float4*)jobs.src[j])[off];
    __nv_bfloat16 h0 = __float2bfloat16(v.x), h1 = __float2bfloat16(v.y);
    __nv_bfloat16 h2 = __float2bfloat16(v.z), h3 = __float2bfloat16(v.w);
    uint2 hp{pack_bf16(h0, h1), pack_bf16(h2, h3)};
    uint2 lp{pack_bf16(__float2bfloat16(v.x - __bfloat162float(h0)),
                       __float2bfloat16(v.y - __bfloat162float(h1))),
             pack_bf16(__float2bfloat16(v.z - __bfloat162float(h2)),
                       __float2bfloat16(v.w - __bfloat162float(h3)))};
    ((uint2*)jobs.hi[j])[off] = hp;
    ((uint2*)jobs.lo[j])[off] = lp;
}

// ---------------------------------------------------------------------------
// Pre-split tensor GEMM core. CTA 128x64, warp 32x32, 3-stage cp.async, occ 2.
// cscale: output scale applied before hi/lo split (0.125 for Q projection).
// ---------------------------------------------------------------------------
#define GST 3
#define GSTAGE 24576u
#define GEMM_SMEM (GST*GSTAGE)

__device__ __forceinline__ void gemm_core(
    const __nv_bfloat16* __restrict__ Ah, const __nv_bfloat16* __restrict__ Al,
    const __nv_bfloat16* __restrict__ Bh, const __nv_bfloat16* __restrict__ Bl,
    const float* __restrict__ bias, float* __restrict__ Cf,
    __nv_bfloat16* __restrict__ Ch, __nv_bfloat16* __restrict__ Cl, int wantf,
    float cscale, char* smem)
{
    const uint32_t sb = smem_u32(smem);
    const int t = threadIdx.x, lane = t & 31, wid = t >> 5;
    const int m0 = blockIdx.y * 128, n0 = blockIdx.x * 64;
    const int mw = (wid & 3) * 32, nw = (wid >> 2) * 32;
    const int g = lane >> 3, r8 = lane & 7;

    auto issue = [&](int ch) {
        const int k0 = ch * TKC;
        const uint32_t abase = sb + (uint32_t)(ch % GST) * GSTAGE;
        const uint32_t bbase = abase + 16384u;
        #pragma unroll
        for (int i = 0; i < 4; i++) {
            const int idx = t + i * 256;
            const int row = idx >> 3, sub = idx & 7;
            const int s3 = sub & 3;
            const uint32_t doff = sw128((uint32_t)row * 128
                                        + (sub < 4 ? 0u : 64u) + (uint32_t)s3 * 16);
            cp16(abase + doff,
                 (sub < 4 ? Ah : Al) + (size_t)(m0 + row) * GK + k0 + s3 * 8);
        }
        #pragma unroll
        for (int i = 0; i < 2; i++) {
            const int idx = t + i * 256;
            const int row = idx >> 3, sub = idx & 7;
            const int s3 = sub & 3;
            const uint32_t doff = sw128((uint32_t)row * 128
                                        + (sub < 4 ? 0u : 64u) + (uint32_t)s3 * 16);
            cp16(bbase + doff,
                 (sub < 4 ? Bh : Bl) + (size_t)(n0 + row) * GK + k0 + s3 * 8);
        }
        CP_COMMIT();
    };

    issue(0); issue(1);

    const uint32_t baseA_off = (uint32_t)(mw + (g & 1) * 8 + r8) * 128
                             + (uint32_t)(g >> 1) * 16;
    const uint32_t baseB_off = (uint32_t)(nw + (g >> 1) * 8 + r8) * 128
                             + (uint32_t)(g & 1) * 16;

    float acc[2][4][4];
    #pragma unroll
    for (int mt = 0; mt < 2; mt++)
        #pragma unroll
        for (int nt = 0; nt < 4; nt++)
            #pragma unroll
            for (int c = 0; c < 4; c++) acc[mt][nt][c] = 0.0f;

    for (int ch = 0; ch < NCH; ch++) {
        CP_WAIT(1);
        __syncthreads();
        if (ch + 2 < NCH) issue(ch + 2);

        const uint32_t sA = sb + (uint32_t)(ch % GST) * GSTAGE;
        const uint32_t sB = sA + 16384u;

        #pragma unroll
        for (int ks = 0; ks < 2; ks++) {
            uint32_t af[2][2][4];
            #pragma unroll
            for (int mt = 0; mt < 2; mt++)
                #pragma unroll
                for (int p = 0; p < 2; p++) {
                    const uint32_t off = baseA_off + (uint32_t)mt * 2048
                                       + (uint32_t)p * 64 + (uint32_t)ks * 32;
                    ldsm4(af[mt][p], sA + sw128(off));
                }
            uint32_t bf_[2][4][2];
            #pragma unroll
            for (int np = 0; np < 2; np++)
                #pragma unroll
                for (int p = 0; p < 2; p++) {
                    uint32_t q[4];
                    const uint32_t off = baseB_off + (uint32_t)np * 2048
                                       + (uint32_t)p * 64 + (uint32_t)ks * 32;
                    ldsm4(q, sB + sw128(off));
                    bf_[p][np*2][0]   = q[0]; bf_[p][np*2][1]   = q[1];
                    bf_[p][np*2+1][0] = q[2]; bf_[p][np*2+1][1] = q[3];
                }
            #pragma unroll
            for (int mt = 0; mt < 2; mt++)
                #pragma unroll
                for (int nt = 0; nt < 4; nt++) {
                    mma_bf16(acc[mt][nt], af[mt][0], bf_[0][nt]);
                    mma_bf16(acc[mt][nt], af[mt][0], bf_[1][nt]);
                    mma_bf16(acc[mt][nt], af[mt][1], bf_[0][nt]);
                }
        }
        __syncthreads();
    }

    float bb[4][2];
    #pragma unroll
    for (int nt = 0; nt < 4; nt++) {
        const int col = n0 + nw + nt * 8 + (lane & 3) * 2;
        bb[nt][0] = bias[col];
        bb[nt][1] = bias[col + 1];
    }
    #pragma unroll
    for (int mt = 0; mt < 2; mt++) {
        const int row0 = m0 + mw + mt * 16 + (lane >> 2);
        #pragma unroll
        for (int nt = 0; nt < 4; nt++) {
            const int col = n0 + nw + nt * 8 + (lane & 3) * 2;
            float v0 = (acc[mt][nt][0] + bb[nt][0]) * cscale;
            float v1 = (acc[mt][nt][1] + bb[nt][1]) * cscale;
            float v2 = (acc[mt][nt][2] + bb[nt][0]) * cscale;
            float v3 = (acc[mt][nt][3] + bb[nt][1]) * cscale;
            if (wantf) {
                *(float2*)&Cf[(size_t)row0 * DD + col]       = float2{v0, v1};
                *(float2*)&Cf[(size_t)(row0 + 8) * DD + col] = float2{v2, v3};
            } else {
                uint32_t h0 = cvt_bf16x2(v0, v1), h1 = cvt_bf16x2(v2, v3);
                float r0 = v0 - __uint_as_float(h0 << 16);
                float r1 = v1 - __uint_as_float(h0 & 0xffff0000u);
                float r2 = v2 - __uint_as_float(h1 << 16);
                float r3 = v3 - __uint_as_float(h1 & 0xffff0000u);
                *(uint32_t*)&Ch[(size_t)row0 * DD + col]       = h0;
                *(uint32_t*)&Ch[(size_t)(row0 + 8) * DD + col] = h1;
                *(uint32_t*)&Cl[(size_t)row0 * DD + col]       = cvt_bf16x2(r0, r1);
                *(uint32_t*)&Cl[(size_t)(row0 + 8) * DD + col] = cvt_bf16x2(r2, r3);
            }
        }
    }
}

// Output projection (fp32 out)
__global__ __launch_bounds__(256, 2) void gemm_pre(
    const __nv_bfloat16* __restrict__ Ah, const __nv_bfloat16* __restrict__ Al,
    const __nv_bfloat16* __restrict__ Bh, const __nv_bfloat16* __restrict__ Bl,
    const float* __restrict__ bias, float* __restrict__ Cf)
{
    extern __shared__ char smem[];
    gemm_core(Ah, Al, Bh, Bl, bias, Cf, nullptr, nullptr, 1, 1.0f, smem);
}

// Fused Q/K/V projections: blockIdx.z selects the job. Q job scaled by 0.125.
struct GemmJobs3 {
    const __nv_bfloat16 *Ah[3], *Al[3], *Bh[3], *Bl[3];
    const float* bias[3];
    __nv_bfloat16 *Ch[3], *Cl[3];
    float scale[3];
};
__global__ __launch_bounds__(256, 2) void gemm_pre3(GemmJobs3 j)
{
    extern __shared__ char smem[];
    const int z = blockIdx.z;
    gemm_core(j.Ah[z], j.Al[z], j.Bh[z], j.Bl[z], j.bias[z],
              nullptr, j.Ch[z], j.Cl[z], 0, j.scale[z], smem);
}

// ---------------------------------------------------------------------------
// Tensor flash attention v3: 128-thread CTAs (4 warps x 32 query rows),
// 2 CTAs/SM for phase decorrelation (softmax of one overlaps MMA of other).
// Q pre-scaled by 0.125 at projection. Q region 32KB, 2-stage K/V.
// ---------------------------------------------------------------------------
#define AST 2
#define ASTAGE 33792u
#define AQ_SZ 32768u
#define AT_SMEM (AQ_SZ + AST*ASTAGE)   // 100352; x2 CTAs = 200704 <= 228KB

__global__ __launch_bounds__(128, 2) void attn_mma(
    const float* __restrict__ madd,
    const __nv_bfloat16* __restrict__ Qh_g, const __nv_bfloat16* __restrict__ Ql_g,
    const __nv_bfloat16* __restrict__ Kh_g, const __nv_bfloat16* __restrict__ Kl_g,
    const __nv_bfloat16* __restrict__ Vh_g, const __nv_bfloat16* __restrict__ Vl_g,
    __nv_bfloat16* __restrict__ Oh_g, __nv_bfloat16* __restrict__ Ol_g)
{
    extern __shared__ char smem[];
    const uint32_t sb = smem_u32(smem);
    const int t = threadIdx.x, lane = t & 31, wid = t >> 5;
    const int b = blockIdx.z, h = blockIdx.y, q0 = blockIdx.x * 128;
    const int g = lane >> 3, r8 = lane & 7;

    const size_t boff = (size_t)b * SS * DD + (size_t)h * DHD;
    const __nv_bfloat16* Qhb = Qh_g + boff;
    const __nv_bfloat16* Qlb = Ql_g + boff;
    const __nv_bfloat16* Khb = Kh_g + boff;
    const __nv_bfloat16* Klb = Kl_g + boff;
    const __nv_bfloat16* Vhb = Vh_g + boff;
    const __nv_bfloat16* Vlb = Vl_g + boff;

    // Q load: 128 rows x 64 bf16, hi @0, lo @16384
    #pragma unroll
    for (int i = 0; i < 16; i++) {
        const int prec = i >> 3;
        const int idx = t + (i & 7) * 128;
        const int row = idx >> 3, sub = idx & 7;
        const uint32_t doff = (prec ? 16384u : 0u)
                            + sw128((uint32_t)row * 128 + (uint32_t)sub * 16);
        cp16(sb + doff,
             (prec ? Qlb : Qhb) + (size_t)(q0 + row) * DD + sub * 8);
    }
    CP_COMMIT();

    auto issue_kv = [&](int ch) {
        const int j0 = ch * 64;
        const uint32_t base = sb + AQ_SZ + (uint32_t)(ch % AST) * ASTAGE;
        #pragma unroll
        for (int i = 0; i < 16; i++) {
            const int tile = i >> 2;
            const int idx = t + (i & 3) * 128;
            const int row = idx >> 3, sub = idx & 7;
            const __nv_bfloat16* src =
                (tile == 0 ? Khb : tile == 1 ? Klb : tile == 2 ? Vhb : Vlb)
                + (size_t)(j0 + row) * DD + sub * 8;
            cp16(base + (uint32_t)tile * 8192u
                      + sw128((uint32_t)row * 128 + (uint32_t)sub * 16), src);
        }
        if (t < 16)
            cp16(base + 32768u + (uint32_t)t * 16, madd + b * SS + j0 + t * 4);
        CP_COMMIT();
    };

    issue_kv(0);
    issue_kv(1);
    CP_WAIT(2);          // Q done
    __syncthreads();

    uint32_t aoff[2];
    #pragma unroll
    for (int mt = 0; mt < 2; mt++)
        aoff[mt] = (uint32_t)(wid*32 + mt*16 + (g & 1)*8 + r8) * 128
                 + (uint32_t)(g >> 1) * 16;

    uint32_t qf[2][4][4];   // Qh frags; Ql reloaded per tile
    #pragma unroll
    for (int mt = 0; mt < 2; mt++)
        #pragma unroll
        for (int ks = 0; ks < 4; ks++)
            ldsm4(qf[mt][ks], sb + sw128(aoff[mt] + ks*32));

    float o[2][8][4];
    #pragma unroll
    for (int mt = 0; mt < 2; mt++)
        #pragma unroll
        for (int nt = 0; nt < 8; nt++)
            #pragma unroll
            for (int c = 0; c < 4; c++) o[mt][nt][c] = 0.0f;
    float mA[2] = {-1e30f, -1e30f}, mB[2] = {-1e30f, -1e30f};
    float lA[2] = {0.0f, 0.0f},     lB[2] = {0.0f, 0.0f};

    const uint32_t kboff = (uint32_t)((g >> 1)*8 + r8) * 128 + (uint32_t)(g & 1)*16;
    const uint32_t vboff = (uint32_t)((g & 1)*8 + r8) * 128 + (uint32_t)(g >> 1)*16;

    const int NKT = SS / 64;   // 32
    for (int ch = 0; ch < NKT; ch++) {
        CP_WAIT(1);
        __syncthreads();

        const uint32_t base = sb + AQ_SZ + (uint32_t)(ch % AST) * ASTAGE;
        const uint32_t sKh = base, sKl = base + 8192u;
        const uint32_t sVh = base + 16384u, sVl = base + 24576u;
        const float* maskS = (const float*)(smem + AQ_SZ
                             + (uint32_t)(ch % AST) * ASTAGE + 32768u);

        // ---- QK^T (Q pre-scaled; K-frags shared across both m-subtiles)
        float s[2][8][4];
        #pragma unroll
        for (int mt = 0; mt < 2; mt++)
            #pragma unroll
            for (int nt = 0; nt < 8; nt++)
                #pragma unroll
                for (int c = 0; c < 4; c++) s[mt][nt][c] = 0.0f;

        #pragma unroll
        for (int ks = 0; ks < 4; ks++) {
            uint32_t qlf[2][4];
            ldsm4(qlf[0], sb + 16384u + sw128(aoff[0] + ks*32));
            ldsm4(qlf[1], sb + 16384u + sw128(aoff[1] + ks*32));
            #pragma unroll
            for (int nq = 0; nq < 4; nq++) {
                uint32_t bh[4], bl[4];
                const uint32_t off = kboff + (uint32_t)nq*2048 + (uint32_t)ks*32;
                ldsm4(bh, sKh + sw128(off));
                ldsm4(bl, sKl + sw128(off));
                #pragma unroll
                for (int mt = 0; mt < 2; mt++) {
                    mma_bf16(s[mt][nq*2],   qf[mt][ks], bh);
                    mma_bf16(s[mt][nq*2],   qf[mt][ks], bl);
                    mma_bf16(s[mt][nq*2],   qlf[mt],    bh);
                    mma_bf16(s[mt][nq*2+1], qf[mt][ks], bh + 2);
                    mma_bf16(s[mt][nq*2+1], qf[mt][ks], bl + 2);
                    mma_bf16(s[mt][nq*2+1], qlf[mt],    bh + 2);
                }
            }
        }

        // ---- mask + online softmax (per m-subtile)
        const int mbase = (lane & 3) * 2;
        #pragma unroll
        for (int mt = 0; mt < 2; mt++) {
            #pragma unroll
            for (int nt = 0; nt < 8; nt++) {
                float2 mk = *(float2*)&maskS[mbase + nt*8];
                s[mt][nt][0] += mk.x;
                s[mt][nt][1] += mk.y;
                s[mt][nt][2] += mk.x;
                s[mt][nt][3] += mk.y;
            }

            float mxA = s[mt][0][0], mxB = s[mt][0][2];
            #pragma unroll
            for (int nt = 0; nt < 8; nt++) {
                mxA = fmaxf(mxA, fmaxf(s[mt][nt][0], s[mt][nt][1]));
                mxB = fmaxf(mxB, fmaxf(s[mt][nt][2], s[mt][nt][3]));
            }
            mxA = fmaxf(mxA, __shfl_xor_sync(0xffffffffu, mxA, 1));
            mxA = fmaxf(mxA, __shfl_xor_sync(0xffffffffu, mxA, 2));
            mxB = fmaxf(mxB, __shfl_xor_sync(0xffffffffu, mxB, 1));
            mxB = fmaxf(mxB, __shfl_xor_sync(0xffffffffu, mxB, 2));
            const float mnA = fmaxf(mA[mt], mxA), mnB = fmaxf(mB[mt], mxB);
            const float scA = __expf(mA[mt] - mnA), scB = __expf(mB[mt] - mnB);
            mA[mt] = mnA; mB[mt] = mnB;

            float sumA = 0.0f, sumB = 0.0f;
            #pragma unroll
            for (int nt = 0; nt < 8; nt++) {
                s[mt][nt][0] = __expf(s[mt][nt][0] - mnA);
                s[mt][nt][1] = __expf(s[mt][nt][1] - mnA);
                s[mt][nt][2] = __expf(s[mt][nt][2] - mnB);
                s[mt][nt][3] = __expf(s[mt][nt][3] - mnB);
                sumA += s[mt][nt][0] + s[mt][nt][1];
                sumB += s[mt][nt][2] + s[mt][nt][3];
            }
            sumA += __shfl_xor_sync(0xffffffffu, sumA, 1);
            sumA += __shfl_xor_sync(0xffffffffu, sumA, 2);
            sumB += __shfl_xor_sync(0xffffffffu, sumB, 1);
            sumB += __shfl_xor_sync(0xffffffffu, sumB, 2);
            lA[mt] = lA[mt] * scA + sumA;
            lB[mt] = lB[mt] * scB + sumB;
            #pragma unroll
            for (int nt = 0; nt < 8; nt++) {
                o[mt][nt][0] *= scA; o[mt][nt][1] *= scA;
                o[mt][nt][2] *= scB; o[mt][nt][3] *= scB;
            }
        }

        // ---- PV (V-frags shared across both m-subtiles; P packed in-loop)
        #pragma unroll
        for (int ks = 0; ks < 4; ks++) {
            uint32_t ph[2][4], pl[2][4];
            #pragma unroll
            for (int mt = 0; mt < 2; mt++)
                #pragma unroll
                for (int half = 0; half < 2; half++) {
                    const int nt = ks*2 + half;
                    uint32_t u0 = cvt_bf16x2(s[mt][nt][0], s[mt][nt][1]);
                    uint32_t u1 = cvt_bf16x2(s[mt][nt][2], s[mt][nt][3]);
                    ph[mt][half*2]   = u0;
                    ph[mt][half*2+1] = u1;
                    float r0 = s[mt][nt][0] - __uint_as_float(u0 << 16);
                    float r1 = s[mt][nt][1] - __uint_as_float(u0 & 0xffff0000u);
                    float r2 = s[mt][nt][2] - __uint_as_float(u1 << 16);
                    float r3 = s[mt][nt][3] - __uint_as_float(u1 & 0xffff0000u);
                    pl[mt][half*2]   = cvt_bf16x2(r0, r1);
                    pl[mt][half*2+1] = cvt_bf16x2(r2, r3);
                }
            #pragma unroll
            for (int nq = 0; nq < 4; nq++) {
                uint32_t vh[4], vl[4];
                const uint32_t off = vboff + (uint32_t)ks*2048 + (uint32_t)nq*32;
                ldsm4t(vh, sVh + sw128(off));
                ldsm4t(vl, sVl + sw128(off));
                #pragma unroll
                for (int mt = 0; mt < 2; mt++) {
                    mma_bf16(o[mt][nq*2],   ph[mt], vh);
                    mma_bf16(o[mt][nq*2],   ph[mt], vl);
                    mma_bf16(o[mt][nq*2],   pl[mt], vh);
                    mma_bf16(o[mt][nq*2+1], ph[mt], vh + 2);
                    mma_bf16(o[mt][nq*2+1], ph[mt], vl + 2);
                    mma_bf16(o[mt][nq*2+1], pl[mt], vh + 2);
                }
            }
        }

        __syncthreads();
        if (ch + 2 < NKT) issue_kv(ch + 2);
    }

    // ---- epilogue: O as hi/lo bf16
    #pragma unroll
    for (int mt = 0; mt < 2; mt++) {
        const float invA = 1.0f / lA[mt], invB = 1.0f / lB[mt];
        const int rowA = q0 + wid*32 + mt*16 + (lane >> 2);
        #pragma unroll
        for (int nt = 0; nt < 8; nt++) {
            const int col = h*DHD + nt*8 + (lane & 3)*2;
            float a0 = o[mt][nt][0]*invA, a1 = o[mt][nt][1]*invA;
            float b0 = o[mt][nt][2]*invB, b1 = o[mt][nt][3]*invB;
            uint32_t hA = cvt_bf16x2(a0, a1), hB = cvt_bf16x2(b0, b1);
            float rA0 = a0 - __uint_as_float(hA << 16);
            float rA1 = a1 - __uint_as_float(hA & 0xffff0000u);
            float rB0 = b0 - __uint_as_float(hB << 16);
            float rB1 = b1 - __uint_as_float(hB & 0xffff0000u);
            const size_t r0 = ((size_t)b*SS + rowA) * DD + col;
            const size_t r1 = ((size_t)b*SS + rowA + 8) * DD + col;
            *(uint32_t*)&Oh_g[r0] = hA;
            *(uint32_t*)&Oh_g[r1] = hB;
            *(uint32_t*)&Ol_g[r0] = cvt_bf16x2(rA0, rA1);
            *(uint32_t*)&Ol_g[r1] = cvt_bf16x2(rB0, rB1);
        }
    }
}

// ---------------------------------------------------------------------------
// Launch
// ---------------------------------------------------------------------------
extern "C" void kernel_launch(void* const* d_in, const int* in_sizes, int n_in,
                              void* d_out, int out_size)
{
    const float* x_q = (const float*)d_in[0];
    const float* x_k = (const float*)d_in[1];
    const float* x_v = (const float*)d_in[2];
    const void*  mask = d_in[3];
    const float* Wq = (const float*)d_in[4];
    const float* bq = (const float*)d_in[5];
    const float* Wk = (const float*)d_in[6];
    const float* bk = (const float*)d_in[7];
    const float* Wv = (const float*)d_in[8];
    const float* bv = (const float*)d_in[9];
    const float* Wo = (const float*)d_in[10];
    const float* bo = (const float*)d_in[11];
    float* out = (float*)d_out;

    float* Mp;
    __nv_bfloat16 *Xqh,*Xql,*Xkh,*Xkl,*Xvh,*Xvl;
    __nv_bfloat16 *Wqh,*Wql,*Wkh,*Wkl,*Wvh,*Wvl,*Woh,*Wol;
    __nv_bfloat16 *Qh,*Ql,*Kh,*Kl,*Vh,*Vl,*Oh,*Ol;
    cudaGetSymbolAddress((void**)&Mp, g_maskadd);
    cudaGetSymbolAddress((void**)&Xqh, g_Xqh); cudaGetSymbolAddress((void**)&Xql, g_Xql);
    cudaGetSymbolAddress((void**)&Xkh, g_Xkh); cudaGetSymbolAddress((void**)&Xkl, g_Xkl);
    cudaGetSymbolAddress((void**)&Xvh, g_Xvh); cudaGetSymbolAddress((void**)&Xvl, g_Xvl);
    cudaGetSymbolAddress((void**)&Wqh, g_Wqh); cudaGetSymbolAddress((void**)&Wql, g_Wql);
    cudaGetSymbolAddress((void**)&Wkh, g_Wkh); cudaGetSymbolAddress((void**)&Wkl, g_Wkl);
    cudaGetSymbolAddress((void**)&Wvh, g_Wvh); cudaGetSymbolAddress((void**)&Wvl, g_Wvl);
    cudaGetSymbolAddress((void**)&Woh, g_Woh); cudaGetSymbolAddress((void**)&Wol, g_Wol);
    cudaGetSymbolAddress((void**)&Qh, g_Qh);   cudaGetSymbolAddress((void**)&Ql, g_Ql);
    cudaGetSymbolAddress((void**)&Kh, g_Kh);   cudaGetSymbolAddress((void**)&Kl, g_Kl);
    cudaGetSymbolAddress((void**)&Vh, g_Vh);   cudaGetSymbolAddress((void**)&Vl, g_Vl);
    cudaGetSymbolAddress((void**)&Oh, g_Oh);   cudaGetSymbolAddress((void**)&Ol, g_Ol);

    SplitJobs7 jobs;
    jobs.src[0] = x_q; jobs.hi[0] = Xqh; jobs.lo[0] = Xql;
    jobs.src[1] = x_k; jobs.hi[1] = Xkh; jobs.lo[1] = Xkl;
    jobs.src[2] = x_v; jobs.hi[2] = Xvh; jobs.lo[2] = Xvl;
    jobs.src[3] = Wq;  jobs.hi[3] = Wqh; jobs.lo[3] = Wql;
    jobs.src[4] = Wk;  jobs.hi[4] = Wkh; jobs.lo[4] = Wkl;
    jobs.src[5] = Wv;  jobs.hi[5] = Wvh; jobs.lo[5] = Wvl;
    jobs.src[6] = Wo;  jobs.hi[6] = Woh; jobs.lo[6] = Wol;
    jobs.mask_raw = mask; jobs.madd = Mp;

    GemmJobs3 gj;
    gj.Ah[0] = Xqh; gj.Al[0] = Xql; gj.Bh[0] = Wqh; gj.Bl[0] = Wql;
    gj.bias[0] = bq; gj.Ch[0] = Qh; gj.Cl[0] = Ql; gj.scale[0] = 0.125f;
    gj.Ah[1] = Xkh; gj.Al[1] = Xkl; gj.Bh[1] = Wkh; gj.Bl[1] = Wkl;
    gj.bias[1] = bk; gj.Ch[1] = Kh; gj.Cl[1] = Kl; gj.scale[1] = 1.0f;
    gj.Ah[2] = Xvh; gj.Al[2] = Xvl; gj.Bh[2] = Wvh; gj.Bl[2] = Wvl;
    gj.bias[2] = bv; gj.Ch[2] = Vh; gj.Cl[2] = Vl; gj.scale[2] = 1.0f;

    cudaFuncSetAttribute(attn_mma,
                         cudaFuncAttributeMaxDynamicSharedMemorySize, AT_SMEM);
    cudaFuncSetAttribute(gemm_pre,
                         cudaFuncAttributeMaxDynamicSharedMemorySize, GEMM_SMEM);
    cudaFuncSetAttribute(gemm_pre3,
                         cudaFuncAttributeMaxDynamicSharedMemorySize, GEMM_SMEM);

    split_all<<<(NTOT + 255)/256, 256>>>(jobs);

    gemm_pre3<<<dim3(DD/64, MTOT/128, 3), 256, GEMM_SMEM>>>(gj);

    attn_mma<<<dim3(SS/128, HH, BB), 128, AT_SMEM>>>(Mp, Qh, Ql, Kh, Kl,
                                                     Vh, Vl, Oh, Ol);

    gemm_pre<<<dim3(DD/64, MTOT/128), 256, GEMM_SMEM>>>(Oh, Ol, Woh, Wol, bo, out);
}

// round 12
// speedup vs baseline: 6.2244x; 1.1634x over previous
#include <cuda_runtime.h>
#include <cuda_bf16.h>
#include <cuda_fp16.h>
#include <cstdint>

// Problem constants
#define BB 2
#define SS 2048
#define DD 1024
#define HH 16
#define DHD 64
#define MTOT (BB*SS)   // 4096
#define GK 1024        // GEMM K
#define TKC 32         // GEMM K chunk (bf16 GEMMs)
#define NCH (GK/TKC)   // 32 chunks

// Scratch (allocation-free rule: __device__ globals)
__device__ float g_maskadd[BB*SS];
__device__ __nv_bfloat16 g_Xqh[MTOT*GK], g_Xql[MTOT*GK];
__device__ __nv_bfloat16 g_Xkh[MTOT*GK], g_Xkl[MTOT*GK];
__device__ __nv_bfloat16 g_Xvh[MTOT*GK], g_Xvl[MTOT*GK];
__device__ __nv_bfloat16 g_Wqh[DD*GK], g_Wql[DD*GK];
__device__ __nv_bfloat16 g_Wkh[DD*GK], g_Wkl[DD*GK];
__device__ __nv_bfloat16 g_Wvh[DD*GK], g_Wvl[DD*GK];
__device__ __half g_Woh[DD*GK], g_Wol[DD*GK];              // fp16 for O-proj
__device__ __nv_bfloat16 g_Qh[MTOT*DD], g_Ql[MTOT*DD];
__device__ __nv_bfloat16 g_Kh[MTOT*DD], g_Kl[MTOT*DD];
__device__ __half g_Vh[MTOT*DD], g_Vl[MTOT*DD];            // fp16 V for PV
__device__ __half g_Oh[MTOT*DD];                           // fp16 attention out

// ---------------------------------------------------------------------------
// helpers
// ---------------------------------------------------------------------------
__device__ __forceinline__ uint32_t smem_u32(const void* p) {
    uint32_t a;
    asm("{ .reg .u64 t; cvta.to.shared.u64 t, %1; cvt.u32.u64 %0, t; }"
        : "=r"(a) : "l"(p));
    return a;
}
__device__ __forceinline__ void ldsm4(uint32_t* r, uint32_t addr) {
    asm volatile("ldmatrix.sync.aligned.m8n8.x4.shared.b16 {%0,%1,%2,%3}, [%4];"
                 : "=r"(r[0]), "=r"(r[1]), "=r"(r[2]), "=r"(r[3]) : "r"(addr));
}
__device__ __forceinline__ void ldsm4t(uint32_t* r, uint32_t addr) {
    asm volatile("ldmatrix.sync.aligned.m8n8.x4.trans.shared.b16 {%0,%1,%2,%3}, [%4];"
                 : "=r"(r[0]), "=r"(r[1]), "=r"(r[2]), "=r"(r[3]) : "r"(addr));
}
__device__ __forceinline__ void mma_bf16(float* c, const uint32_t* a,
                                         const uint32_t* b) {
    asm volatile(
        "mma.sync.aligned.m16n8k16.row.col.f32.bf16.bf16.f32 "
        "{%0,%1,%2,%3}, {%4,%5,%6,%7}, {%8,%9}, {%0,%1,%2,%3};"
        : "+f"(c[0]), "+f"(c[1]), "+f"(c[2]), "+f"(c[3])
        : "r"(a[0]), "r"(a[1]), "r"(a[2]), "r"(a[3]), "r"(b[0]), "r"(b[1]));
}
__device__ __forceinline__ void mma_f16(float* c, const uint32_t* a,
                                        const uint32_t* b) {
    asm volatile(
        "mma.sync.aligned.m16n8k16.row.col.f32.f16.f16.f32 "
        "{%0,%1,%2,%3}, {%4,%5,%6,%7}, {%8,%9}, {%0,%1,%2,%3};"
        : "+f"(c[0]), "+f"(c[1]), "+f"(c[2]), "+f"(c[3])
        : "r"(a[0]), "r"(a[1]), "r"(a[2]), "r"(a[3]), "r"(b[0]), "r"(b[1]));
}
__device__ __forceinline__ uint32_t pack_bf16(__nv_bfloat16 x, __nv_bfloat16 y) {
    __nv_bfloat162 t(x, y);
    return *reinterpret_cast<uint32_t*>(&t);
}
__device__ __forceinline__ uint32_t cvt_bf16x2(float lo, float hi) {
    uint32_t d;
    asm("cvt.rn.bf16x2.f32 %0, %1, %2;" : "=r"(d) : "f"(hi), "f"(lo));
    return d;
}
__device__ __forceinline__ uint32_t cvt_f16x2(float lo, float hi) {
    uint32_t d;
    asm("cvt.rn.f16x2.f32 %0, %1, %2;" : "=r"(d) : "f"(hi), "f"(lo));
    return d;
}
__device__ __forceinline__ float f16lo_f(uint32_t u) {
    return __half2float(__ushort_as_half((unsigned short)(u & 0xffffu)));
}
__device__ __forceinline__ float f16hi_f(uint32_t u) {
    return __half2float(__ushort_as_half((unsigned short)(u >> 16)));
}
__device__ __forceinline__ uint32_t sw128(uint32_t off) {
    return off ^ ((off >> 3) & 0x70);
}
__device__ __forceinline__ void cp16(uint32_t dst, const void* src) {
    asm volatile("cp.async.cg.shared.global [%0], [%1], 16;"
                 :: "r"(dst), "l"(src) : "memory");
}
#define CP_COMMIT() asm volatile("cp.async.commit_group;" ::: "memory")
#define CP_WAIT(n)  asm volatile("cp.async.wait_group %0;" :: "n"(n) : "memory")

// ---------------------------------------------------------------------------
// Fused prepass: hi/lo split of 7 tensors (job 6 = Wo in fp16) + mask.
// ---------------------------------------------------------------------------
struct SplitJobs7 {
    const float* src[7];
    void* hi[7];
    void* lo[7];
    const void* mask_raw;
    float* madd;
};

#define NX4 (MTOT*GK/4)   // 1048576
#define NW4 (DD*GK/4)     // 262144
#define NSPLIT4 (3*NX4 + 4*NW4)
#define NTOT (NSPLIT4 + BB*SS)

__global__ void split_all(SplitJobs7 jobs)
{
    const int i = blockIdx.x * blockDim.x + threadIdx.x;
    if (i >= NSPLIT4) {
        const int idx = i - NSPLIT4;
        if (idx < BB * SS) {
            const unsigned* mw = (const unsigned*)jobs.mask_raw;
            bool is_int32 = true;
            #pragma unroll
            for (int k = 0; k < 64; k++)
                if (mw[k] > 1u) is_int32 = false;
            int m = is_int32 ? (int)mw[idx]
                             : (int)((const unsigned char*)jobs.mask_raw)[idx];
            jobs.madd[idx] = m ? 0.0f : -1e9f;
        }
        return;
    }
    int j, off;
    if (i < 3*NX4) { j = i / NX4; off = i - j*NX4; }
    else { int w = i - 3*NX4; j = 3 + w / NW4; off = w - (j-3)*NW4; }
    float4 v = ((const float4*)jobs.src[j])[off];
    if (j == 6) {   // Wo -> fp16 hi/lo
        __half h0 = __float2half_rn(v.x), h1 = __float2half_rn(v.y);
        __half h2 = __float2half_rn(v.z), h3 = __float2half_rn(v.w);
        __half2 hp0(h0, h1), hp1(h2, h3);
        __half2 lp0(__float2half_rn(v.x - __half2float(h0)),
                    __float2half_rn(v.y - __half2float(h1)));
        __half2 lp1(__float2half_rn(v.z - __half2float(h2)),
                    __float2half_rn(v.w - __half2float(h3)));
        uint2 hp{*(uint32_t*)&hp0, *(uint32_t*)&hp1};
        uint2 lp{*(uint32_t*)&lp0, *(uint32_t*)&lp1};
        ((uint2*)jobs.hi[j])[off] = hp;
        ((uint2*)jobs.lo[j])[off] = lp;
    } else {        // bf16 hi/lo
        __nv_bfloat16 h0 = __float2bfloat16(v.x), h1 = __float2bfloat16(v.y);
        __nv_bfloat16 h2 = __float2bfloat16(v.z), h3 = __float2bfloat16(v.w);
        uint2 hp{pack_bf16(h0, h1), pack_bf16(h2, h3)};
        uint2 lp{pack_bf16(__float2bfloat16(v.x - __bfloat162float(h0)),
                           __float2bfloat16(v.y - __bfloat162float(h1))),
                 pack_bf16(__float2bfloat16(v.z - __bfloat162float(h2)),
                           __float2bfloat16(v.w - __bfloat162float(h3)))};
        ((uint2*)jobs.hi[j])[off] = hp;
        ((uint2*)jobs.lo[j])[off] = lp;
    }
}

// ---------------------------------------------------------------------------
// bf16 3-term GEMM core. CTA 128x64, warp 32x32, 3-stage, occ 2.
// outfmt: 0 = bf16 hi/lo pair, 2 = fp16 hi/lo pair (V projection).
// ---------------------------------------------------------------------------
#define GST 3
#define GSTAGE 24576u
#define GEMM_SMEM (GST*GSTAGE)

__device__ __forceinline__ void gemm_core(
    const __nv_bfloat16* __restrict__ Ah, const __nv_bfloat16* __restrict__ Al,
    const __nv_bfloat16* __restrict__ Bh, const __nv_bfloat16* __restrict__ Bl,
    const float* __restrict__ bias,
    void* __restrict__ Ch, void* __restrict__ Cl, int outfmt,
    float cscale, char* smem)
{
    const uint32_t sb = smem_u32(smem);
    const int t = threadIdx.x, lane = t & 31, wid = t >> 5;
    const int m0 = blockIdx.y * 128, n0 = blockIdx.x * 64;
    const int mw = (wid & 3) * 32, nw = (wid >> 2) * 32;
    const int g = lane >> 3, r8 = lane & 7;

    auto issue = [&](int ch) {
        const int k0 = ch * TKC;
        const uint32_t abase = sb + (uint32_t)(ch % GST) * GSTAGE;
        const uint32_t bbase = abase + 16384u;
        #pragma unroll
        for (int i = 0; i < 4; i++) {
            const int idx = t + i * 256;
            const int row = idx >> 3, sub = idx & 7;
            const int s3 = sub & 3;
            const uint32_t doff = sw128((uint32_t)row * 128
                                        + (sub < 4 ? 0u : 64u) + (uint32_t)s3 * 16);
            cp16(abase + doff,
                 (sub < 4 ? Ah : Al) + (size_t)(m0 + row) * GK + k0 + s3 * 8);
        }
        #pragma unroll
        for (int i = 0; i < 2; i++) {
            const int idx = t + i * 256;
            const int row = idx >> 3, sub = idx & 7;
            const int s3 = sub & 3;
            const uint32_t doff = sw128((uint32_t)row * 128
                                        + (sub < 4 ? 0u : 64u) + (uint32_t)s3 * 16);
            cp16(bbase + doff,
                 (sub < 4 ? Bh : Bl) + (size_t)(n0 + row) * GK + k0 + s3 * 8);
        }
        CP_COMMIT();
    };

    issue(0); issue(1);

    const uint32_t baseA_off = (uint32_t)(mw + (g & 1) * 8 + r8) * 128
                             + (uint32_t)(g >> 1) * 16;
    const uint32_t baseB_off = (uint32_t)(nw + (g >> 1) * 8 + r8) * 128
                             + (uint32_t)(g & 1) * 16;

    float acc[2][4][4];
    #pragma unroll
    for (int mt = 0; mt < 2; mt++)
        #pragma unroll
        for (int nt = 0; nt < 4; nt++)
            #pragma unroll
            for (int c = 0; c < 4; c++) acc[mt][nt][c] = 0.0f;

    for (int ch = 0; ch < NCH; ch++) {
        CP_WAIT(1);
        __syncthreads();
        if (ch + 2 < NCH) issue(ch + 2);

        const uint32_t sA = sb + (uint32_t)(ch % GST) * GSTAGE;
        const uint32_t sB = sA + 16384u;

        #pragma unroll
        for (int ks = 0; ks < 2; ks++) {
            uint32_t af[2][2][4];
            #pragma unroll
            for (int mt = 0; mt < 2; mt++)
                #pragma unroll
                for (int p = 0; p < 2; p++) {
                    const uint32_t off = baseA_off + (uint32_t)mt * 2048
                                       + (uint32_t)p * 64 + (uint32_t)ks * 32;
                    ldsm4(af[mt][p], sA + sw128(off));
                }
            uint32_t bf_[2][4][2];
            #pragma unroll
            for (int np = 0; np < 2; np++)
                #pragma unroll
                for (int p = 0; p < 2; p++) {
                    uint32_t q[4];
                    const uint32_t off = baseB_off + (uint32_t)np * 2048
                                       + (uint32_t)p * 64 + (uint32_t)ks * 32;
                    ldsm4(q, sB + sw128(off));
                    bf_[p][np*2][0]   = q[0]; bf_[p][np*2][1]   = q[1];
                    bf_[p][np*2+1][0] = q[2]; bf_[p][np*2+1][1] = q[3];
                }
            #pragma unroll
            for (int mt = 0; mt < 2; mt++)
                #pragma unroll
                for (int nt = 0; nt < 4; nt++) {
                    mma_bf16(acc[mt][nt], af[mt][0], bf_[0][nt]);
                    mma_bf16(acc[mt][nt], af[mt][0], bf_[1][nt]);
                    mma_bf16(acc[mt][nt], af[mt][1], bf_[0][nt]);
                }
        }
        __syncthreads();
    }

    float bb[4][2];
    #pragma unroll
    for (int nt = 0; nt < 4; nt++) {
        const int col = n0 + nw + nt * 8 + (lane & 3) * 2;
        bb[nt][0] = bias[col];
        bb[nt][1] = bias[col + 1];
    }
    #pragma unroll
    for (int mt = 0; mt < 2; mt++) {
        const int row0 = m0 + mw + mt * 16 + (lane >> 2);
        #pragma unroll
        for (int nt = 0; nt < 4; nt++) {
            const int col = n0 + nw + nt * 8 + (lane & 3) * 2;
            float v0 = (acc[mt][nt][0] + bb[nt][0]) * cscale;
            float v1 = (acc[mt][nt][1] + bb[nt][1]) * cscale;
            float v2 = (acc[mt][nt][2] + bb[nt][0]) * cscale;
            float v3 = (acc[mt][nt][3] + bb[nt][1]) * cscale;
            const size_t i0 = (size_t)row0 * DD + col;
            const size_t i1 = (size_t)(row0 + 8) * DD + col;
            if (outfmt == 0) {
                uint32_t h0 = cvt_bf16x2(v0, v1), h1 = cvt_bf16x2(v2, v3);
                float r0 = v0 - __uint_as_float(h0 << 16);
                float r1 = v1 - __uint_as_float(h0 & 0xffff0000u);
                float r2 = v2 - __uint_as_float(h1 << 16);
                float r3 = v3 - __uint_as_float(h1 & 0xffff0000u);
                ((uint32_t*)Ch)[i0/2] = h0;  ((uint32_t*)Ch)[i1/2] = h1;
                ((uint32_t*)Cl)[i0/2] = cvt_bf16x2(r0, r1);
                ((uint32_t*)Cl)[i1/2] = cvt_bf16x2(r2, r3);
            } else {   // fp16 pair
                uint32_t h0 = cvt_f16x2(v0, v1), h1 = cvt_f16x2(v2, v3);
                float r0 = v0 - f16lo_f(h0), r1 = v1 - f16hi_f(h0);
                float r2 = v2 - f16lo_f(h1), r3 = v3 - f16hi_f(h1);
                ((uint32_t*)Ch)[i0/2] = h0;  ((uint32_t*)Ch)[i1/2] = h1;
                ((uint32_t*)Cl)[i0/2] = cvt_f16x2(r0, r1);
                ((uint32_t*)Cl)[i1/2] = cvt_f16x2(r2, r3);
            }
        }
    }
}

// Fused Q/K/V projections: blockIdx.z = job. V emits fp16 pair.
struct GemmJobs3 {
    const __nv_bfloat16 *Ah[3], *Al[3], *Bh[3], *Bl[3];
    const float* bias[3];
    void *Ch[3], *Cl[3];
    float scale[3];
    int outfmt[3];
};
__global__ __launch_bounds__(256, 2) void gemm_pre3(GemmJobs3 j)
{
    extern __shared__ char smem[];
    const int z = blockIdx.z;
    gemm_core(j.Ah[z], j.Al[z], j.Bh[z], j.Bl[z], j.bias[z],
              j.Ch[z], j.Cl[z], j.outfmt[z], j.scale[z], smem);
}

// ---------------------------------------------------------------------------
// O-projection GEMM: fp16 2-term, C = Oh @ (Wh+Wl)^T + bias (fp32 out).
// CTA 128x64, warp 32x32, K chunk 64, 3-stage. Stage 32KB: A 16K | Bh 8K | Bl 8K.
// ---------------------------------------------------------------------------
#define OCH 16
#define OST 3
#define OSTAGE 32768u
#define GEMMO_SMEM (OST*OSTAGE)

__global__ __launch_bounds__(256, 2) void gemm_o(
    const __half* __restrict__ A,
    const __half* __restrict__ Bh, const __half* __restrict__ Bl,
    const float* __restrict__ bias, float* __restrict__ Cf)
{
    extern __shared__ char smem[];
    const uint32_t sb = smem_u32(smem);
    const int t = threadIdx.x, lane = t & 31, wid = t >> 5;
    const int m0 = blockIdx.y * 128, n0 = blockIdx.x * 64;
    const int mw = (wid & 3) * 32, nw = (wid >> 2) * 32;
    const int g = lane >> 3, r8 = lane & 7;

    auto issue = [&](int ch) {
        const int k0 = ch * 64;
        const uint32_t abase = sb + (uint32_t)(ch % OST) * OSTAGE;
        #pragma unroll
        for (int i = 0; i < 4; i++) {       // A: 128 rows x 128B (64 f16)
            const int idx = t + i * 256;
            const int row = idx >> 3, sub = idx & 7;
            cp16(abase + sw128((uint32_t)row * 128 + (uint32_t)sub * 16),
                 A + (size_t)(m0 + row) * GK + k0 + sub * 8);
        }
        #pragma unroll
        for (int i = 0; i < 2; i++) {       // Bh + Bl: 64 rows x 128B each
            const int idx = t + i * 256;
            const int row = idx >> 3, sub = idx & 7;
            const uint32_t doff = sw128((uint32_t)row * 128 + (uint32_t)sub * 16);
            cp16(abase + 16384u + doff,
                 Bh + (size_t)(n0 + row) * GK + k0 + sub * 8);
            cp16(abase + 24576u + doff,
                 Bl + (size_t)(n0 + row) * GK + k0 + sub * 8);
        }
        CP_COMMIT();
    };

    issue(0); issue(1);

    const uint32_t baseA_off = (uint32_t)(mw + (g & 1) * 8 + r8) * 128
                             + (uint32_t)(g >> 1) * 16;
    const uint32_t baseB_off = (uint32_t)(nw + (g >> 1) * 8 + r8) * 128
                             + (uint32_t)(g & 1) * 16;

    float acc[2][4][4];
    #pragma unroll
    for (int mt = 0; mt < 2; mt++)
        #pragma unroll
        for (int nt = 0; nt < 4; nt++)
            #pragma unroll
            for (int c = 0; c < 4; c++) acc[mt][nt][c] = 0.0f;

    for (int ch = 0; ch < OCH; ch++) {
        CP_WAIT(1);
        __syncthreads();
        if (ch + 2 < OCH) issue(ch + 2);

        const uint32_t sA = sb + (uint32_t)(ch % OST) * OSTAGE;
        const uint32_t sBh = sA + 16384u, sBl = sA + 24576u;

        #pragma unroll
        for (int ks = 0; ks < 4; ks++) {
            uint32_t af[2][4];
            #pragma unroll
            for (int mt = 0; mt < 2; mt++)
                ldsm4(af[mt], sA + sw128(baseA_off + (uint32_t)mt*2048
                                         + (uint32_t)ks*32));
            uint32_t bh[2][4][2], bl[2][4][2];  // actually [nt][2]
            uint32_t bfh[4][2], bfl[4][2];
            #pragma unroll
            for (int np = 0; np < 2; np++) {
                uint32_t q[4];
                const uint32_t off = baseB_off + (uint32_t)np*2048 + (uint32_t)ks*32;
                ldsm4(q, sBh + sw128(off));
                bfh[np*2][0] = q[0]; bfh[np*2][1] = q[1];
                bfh[np*2+1][0] = q[2]; bfh[np*2+1][1] = q[3];
                ldsm4(q, sBl + sw128(off));
                bfl[np*2][0] = q[0]; bfl[np*2][1] = q[1];
                bfl[np*2+1][0] = q[2]; bfl[np*2+1][1] = q[3];
            }
            (void)bh; (void)bl;
            #pragma unroll
            for (int mt = 0; mt < 2; mt++)
                #pragma unroll
                for (int nt = 0; nt < 4; nt++) {
                    mma_f16(acc[mt][nt], af[mt], bfh[nt]);
                    mma_f16(acc[mt][nt], af[mt], bfl[nt]);
                }
        }
        __syncthreads();
    }

    float bb[4][2];
    #pragma unroll
    for (int nt = 0; nt < 4; nt++) {
        const int col = n0 + nw + nt * 8 + (lane & 3) * 2;
        bb[nt][0] = bias[col];
        bb[nt][1] = bias[col + 1];
    }
    #pragma unroll
    for (int mt = 0; mt < 2; mt++) {
        const int row0 = m0 + mw + mt * 16 + (lane >> 2);
        #pragma unroll
        for (int nt = 0; nt < 4; nt++) {
            const int col = n0 + nw + nt * 8 + (lane & 3) * 2;
            *(float2*)&Cf[(size_t)row0 * DD + col] =
                float2{acc[mt][nt][0] + bb[nt][0], acc[mt][nt][1] + bb[nt][1]};
            *(float2*)&Cf[(size_t)(row0 + 8) * DD + col] =
                float2{acc[mt][nt][2] + bb[nt][0], acc[mt][nt][3] + bb[nt][1]};
        }
    }
}

// ---------------------------------------------------------------------------
// Tensor flash attention: 128-thread CTAs (4 warps x 32 rows), occ 2.
// QK^T bf16 3-term (Q pre-scaled by 0.125); PV fp16 2-term (P fp16, V fp16
// hi/lo). Output Oh = fp16(O) single.
// ---------------------------------------------------------------------------
#define AST 2
#define ASTAGE 33792u
#define AQ_SZ 32768u
#define AT_SMEM (AQ_SZ + AST*ASTAGE)   // 100352; 2 CTAs/SM

__global__ __launch_bounds__(128, 2) void attn_mma(
    const float* __restrict__ madd,
    const __nv_bfloat16* __restrict__ Qh_g, const __nv_bfloat16* __restrict__ Ql_g,
    const __nv_bfloat16* __restrict__ Kh_g, const __nv_bfloat16* __restrict__ Kl_g,
    const __half* __restrict__ Vh_g, const __half* __restrict__ Vl_g,
    __half* __restrict__ Oh_g)
{
    extern __shared__ char smem[];
    const uint32_t sb = smem_u32(smem);
    const int t = threadIdx.x, lane = t & 31, wid = t >> 5;
    const int b = blockIdx.z, h = blockIdx.y, q0 = blockIdx.x * 128;
    const int g = lane >> 3, r8 = lane & 7;

    const size_t boff = (size_t)b * SS * DD + (size_t)h * DHD;
    const __nv_bfloat16* Qhb = Qh_g + boff;
    const __nv_bfloat16* Qlb = Ql_g + boff;
    const char* kvsrc[4] = {
        (const char*)(Kh_g + boff), (const char*)(Kl_g + boff),
        (const char*)(Vh_g + boff), (const char*)(Vl_g + boff)
    };

    // Q load: 128 rows x 64 bf16, hi @0, lo @16384
    #pragma unroll
    for (int i = 0; i < 16; i++) {
        const int prec = i >> 3;
        const int idx = t + (i & 7) * 128;
        const int row = idx >> 3, sub = idx & 7;
        const uint32_t doff = (prec ? 16384u : 0u)
                            + sw128((uint32_t)row * 128 + (uint32_t)sub * 16);
        cp16(sb + doff,
             (prec ? Qlb : Qhb) + (size_t)(q0 + row) * DD + sub * 8);
    }
    CP_COMMIT();

    auto issue_kv = [&](int ch) {
        const int j0 = ch * 64;
        const uint32_t base = sb + AQ_SZ + (uint32_t)(ch % AST) * ASTAGE;
        #pragma unroll
        for (int i = 0; i < 16; i++) {
            const int tile = i >> 2;
            const int idx = t + (i & 3) * 128;
            const int row = idx >> 3, sub = idx & 7;
            const char* src = kvsrc[tile]
                + ((size_t)(j0 + row) * DD + sub * 8) * 2;
            cp16(base + (uint32_t)tile * 8192u
                      + sw128((uint32_t)row * 128 + (uint32_t)sub * 16), src);
        }
        if (t < 16)
            cp16(base + 32768u + (uint32_t)t * 16, madd + b * SS + j0 + t * 4);
        CP_COMMIT();
    };

    issue_kv(0);
    issue_kv(1);
    CP_WAIT(2);
    __syncthreads();

    uint32_t aoff[2];
    #pragma unroll
    for (int mt = 0; mt < 2; mt++)
        aoff[mt] = (uint32_t)(wid*32 + mt*16 + (g & 1)*8 + r8) * 128
                 + (uint32_t)(g >> 1) * 16;

    uint32_t qf[2][4][4];
    #pragma unroll
    for (int mt = 0; mt < 2; mt++)
        #pragma unroll
        for (int ks = 0; ks < 4; ks++)
            ldsm4(qf[mt][ks], sb + sw128(aoff[mt] + ks*32));

    float o[2][8][4];
    #pragma unroll
    for (int mt = 0; mt < 2; mt++)
        #pragma unroll
        for (int nt = 0; nt < 8; nt++)
            #pragma unroll
            for (int c = 0; c < 4; c++) o[mt][nt][c] = 0.0f;
    float mA[2] = {-1e30f, -1e30f}, mB[2] = {-1e30f, -1e30f};
    float lA[2] = {0.0f, 0.0f},     lB[2] = {0.0f, 0.0f};

    const uint32_t kboff = (uint32_t)((g >> 1)*8 + r8) * 128 + (uint32_t)(g & 1)*16;
    const uint32_t vboff = (uint32_t)((g & 1)*8 + r8) * 128 + (uint32_t)(g >> 1)*16;

    const int NKT = SS / 64;   // 32
    for (int ch = 0; ch < NKT; ch++) {
        CP_WAIT(1);
        __syncthreads();

        const uint32_t base = sb + AQ_SZ + (uint32_t)(ch % AST) * ASTAGE;
        const uint32_t sKh = base, sKl = base + 8192u;
        const uint32_t sVh = base + 16384u, sVl = base + 24576u;
        const float* maskS = (const float*)(smem + AQ_SZ
                             + (uint32_t)(ch % AST) * ASTAGE + 32768u);

        // ---- QK^T (bf16 3-term; Q pre-scaled)
        float s[2][8][4];
        #pragma unroll
        for (int mt = 0; mt < 2; mt++)
            #pragma unroll
            for (int nt = 0; nt < 8; nt++)
                #pragma unroll
                for (int c = 0; c < 4; c++) s[mt][nt][c] = 0.0f;

        #pragma unroll
        for (int ks = 0; ks < 4; ks++) {
            uint32_t qlf[2][4];
            ldsm4(qlf[0], sb + 16384u + sw128(aoff[0] + ks*32));
            ldsm4(qlf[1], sb + 16384u + sw128(aoff[1] + ks*32));
            #pragma unroll
            for (int nq = 0; nq < 4; nq++) {
                uint32_t bh[4], bl[4];
                const uint32_t off = kboff + (uint32_t)nq*2048 + (uint32_t)ks*32;
                ldsm4(bh, sKh + sw128(off));
                ldsm4(bl, sKl + sw128(off));
                #pragma unroll
                for (int mt = 0; mt < 2; mt++) {
                    mma_bf16(s[mt][nq*2],   qf[mt][ks], bh);
                    mma_bf16(s[mt][nq*2],   qf[mt][ks], bl);
                    mma_bf16(s[mt][nq*2],   qlf[mt],    bh);
                    mma_bf16(s[mt][nq*2+1], qf[mt][ks], bh + 2);
                    mma_bf16(s[mt][nq*2+1], qf[mt][ks], bl + 2);
                    mma_bf16(s[mt][nq*2+1], qlf[mt],    bh + 2);
                }
            }
        }

        // ---- mask + online softmax
        const int mbase = (lane & 3) * 2;
        #pragma unroll
        for (int mt = 0; mt < 2; mt++) {
            #pragma unroll
            for (int nt = 0; nt < 8; nt++) {
                float2 mk = *(float2*)&maskS[mbase + nt*8];
                s[mt][nt][0] += mk.x;
                s[mt][nt][1] += mk.y;
                s[mt][nt][2] += mk.x;
                s[mt][nt][3] += mk.y;
            }

            float mxA = s[mt][0][0], mxB = s[mt][0][2];
            #pragma unroll
            for (int nt = 0; nt < 8; nt++) {
                mxA = fmaxf(mxA, fmaxf(s[mt][nt][0], s[mt][nt][1]));
                mxB = fmaxf(mxB, fmaxf(s[mt][nt][2], s[mt][nt][3]));
            }
            mxA = fmaxf(mxA, __shfl_xor_sync(0xffffffffu, mxA, 1));
            mxA = fmaxf(mxA, __shfl_xor_sync(0xffffffffu, mxA, 2));
            mxB = fmaxf(mxB, __shfl_xor_sync(0xffffffffu, mxB, 1));
            mxB = fmaxf(mxB, __shfl_xor_sync(0xffffffffu, mxB, 2));
            const float mnA = fmaxf(mA[mt], mxA), mnB = fmaxf(mB[mt], mxB);
            const float scA = __expf(mA[mt] - mnA), scB = __expf(mB[mt] - mnB);
            mA[mt] = mnA; mB[mt] = mnB;

            float sumA = 0.0f, sumB = 0.0f;
            #pragma unroll
            for (int nt = 0; nt < 8; nt++) {
                s[mt][nt][0] = __expf(s[mt][nt][0] - mnA);
                s[mt][nt][1] = __expf(s[mt][nt][1] - mnA);
                s[mt][nt][2] = __expf(s[mt][nt][2] - mnB);
                s[mt][nt][3] = __expf(s[mt][nt][3] - mnB);
                sumA += s[mt][nt][0] + s[mt][nt][1];
                sumB += s[mt][nt][2] + s[mt][nt][3];
            }
            sumA += __shfl_xor_sync(0xffffffffu, sumA, 1);
            sumA += __shfl_xor_sync(0xffffffffu, sumA, 2);
            sumB += __shfl_xor_sync(0xffffffffu, sumB, 1);
            sumB += __shfl_xor_sync(0xffffffffu, sumB, 2);
            lA[mt] = lA[mt] * scA + sumA;
            lB[mt] = lB[mt] * scB + sumB;
            #pragma unroll
            for (int nt = 0; nt < 8; nt++) {
                o[mt][nt][0] *= scA; o[mt][nt][1] *= scA;
                o[mt][nt][2] *= scB; o[mt][nt][3] *= scB;
            }
        }

        // ---- PV: fp16 2-term (P fp16, V fp16 hi/lo)
        #pragma unroll
        for (int ks = 0; ks < 4; ks++) {
            uint32_t ph[2][4];
            #pragma unroll
            for (int mt = 0; mt < 2; mt++)
                #pragma unroll
                for (int half = 0; half < 2; half++) {
                    const int nt = ks*2 + half;
                    ph[mt][half*2]   = cvt_f16x2(s[mt][nt][0], s[mt][nt][1]);
                    ph[mt][half*2+1] = cvt_f16x2(s[mt][nt][2], s[mt][nt][3]);
                }
            #pragma unroll
            for (int nq = 0; nq < 4; nq++) {
                uint32_t vh[4], vl[4];
                const uint32_t off = vboff + (uint32_t)ks*2048 + (uint32_t)nq*32;
                ldsm4t(vh, sVh + sw128(off));
                ldsm4t(vl, sVl + sw128(off));
                #pragma unroll
                for (int mt = 0; mt < 2; mt++) {
                    mma_f16(o[mt][nq*2],   ph[mt], vh);
                    mma_f16(o[mt][nq*2],   ph[mt], vl);
                    mma_f16(o[mt][nq*2+1], ph[mt], vh + 2);
                    mma_f16(o[mt][nq*2+1], ph[mt], vl + 2);
                }
            }
        }

        __syncthreads();
        if (ch + 2 < NKT) issue_kv(ch + 2);
    }

    // ---- epilogue: Oh = fp16(O)
    #pragma unroll
    for (int mt = 0; mt < 2; mt++) {
        const float invA = 1.0f / lA[mt], invB = 1.0f / lB[mt];
        const int rowA = q0 + wid*32 + mt*16 + (lane >> 2);
        #pragma unroll
        for (int nt = 0; nt < 8; nt++) {
            const int col = h*DHD + nt*8 + (lane & 3)*2;
            const size_t r0 = ((size_t)b*SS + rowA) * DD + col;
            const size_t r1 = ((size_t)b*SS + rowA + 8) * DD + col;
            *(uint32_t*)&Oh_g[r0] = cvt_f16x2(o[mt][nt][0]*invA, o[mt][nt][1]*invA);
            *(uint32_t*)&Oh_g[r1] = cvt_f16x2(o[mt][nt][2]*invB, o[mt][nt][3]*invB);
        }
    }
}

// ---------------------------------------------------------------------------
// Launch
// ---------------------------------------------------------------------------
extern "C" void kernel_launch(void* const* d_in, const int* in_sizes, int n_in,
                              void* d_out, int out_size)
{
    const float* x_q = (const float*)d_in[0];
    const float* x_k = (const float*)d_in[1];
    const float* x_v = (const float*)d_in[2];
    const void*  mask = d_in[3];
    const float* Wq = (const float*)d_in[4];
    const float* bq = (const float*)d_in[5];
    const float* Wk = (const float*)d_in[6];
    const float* bk = (const float*)d_in[7];
    const float* Wv = (const float*)d_in[8];
    const float* bv = (const float*)d_in[9];
    const float* Wo = (const float*)d_in[10];
    const float* bo = (const float*)d_in[11];
    float* out = (float*)d_out;

    float* Mp;
    __nv_bfloat16 *Xqh,*Xql,*Xkh,*Xkl,*Xvh,*Xvl;
    __nv_bfloat16 *Wqh,*Wql,*Wkh,*Wkl,*Wvh,*Wvl;
    __half *Woh,*Wol,*Vh,*Vl,*Oh;
    __nv_bfloat16 *Qh,*Ql,*Kh,*Kl;
    cudaGetSymbolAddress((void**)&Mp, g_maskadd);
    cudaGetSymbolAddress((void**)&Xqh, g_Xqh); cudaGetSymbolAddress((void**)&Xql, g_Xql);
    cudaGetSymbolAddress((void**)&Xkh, g_Xkh); cudaGetSymbolAddress((void**)&Xkl, g_Xkl);
    cudaGetSymbolAddress((void**)&Xvh, g_Xvh); cudaGetSymbolAddress((void**)&Xvl, g_Xvl);
    cudaGetSymbolAddress((void**)&Wqh, g_Wqh); cudaGetSymbolAddress((void**)&Wql, g_Wql);
    cudaGetSymbolAddress((void**)&Wkh, g_Wkh); cudaGetSymbolAddress((void**)&Wkl, g_Wkl);
    cudaGetSymbolAddress((void**)&Wvh, g_Wvh); cudaGetSymbolAddress((void**)&Wvl, g_Wvl);
    cudaGetSymbolAddress((void**)&Woh, g_Woh); cudaGetSymbolAddress((void**)&Wol, g_Wol);
    cudaGetSymbolAddress((void**)&Qh, g_Qh);   cudaGetSymbolAddress((void**)&Ql, g_Ql);
    cudaGetSymbolAddress((void**)&Kh, g_Kh);   cudaGetSymbolAddress((void**)&Kl, g_Kl);
    cudaGetSymbolAddress((void**)&Vh, g_Vh);   cudaGetSymbolAddress((void**)&Vl, g_Vl);
    cudaGetSymbolAddress((void**)&Oh, g_Oh);

    SplitJobs7 jobs;
    jobs.src[0] = x_q; jobs.hi[0] = Xqh; jobs.lo[0] = Xql;
    jobs.src[1] = x_k; jobs.hi[1] = Xkh; jobs.lo[1] = Xkl;
    jobs.src[2] = x_v; jobs.hi[2] = Xvh; jobs.lo[2] = Xvl;
    jobs.src[3] = Wq;  jobs.hi[3] = Wqh; jobs.lo[3] = Wql;
    jobs.src[4] = Wk;  jobs.hi[4] = Wkh; jobs.lo[4] = Wkl;
    jobs.src[5] = Wv;  jobs.hi[5] = Wvh; jobs.lo[5] = Wvl;
    jobs.src[6] = Wo;  jobs.hi[6] = Woh; jobs.lo[6] = Wol;   // fp16
    jobs.mask_raw = mask; jobs.madd = Mp;

    GemmJobs3 gj;
    gj.Ah[0] = Xqh; gj.Al[0] = Xql; gj.Bh[0] = Wqh; gj.Bl[0] = Wql;
    gj.bias[0] = bq; gj.Ch[0] = Qh; gj.Cl[0] = Ql; gj.scale[0] = 0.125f;
    gj.outfmt[0] = 0;
    gj.Ah[1] = Xkh; gj.Al[1] = Xkl; gj.Bh[1] = Wkh; gj.Bl[1] = Wkl;
    gj.bias[1] = bk; gj.Ch[1] = Kh; gj.Cl[1] = Kl; gj.scale[1] = 1.0f;
    gj.outfmt[1] = 0;
    gj.Ah[2] = Xvh; gj.Al[2] = Xvl; gj.Bh[2] = Wvh; gj.Bl[2] = Wvl;
    gj.bias[2] = bv; gj.Ch[2] = Vh; gj.Cl[2] = Vl; gj.scale[2] = 1.0f;
    gj.outfmt[2] = 2;   // fp16 pair

    cudaFuncSetAttribute(attn_mma,
                         cudaFuncAttributeMaxDynamicSharedMemorySize, AT_SMEM);
    cudaFuncSetAttribute(gemm_pre3,
                         cudaFuncAttributeMaxDynamicSharedMemorySize, GEMM_SMEM);
    cudaFuncSetAttribute(gemm_o,
                         cudaFuncAttributeMaxDynamicSharedMemorySize, GEMMO_SMEM);

    split_all<<<(NTOT + 255)/256, 256>>>(jobs);

    gemm_pre3<<<dim3(DD/64, MTOT/128, 3), 256, GEMM_SMEM>>>(gj);

    attn_mma<<<dim3(SS/128, HH, BB), 128, AT_SMEM>>>(Mp, Qh, Ql, Kh, Kl,
                                                     Vh, Vl, Oh);

    gemm_o<<<dim3(DD/64, MTOT/128), 256, GEMMO_SMEM>>>(Oh, Woh, Wol, bo, out);
}

// round 15
// speedup vs baseline: 7.3067x; 1.1739x over previous
#include <cuda_runtime.h>
#include <cuda_bf16.h>
#include <cuda_fp16.h>
#include <cstdint>

// Problem constants
#define BB 2
#define SS 2048
#define DD 1024
#define HH 16
#define DHD 64
#define MTOT (BB*SS)   // 4096
#define GK 1024        // GEMM K

// Scratch (allocation-free rule: __device__ globals)
__device__ float g_maskadd[BB*SS];
__device__ __half g_Xq[MTOT*GK], g_Xk[MTOT*GK], g_Xv[MTOT*GK];   // fp16 single
__device__ __half g_Wqh[DD*GK], g_Wql[DD*GK];
__device__ __half g_Wkh[DD*GK], g_Wkl[DD*GK];
__device__ __half g_Wvh[DD*GK], g_Wvl[DD*GK];
__device__ __half g_Woh[DD*GK], g_Wol[DD*GK];
__device__ __nv_bfloat16 g_Qh[MTOT*DD], g_Ql[MTOT*DD];
__device__ __nv_bfloat16 g_Kh[MTOT*DD], g_Kl[MTOT*DD];
__device__ __half g_Vh[MTOT*DD], g_Vl[MTOT*DD];
__device__ __half g_Oh[MTOT*DD];

// ---------------------------------------------------------------------------
// helpers
// ---------------------------------------------------------------------------
__device__ __forceinline__ uint32_t smem_u32(const void* p) {
    uint32_t a;
    asm("{ .reg .u64 t; cvta.to.shared.u64 t, %1; cvt.u32.u64 %0, t; }"
        : "=r"(a) : "l"(p));
    return a;
}
__device__ __forceinline__ void ldsm4(uint32_t* r, uint32_t addr) {
    asm volatile("ldmatrix.sync.aligned.m8n8.x4.shared.b16 {%0,%1,%2,%3}, [%4];"
                 : "=r"(r[0]), "=r"(r[1]), "=r"(r[2]), "=r"(r[3]) : "r"(addr));
}
__device__ __forceinline__ void ldsm4t(uint32_t* r, uint32_t addr) {
    asm volatile("ldmatrix.sync.aligned.m8n8.x4.trans.shared.b16 {%0,%1,%2,%3}, [%4];"
                 : "=r"(r[0]), "=r"(r[1]), "=r"(r[2]), "=r"(r[3]) : "r"(addr));
}
__device__ __forceinline__ void mma_bf16(float* c, const uint32_t* a,
                                         const uint32_t* b) {
    asm volatile(
        "mma.sync.aligned.m16n8k16.row.col.f32.bf16.bf16.f32 "
        "{%0,%1,%2,%3}, {%4,%5,%6,%7}, {%8,%9}, {%0,%1,%2,%3};"
        : "+f"(c[0]), "+f"(c[1]), "+f"(c[2]), "+f"(c[3])
        : "r"(a[0]), "r"(a[1]), "r"(a[2]), "r"(a[3]), "r"(b[0]), "r"(b[1]));
}
__device__ __forceinline__ void mma_f16(float* c, const uint32_t* a,
                                        const uint32_t* b) {
    asm volatile(
        "mma.sync.aligned.m16n8k16.row.col.f32.f16.f16.f32 "
        "{%0,%1,%2,%3}, {%4,%5,%6,%7}, {%8,%9}, {%0,%1,%2,%3};"
        : "+f"(c[0]), "+f"(c[1]), "+f"(c[2]), "+f"(c[3])
        : "r"(a[0]), "r"(a[1]), "r"(a[2]), "r"(a[3]), "r"(b[0]), "r"(b[1]));
}
__device__ __forceinline__ uint32_t cvt_bf16x2(float lo, float hi) {
    uint32_t d;
    asm("cvt.rn.bf16x2.f32 %0, %1, %2;" : "=r"(d) : "f"(hi), "f"(lo));
    return d;
}
__device__ __forceinline__ uint32_t cvt_f16x2(float lo, float hi) {
    uint32_t d;
    asm("cvt.rn.f16x2.f32 %0, %1, %2;" : "=r"(d) : "f"(hi), "f"(lo));
    return d;
}
__device__ __forceinline__ float f16lo_f(uint32_t u) {
    return __half2float(__ushort_as_half((unsigned short)(u & 0xffffu)));
}
__device__ __forceinline__ float f16hi_f(uint32_t u) {
    return __half2float(__ushort_as_half((unsigned short)(u >> 16)));
}
__device__ __forceinline__ uint32_t sw128(uint32_t off) {
    return off ^ ((off >> 3) & 0x70);
}
__device__ __forceinline__ void cp16(uint32_t dst, const void* src) {
    asm volatile("cp.async.cg.shared.global [%0], [%1], 16;"
                 :: "r"(dst), "l"(src) : "memory");
}
#define CP_COMMIT() asm volatile("cp.async.commit_group;" ::: "memory")
#define CP_WAIT(n)  asm volatile("cp.async.wait_group %0;" :: "n"(n) : "memory")

// ---------------------------------------------------------------------------
// Fused prepass: X tensors -> fp16 single; weights -> fp16 hi/lo; mask.
// ---------------------------------------------------------------------------
struct SplitJobs7 {
    const float* src[7];
    void* hi[7];
    void* lo[7];     // null for jobs 0-2
    const void* mask_raw;
    float* madd;
};

#define NX4 (MTOT*GK/4)   // 1048576
#define NW4 (DD*GK/4)     // 262144
#define NSPLIT4 (3*NX4 + 4*NW4)
#define NTOT (NSPLIT4 + BB*SS)

__global__ void split_all(SplitJobs7 jobs)
{
    const int i = blockIdx.x * blockDim.x + threadIdx.x;
    if (i >= NSPLIT4) {
        const int idx = i - NSPLIT4;
        if (idx < BB * SS) {
            const unsigned* mw = (const unsigned*)jobs.mask_raw;
            bool is_int32 = true;
            #pragma unroll
            for (int k = 0; k < 64; k++)
                if (mw[k] > 1u) is_int32 = false;
            int m = is_int32 ? (int)mw[idx]
                             : (int)((const unsigned char*)jobs.mask_raw)[idx];
            jobs.madd[idx] = m ? 0.0f : -1e9f;
        }
        return;
    }
    int j, off;
    if (i < 3*NX4) { j = i / NX4; off = i - j*NX4; }
    else { int w = i - 3*NX4; j = 3 + w / NW4; off = w - (j-3)*NW4; }
    float4 v = ((const float4*)jobs.src[j])[off];
    __half h0 = __float2half_rn(v.x), h1 = __float2half_rn(v.y);
    __half h2 = __float2half_rn(v.z), h3 = __float2half_rn(v.w);
    __half2 hp0(h0, h1), hp1(h2, h3);
    uint2 hp{*(uint32_t*)&hp0, *(uint32_t*)&hp1};
    ((uint2*)jobs.hi[j])[off] = hp;
    if (j >= 3) {
        __half2 lp0(__float2half_rn(v.x - __half2float(h0)),
                    __float2half_rn(v.y - __half2float(h1)));
        __half2 lp1(__float2half_rn(v.z - __half2float(h2)),
                    __float2half_rn(v.w - __half2float(h3)));
        uint2 lp{*(uint32_t*)&lp0, *(uint32_t*)&lp1};
        ((uint2*)jobs.lo[j])[off] = lp;
    }
}

// ---------------------------------------------------------------------------
// fp16 2-term GEMM core: C = A @ (Bh+Bl)^T + bias.
// CTA 128x64, warp 32x32, K chunk 64, 3-stage. Stage 32KB: A 16K | Bh 8K | Bl 8K.
// outfmt: -1 = fp32, 0 = bf16 hi/lo pair, 2 = fp16 hi/lo pair.
// ---------------------------------------------------------------------------
#define OCH 16
#define OST 3
#define OSTAGE 32768u
#define GEMMO_SMEM (OST*OSTAGE)

__device__ __forceinline__ void gemm_f16_core(
    const __half* __restrict__ A,
    const __half* __restrict__ Bh, const __half* __restrict__ Bl,
    const float* __restrict__ bias, float* __restrict__ Cf,
    void* __restrict__ Ch, void* __restrict__ Cl, int outfmt,
    float cscale, char* smem)
{
    const uint32_t sb = smem_u32(smem);
    const int t = threadIdx.x, lane = t & 31, wid = t >> 5;
    const int m0 = blockIdx.y * 128, n0 = blockIdx.x * 64;
    const int mw = (wid & 3) * 32, nw = (wid >> 2) * 32;
    const int g = lane >> 3, r8 = lane & 7;

    auto issue = [&](int ch) {
        const int k0 = ch * 64;
        const uint32_t abase = sb + (uint32_t)(ch % OST) * OSTAGE;
        #pragma unroll
        for (int i = 0; i < 4; i++) {
            const int idx = t + i * 256;
            const int row = idx >> 3, sub = idx & 7;
            cp16(abase + sw128((uint32_t)row * 128 + (uint32_t)sub * 16),
                 A + (size_t)(m0 + row) * GK + k0 + sub * 8);
        }
        #pragma unroll
        for (int i = 0; i < 2; i++) {
            const int idx = t + i * 256;
            const int row = idx >> 3, sub = idx & 7;
            const uint32_t doff = sw128((uint32_t)row * 128 + (uint32_t)sub * 16);
            cp16(abase + 16384u + doff,
                 Bh + (size_t)(n0 + row) * GK + k0 + sub * 8);
            cp16(abase + 24576u + doff,
                 Bl + (size_t)(n0 + row) * GK + k0 + sub * 8);
        }
        CP_COMMIT();
    };

    issue(0); issue(1);

    const uint32_t baseA_off = (uint32_t)(mw + (g & 1) * 8 + r8) * 128
                             + (uint32_t)(g >> 1) * 16;
    const uint32_t baseB_off = (uint32_t)(nw + (g >> 1) * 8 + r8) * 128
                             + (uint32_t)(g & 1) * 16;

    float acc[2][4][4];
    #pragma unroll
    for (int mt = 0; mt < 2; mt++)
        #pragma unroll
        for (int nt = 0; nt < 4; nt++)
            #pragma unroll
            for (int c = 0; c < 4; c++) acc[mt][nt][c] = 0.0f;

    for (int ch = 0; ch < OCH; ch++) {
        CP_WAIT(1);
        __syncthreads();
        if (ch + 2 < OCH) issue(ch + 2);

        const uint32_t sA = sb + (uint32_t)(ch % OST) * OSTAGE;
        const uint32_t sBh = sA + 16384u, sBl = sA + 24576u;

        #pragma unroll
        for (int ks = 0; ks < 4; ks++) {
            uint32_t af[2][4];
            #pragma unroll
            for (int mt = 0; mt < 2; mt++)
                ldsm4(af[mt], sA + sw128(baseA_off + (uint32_t)mt*2048
                                         + (uint32_t)ks*32));
            uint32_t bfh[4][2], bfl[4][2];
            #pragma unroll
            for (int np = 0; np < 2; np++) {
                uint32_t q[4];
                const uint32_t off = baseB_off + (uint32_t)np*2048 + (uint32_t)ks*32;
                ldsm4(q, sBh + sw128(off));
                bfh[np*2][0] = q[0]; bfh[np*2][1] = q[1];
                bfh[np*2+1][0] = q[2]; bfh[np*2+1][1] = q[3];
                ldsm4(q, sBl + sw128(off));
                bfl[np*2][0] = q[0]; bfl[np*2][1] = q[1];
                bfl[np*2+1][0] = q[2]; bfl[np*2+1][1] = q[3];
            }
            #pragma unroll
            for (int mt = 0; mt < 2; mt++)
                #pragma unroll
                for (int nt = 0; nt < 4; nt++) {
                    mma_f16(acc[mt][nt], af[mt], bfh[nt]);
                    mma_f16(acc[mt][nt], af[mt], bfl[nt]);
                }
        }
        __syncthreads();
    }

    float bb[4][2];
    #pragma unroll
    for (int nt = 0; nt < 4; nt++) {
        const int col = n0 + nw + nt * 8 + (lane & 3) * 2;
        bb[nt][0] = bias[col];
        bb[nt][1] = bias[col + 1];
    }
    #pragma unroll
    for (int mt = 0; mt < 2; mt++) {
        const int row0 = m0 + mw + mt * 16 + (lane >> 2);
        #pragma unroll
        for (int nt = 0; nt < 4; nt++) {
            const int col = n0 + nw + nt * 8 + (lane & 3) * 2;
            float v0 = (acc[mt][nt][0] + bb[nt][0]) * cscale;
            float v1 = (acc[mt][nt][1] + bb[nt][1]) * cscale;
            float v2 = (acc[mt][nt][2] + bb[nt][0]) * cscale;
            float v3 = (acc[mt][nt][3] + bb[nt][1]) * cscale;
            const size_t i0 = (size_t)row0 * DD + col;
            const size_t i1 = (size_t)(row0 + 8) * DD + col;
            if (outfmt < 0) {
                *(float2*)&Cf[i0] = float2{v0, v1};
                *(float2*)&Cf[i1] = float2{v2, v3};
            } else if (outfmt == 0) {
                uint32_t h0 = cvt_bf16x2(v0, v1), h1 = cvt_bf16x2(v2, v3);
                float r0 = v0 - __uint_as_float(h0 << 16);
                float r1 = v1 - __uint_as_float(h0 & 0xffff0000u);
                float r2 = v2 - __uint_as_float(h1 << 16);
                float r3 = v3 - __uint_as_float(h1 & 0xffff0000u);
                ((uint32_t*)Ch)[i0/2] = h0;  ((uint32_t*)Ch)[i1/2] = h1;
                ((uint32_t*)Cl)[i0/2] = cvt_bf16x2(r0, r1);
                ((uint32_t*)Cl)[i1/2] = cvt_bf16x2(r2, r3);
            } else {
                uint32_t h0 = cvt_f16x2(v0, v1), h1 = cvt_f16x2(v2, v3);
                float r0 = v0 - f16lo_f(h0), r1 = v1 - f16hi_f(h0);
                float r2 = v2 - f16lo_f(h1), r3 = v3 - f16hi_f(h1);
                ((uint32_t*)Ch)[i0/2] = h0;  ((uint32_t*)Ch)[i1/2] = h1;
                ((uint32_t*)Cl)[i0/2] = cvt_f16x2(r0, r1);
                ((uint32_t*)Cl)[i1/2] = cvt_f16x2(r2, r3);
            }
        }
    }
}

// Output projection (fp32 out)
__global__ __launch_bounds__(256, 2) void gemm_o(
    const __half* __restrict__ A,
    const __half* __restrict__ Bh, const __half* __restrict__ Bl,
    const float* __restrict__ bias, float* __restrict__ Cf)
{
    extern __shared__ char smem[];
    gemm_f16_core(A, Bh, Bl, bias, Cf, nullptr, nullptr, -1, 1.0f, smem);
}

// Fused Q/K/V projections: blockIdx.z = job.
struct GemmJobsP {
    const __half *A[3], *Bh[3], *Bl[3];
    const float* bias[3];
    void *Ch[3], *Cl[3];
    float scale[3];
    int outfmt[3];
};
__global__ __launch_bounds__(256, 2) void gemm_p3(GemmJobsP j)
{
    extern __shared__ char smem[];
    const int z = blockIdx.z;
    gemm_f16_core(j.A[z], j.Bh[z], j.Bl[z], j.bias[z],
                  nullptr, j.Ch[z], j.Cl[z], j.outfmt[z], j.scale[z], smem);
}

// ---------------------------------------------------------------------------
// Tensor flash attention (unchanged from R12): 128-thread CTAs, occ 2.
// QK^T bf16 3-term (Q pre-scaled); PV fp16 2-term; Oh = fp16(O).
// ---------------------------------------------------------------------------
#define AST 2
#define ASTAGE 33792u
#define AQ_SZ 32768u
#define AT_SMEM (AQ_SZ + AST*ASTAGE)

__global__ __launch_bounds__(128, 2) void attn_mma(
    const float* __restrict__ madd,
    const __nv_bfloat16* __restrict__ Qh_g, const __nv_bfloat16* __restrict__ Ql_g,
    const __nv_bfloat16* __restrict__ Kh_g, const __nv_bfloat16* __restrict__ Kl_g,
    const __half* __restrict__ Vh_g, const __half* __restrict__ Vl_g,
    __half* __restrict__ Oh_g)
{
    extern __shared__ char smem[];
    const uint32_t sb = smem_u32(smem);
    const int t = threadIdx.x, lane = t & 31, wid = t >> 5;
    const int b = blockIdx.z, h = blockIdx.y, q0 = blockIdx.x * 128;
    const int g = lane >> 3, r8 = lane & 7;

    const size_t boff = (size_t)b * SS * DD + (size_t)h * DHD;
    const __nv_bfloat16* Qhb = Qh_g + boff;
    const __nv_bfloat16* Qlb = Ql_g + boff;
    const char* kvsrc[4] = {
        (const char*)(Kh_g + boff), (const char*)(Kl_g + boff),
        (const char*)(Vh_g + boff), (const char*)(Vl_g + boff)
    };

    #pragma unroll
    for (int i = 0; i < 16; i++) {
        const int prec = i >> 3;
        const int idx = t + (i & 7) * 128;
        const int row = idx >> 3, sub = idx & 7;
        const uint32_t doff = (prec ? 16384u : 0u)
                            + sw128((uint32_t)row * 128 + (uint32_t)sub * 16);
        cp16(sb + doff,
             (prec ? Qlb : Qhb) + (size_t)(q0 + row) * DD + sub * 8);
    }
    CP_COMMIT();

    auto issue_kv = [&](int ch) {
        const int j0 = ch * 64;
        const uint32_t base = sb + AQ_SZ + (uint32_t)(ch % AST) * ASTAGE;
        #pragma unroll
        for (int i = 0; i < 16; i++) {
            const int tile = i >> 2;
            const int idx = t + (i & 3) * 128;
            const int row = idx >> 3, sub = idx & 7;
            const char* src = kvsrc[tile]
                + ((size_t)(j0 + row) * DD + sub * 8) * 2;
            cp16(base + (uint32_t)tile * 8192u
                      + sw128((uint32_t)row * 128 + (uint32_t)sub * 16), src);
        }
        if (t < 16)
            cp16(base + 32768u + (uint32_t)t * 16, madd + b * SS + j0 + t * 4);
        CP_COMMIT();
    };

    issue_kv(0);
    issue_kv(1);
    CP_WAIT(2);
    __syncthreads();

    uint32_t aoff[2];
    #pragma unroll
    for (int mt = 0; mt < 2; mt++)
        aoff[mt] = (uint32_t)(wid*32 + mt*16 + (g & 1)*8 + r8) * 128
                 + (uint32_t)(g >> 1) * 16;

    uint32_t qf[2][4][4];
    #pragma unroll
    for (int mt = 0; mt < 2; mt++)
        #pragma unroll
        for (int ks = 0; ks < 4; ks++)
            ldsm4(qf[mt][ks], sb + sw128(aoff[mt] + ks*32));

    float o[2][8][4];
    #pragma unroll
    for (int mt = 0; mt < 2; mt++)
        #pragma unroll
        for (int nt = 0; nt < 8; nt++)
            #pragma unroll
            for (int c = 0; c < 4; c++) o[mt][nt][c] = 0.0f;
    float mA[2] = {-1e30f, -1e30f}, mB[2] = {-1e30f, -1e30f};
    float lA[2] = {0.0f, 0.0f},     lB[2] = {0.0f, 0.0f};

    const uint32_t kboff = (uint32_t)((g >> 1)*8 + r8) * 128 + (uint32_t)(g & 1)*16;
    const uint32_t vboff = (uint32_t)((g & 1)*8 + r8) * 128 + (uint32_t)(g >> 1)*16;

    const int NKT = SS / 64;
    for (int ch = 0; ch < NKT; ch++) {
        CP_WAIT(1);
        __syncthreads();

        const uint32_t base = sb + AQ_SZ + (uint32_t)(ch % AST) * ASTAGE;
        const uint32_t sKh = base, sKl = base + 8192u;
        const uint32_t sVh = base + 16384u, sVl = base + 24576u;
        const float* maskS = (const float*)(smem + AQ_SZ
                             + (uint32_t)(ch % AST) * ASTAGE + 32768u);

        float s[2][8][4];
        #pragma unroll
        for (int mt = 0; mt < 2; mt++)
            #pragma unroll
            for (int nt = 0; nt < 8; nt++)
                #pragma unroll
                for (int c = 0; c < 4; c++) s[mt][nt][c] = 0.0f;

        #pragma unroll
        for (int ks = 0; ks < 4; ks++) {
            uint32_t qlf[2][4];
            ldsm4(qlf[0], sb + 16384u + sw128(aoff[0] + ks*32));
            ldsm4(qlf[1], sb + 16384u + sw128(aoff[1] + ks*32));
            #pragma unroll
            for (int nq = 0; nq < 4; nq++) {
                uint32_t bh[4], bl[4];
                const uint32_t off = kboff + (uint32_t)nq*2048 + (uint32_t)ks*32;
                ldsm4(bh, sKh + sw128(off));
                ldsm4(bl, sKl + sw128(off));
                #pragma unroll
                for (int mt = 0; mt < 2; mt++) {
                    mma_bf16(s[mt][nq*2],   qf[mt][ks], bh);
                    mma_bf16(s[mt][nq*2],   qf[mt][ks], bl);
                    mma_bf16(s[mt][nq*2],   qlf[mt],    bh);
                    mma_bf16(s[mt][nq*2+1], qf[mt][ks], bh + 2);
                    mma_bf16(s[mt][nq*2+1], qf[mt][ks], bl + 2);
                    mma_bf16(s[mt][nq*2+1], qlf[mt],    bh + 2);
                }
            }
        }

        const int mbase = (lane & 3) * 2;
        #pragma unroll
        for (int mt = 0; mt < 2; mt++) {
            #pragma unroll
            for (int nt = 0; nt < 8; nt++) {
                float2 mk = *(float2*)&maskS[mbase + nt*8];
                s[mt][nt][0] += mk.x;
                s[mt][nt][1] += mk.y;
                s[mt][nt][2] += mk.x;
                s[mt][nt][3] += mk.y;
            }

            float mxA = s[mt][0][0], mxB = s[mt][0][2];
            #pragma unroll
            for (int nt = 0; nt < 8; nt++) {
                mxA = fmaxf(mxA, fmaxf(s[mt][nt][0], s[mt][nt][1]));
                mxB = fmaxf(mxB, fmaxf(s[mt][nt][2], s[mt][nt][3]));
            }
            mxA = fmaxf(mxA, __shfl_xor_sync(0xffffffffu, mxA, 1));
            mxA = fmaxf(mxA, __shfl_xor_sync(0xffffffffu, mxA, 2));
            mxB = fmaxf(mxB, __shfl_xor_sync(0xffffffffu, mxB, 1));
            mxB = fmaxf(mxB, __shfl_xor_sync(0xffffffffu, mxB, 2));
            const float mnA = fmaxf(mA[mt], mxA), mnB = fmaxf(mB[mt], mxB);
            const float scA = __expf(mA[mt] - mnA), scB = __expf(mB[mt] - mnB);
            mA[mt] = mnA; mB[mt] = mnB;

            float sumA = 0.0f, sumB = 0.0f;
            #pragma unroll
            for (int nt = 0; nt < 8; nt++) {
                s[mt][nt][0] = __expf(s[mt][nt][0] - mnA);
                s[mt][nt][1] = __expf(s[mt][nt][1] - mnA);
                s[mt][nt][2] = __expf(s[mt][nt][2] - mnB);
                s[mt][nt][3] = __expf(s[mt][nt][3] - mnB);
                sumA += s[mt][nt][0] + s[mt][nt][1];
                sumB += s[mt][nt][2] + s[mt][nt][3];
            }
            sumA += __shfl_xor_sync(0xffffffffu, sumA, 1);
            sumA += __shfl_xor_sync(0xffffffffu, sumA, 2);
            sumB += __shfl_xor_sync(0xffffffffu, sumB, 1);
            sumB += __shfl_xor_sync(0xffffffffu, sumB, 2);
            lA[mt] = lA[mt] * scA + sumA;
            lB[mt] = lB[mt] * scB + sumB;
            #pragma unroll
            for (int nt = 0; nt < 8; nt++) {
                o[mt][nt][0] *= scA; o[mt][nt][1] *= scA;
                o[mt][nt][2] *= scB; o[mt][nt][3] *= scB;
            }
        }

        #pragma unroll
        for (int ks = 0; ks < 4; ks++) {
            uint32_t ph[2][4];
            #pragma unroll
            for (int mt = 0; mt < 2; mt++)
                #pragma unroll
                for (int half = 0; half < 2; half++) {
                    const int nt = ks*2 + half;
                    ph[mt][half*2]   = cvt_f16x2(s[mt][nt][0], s[mt][nt][1]);
                    ph[mt][half*2+1] = cvt_f16x2(s[mt][nt][2], s[mt][nt][3]);
                }
            #pragma unroll
            for (int nq = 0; nq < 4; nq++) {
                uint32_t vh[4], vl[4];
                const uint32_t off = vboff + (uint32_t)ks*2048 + (uint32_t)nq*32;
                ldsm4t(vh, sVh + sw128(off));
                ldsm4t(vl, sVl + sw128(off));
                #pragma unroll
                for (int mt = 0; mt < 2; mt++) {
                    mma_f16(o[mt][nq*2],   ph[mt], vh);
                    mma_f16(o[mt][nq*2],   ph[mt], vl);
                    mma_f16(o[mt][nq*2+1], ph[mt], vh + 2);
                    mma_f16(o[mt][nq*2+1], ph[mt], vl + 2);
                }
            }
        }

        __syncthreads();
        if (ch + 2 < NKT) issue_kv(ch + 2);
    }

    #pragma unroll
    for (int mt = 0; mt < 2; mt++) {
        const float invA = 1.0f / lA[mt], invB = 1.0f / lB[mt];
        const int rowA = q0 + wid*32 + mt*16 + (lane >> 2);
        #pragma unroll
        for (int nt = 0; nt < 8; nt++) {
            const int col = h*DHD + nt*8 + (lane & 3)*2;
            const size_t r0 = ((size_t)b*SS + rowA) * DD + col;
            const size_t r1 = ((size_t)b*SS + rowA + 8) * DD + col;
            *(uint32_t*)&Oh_g[r0] = cvt_f16x2(o[mt][nt][0]*invA, o[mt][nt][1]*invA);
            *(uint32_t*)&Oh_g[r1] = cvt_f16x2(o[mt][nt][2]*invB, o[mt][nt][3]*invB);
        }
    }
}

// ---------------------------------------------------------------------------
// Launch
// ---------------------------------------------------------------------------
extern "C" void kernel_launch(void* const* d_in, const int* in_sizes, int n_in,
                              void* d_out, int out_size)
{
    const float* x_q = (const float*)d_in[0];
    const float* x_k = (const float*)d_in[1];
    const float* x_v = (const float*)d_in[2];
    const void*  mask = d_in[3];
    const float* Wq = (const float*)d_in[4];
    const float* bq = (const float*)d_in[5];
    const float* Wk = (const float*)d_in[6];
    const float* bk = (const float*)d_in[7];
    const float* Wv = (const float*)d_in[8];
    const float* bv = (const float*)d_in[9];
    const float* Wo = (const float*)d_in[10];
    const float* bo = (const float*)d_in[11];
    float* out = (float*)d_out;

    float* Mp;
    __half *Xq,*Xk,*Xv;
    __half *Wqh,*Wql,*Wkh,*Wkl,*Wvh,*Wvl,*Woh,*Wol,*Vh,*Vl,*Oh;
    __nv_bfloat16 *Qh,*Ql,*Kh,*Kl;
    cudaGetSymbolAddress((void**)&Mp, g_maskadd);
    cudaGetSymbolAddress((void**)&Xq, g_Xq);
    cudaGetSymbolAddress((void**)&Xk, g_Xk);
    cudaGetSymbolAddress((void**)&Xv, g_Xv);
    cudaGetSymbolAddress((void**)&Wqh, g_Wqh); cudaGetSymbolAddress((void**)&Wql, g_Wql);
    cudaGetSymbolAddress((void**)&Wkh, g_Wkh); cudaGetSymbolAddress((void**)&Wkl, g_Wkl);
    cudaGetSymbolAddress((void**)&Wvh, g_Wvh); cudaGetSymbolAddress((void**)&Wvl, g_Wvl);
    cudaGetSymbolAddress((void**)&Woh, g_Woh); cudaGetSymbolAddress((void**)&Wol, g_Wol);
    cudaGetSymbolAddress((void**)&Qh, g_Qh);   cudaGetSymbolAddress((void**)&Ql, g_Ql);
    cudaGetSymbolAddress((void**)&Kh, g_Kh);   cudaGetSymbolAddress((void**)&Kl, g_Kl);
    cudaGetSymbolAddress((void**)&Vh, g_Vh);   cudaGetSymbolAddress((void**)&Vl, g_Vl);
    cudaGetSymbolAddress((void**)&Oh, g_Oh);

    SplitJobs7 jobs;
    jobs.src[0] = x_q; jobs.hi[0] = Xq;  jobs.lo[0] = nullptr;
    jobs.src[1] = x_k; jobs.hi[1] = Xk;  jobs.lo[1] = nullptr;
    jobs.src[2] = x_v; jobs.hi[2] = Xv;  jobs.lo[2] = nullptr;
    jobs.src[3] = Wq;  jobs.hi[3] = Wqh; jobs.lo[3] = Wql;
    jobs.src[4] = Wk;  jobs.hi[4] = Wkh; jobs.lo[4] = Wkl;
    jobs.src[5] = Wv;  jobs.hi[5] = Wvh; jobs.lo[5] = Wvl;
    jobs.src[6] = Wo;  jobs.hi[6] = Woh; jobs.lo[6] = Wol;
    jobs.mask_raw = mask; jobs.madd = Mp;

    GemmJobsP gj;
    gj.A[0] = Xq; gj.Bh[0] = Wqh; gj.Bl[0] = Wql;
    gj.bias[0] = bq; gj.Ch[0] = Qh; gj.Cl[0] = Ql;
    gj.scale[0] = 0.125f; gj.outfmt[0] = 0;
    gj.A[1] = Xk; gj.Bh[1] = Wkh; gj.Bl[1] = Wkl;
    gj.bias[1] = bk; gj.Ch[1] = Kh; gj.Cl[1] = Kl;
    gj.scale[1] = 1.0f; gj.outfmt[1] = 0;
    gj.A[2] = Xv; gj.Bh[2] = Wvh; gj.Bl[2] = Wvl;
    gj.bias[2] = bv; gj.Ch[2] = Vh; gj.Cl[2] = Vl;
    gj.scale[2] = 1.0f; gj.outfmt[2] = 2;

    cudaFuncSetAttribute(attn_mma,
                         cudaFuncAttributeMaxDynamicSharedMemorySize, AT_SMEM);
    cudaFuncSetAttribute(gemm_p3,
                         cudaFuncAttributeMaxDynamicSharedMemorySize, GEMMO_SMEM);
    cudaFuncSetAttribute(gemm_o,
                         cudaFuncAttributeMaxDynamicSharedMemorySize, GEMMO_SMEM);

    split_all<<<(NTOT + 255)/256, 256>>>(jobs);

    gemm_p3<<<dim3(DD/64, MTOT/128, 3), 256, GEMMO_SMEM>>>(gj);

    attn_mma<<<dim3(SS/128, HH, BB), 128, AT_SMEM>>>(Mp, Qh, Ql, Kh, Kl,
                                                     Vh, Vl, Oh);

    gemm_o<<<dim3(DD/64, MTOT/128), 256, GEMMO_SMEM>>>(Oh, Woh, Wol, bo, out);
}

// round 17
// speedup vs baseline: 9.8548x; 1.3487x over previous
#include <cuda_runtime.h>
#include <cuda_bf16.h>
#include <cuda_fp16.h>
#include <cstdint>

// Problem constants
#define BB 2
#define SS 2048
#define DD 1024
#define HH 16
#define DHD 64
#define MTOT (BB*SS)   // 4096
#define GK 1024        // GEMM K

// Scratch (allocation-free rule: __device__ globals)
__device__ float g_maskadd[BB*SS];
__device__ __half g_Xq[MTOT*GK], g_Xk[MTOT*GK], g_Xv[MTOT*GK];   // fp16 single
__device__ __half g_Wqh[DD*GK], g_Wql[DD*GK];
__device__ __half g_Wkh[DD*GK], g_Wkl[DD*GK];
__device__ __half g_Wvh[DD*GK], g_Wvl[DD*GK];
__device__ __half g_Woh[DD*GK], g_Wol[DD*GK];
__device__ __half g_Q[MTOT*DD];     // fp16 single (pre-scaled 0.125)
__device__ __half g_K[MTOT*DD];     // fp16 single
__device__ __half g_V[MTOT*DD];     // fp16 single
__device__ __half g_Oh[MTOT*DD];

// ---------------------------------------------------------------------------
// helpers
// ---------------------------------------------------------------------------
__device__ __forceinline__ uint32_t smem_u32(const void* p) {
    uint32_t a;
    asm("{ .reg .u64 t; cvta.to.shared.u64 t, %1; cvt.u32.u64 %0, t; }"
        : "=r"(a) : "l"(p));
    return a;
}
__device__ __forceinline__ void ldsm4(uint32_t* r, uint32_t addr) {
    asm volatile("ldmatrix.sync.aligned.m8n8.x4.shared.b16 {%0,%1,%2,%3}, [%4];"
                 : "=r"(r[0]), "=r"(r[1]), "=r"(r[2]), "=r"(r[3]) : "r"(addr));
}
__device__ __forceinline__ void ldsm4t(uint32_t* r, uint32_t addr) {
    asm volatile("ldmatrix.sync.aligned.m8n8.x4.trans.shared.b16 {%0,%1,%2,%3}, [%4];"
                 : "=r"(r[0]), "=r"(r[1]), "=r"(r[2]), "=r"(r[3]) : "r"(addr));
}
__device__ __forceinline__ void mma_f16(float* c, const uint32_t* a,
                                        const uint32_t* b) {
    asm volatile(
        "mma.sync.aligned.m16n8k16.row.col.f32.f16.f16.f32 "
        "{%0,%1,%2,%3}, {%4,%5,%6,%7}, {%8,%9}, {%0,%1,%2,%3};"
        : "+f"(c[0]), "+f"(c[1]), "+f"(c[2]), "+f"(c[3])
        : "r"(a[0]), "r"(a[1]), "r"(a[2]), "r"(a[3]), "r"(b[0]), "r"(b[1]));
}
__device__ __forceinline__ uint32_t cvt_f16x2(float lo, float hi) {
    uint32_t d;
    asm("cvt.rn.f16x2.f32 %0, %1, %2;" : "=r"(d) : "f"(hi), "f"(lo));
    return d;
}
__device__ __forceinline__ uint32_t sw128(uint32_t off) {
    return off ^ ((off >> 3) & 0x70);
}
__device__ __forceinline__ void cp16(uint32_t dst, const void* src) {
    asm volatile("cp.async.cg.shared.global [%0], [%1], 16;"
                 :: "r"(dst), "l"(src) : "memory");
}
#define CP_COMMIT() asm volatile("cp.async.commit_group;" ::: "memory")
#define CP_WAIT(n)  asm volatile("cp.async.wait_group %0;" :: "n"(n) : "memory")

// ---------------------------------------------------------------------------
// Fused prepass: X tensors -> fp16 single; weights -> fp16 hi/lo; mask.
// ---------------------------------------------------------------------------
struct SplitJobs7 {
    const float* src[7];
    void* hi[7];
    void* lo[7];     // null for jobs 0-2
    const void* mask_raw;
    float* madd;
};

#define NX4 (MTOT*GK/4)   // 1048576
#define NW4 (DD*GK/4)     // 262144
#define NSPLIT4 (3*NX4 + 4*NW4)
#define NTOT (NSPLIT4 + BB*SS)

__global__ void split_all(SplitJobs7 jobs)
{
    const int i = blockIdx.x * blockDim.x + threadIdx.x;
    if (i >= NSPLIT4) {
        const int idx = i - NSPLIT4;
        if (idx < BB * SS) {
            const unsigned* mw = (const unsigned*)jobs.mask_raw;
            bool is_int32 = true;
            #pragma unroll
            for (int k = 0; k < 64; k++)
                if (mw[k] > 1u) is_int32 = false;
            int m = is_int32 ? (int)mw[idx]
                             : (int)((const unsigned char*)jobs.mask_raw)[idx];
            jobs.madd[idx] = m ? 0.0f : -1e9f;
        }
        return;
    }
    int j, off;
    if (i < 3*NX4) { j = i / NX4; off = i - j*NX4; }
    else { int w = i - 3*NX4; j = 3 + w / NW4; off = w - (j-3)*NW4; }
    float4 v = ((const float4*)jobs.src[j])[off];
    __half h0 = __float2half_rn(v.x), h1 = __float2half_rn(v.y);
    __half h2 = __float2half_rn(v.z), h3 = __float2half_rn(v.w);
    __half2 hp0(h0, h1), hp1(h2, h3);
    uint2 hp{*(uint32_t*)&hp0, *(uint32_t*)&hp1};
    ((uint2*)jobs.hi[j])[off] = hp;
    if (j >= 3) {
        __half2 lp0(__float2half_rn(v.x - __half2float(h0)),
                    __float2half_rn(v.y - __half2float(h1)));
        __half2 lp1(__float2half_rn(v.z - __half2float(h2)),
                    __float2half_rn(v.w - __half2float(h3)));
        uint2 lp{*(uint32_t*)&lp0, *(uint32_t*)&lp1};
        ((uint2*)jobs.lo[j])[off] = lp;
    }
}

// ---------------------------------------------------------------------------
// fp16 2-term GEMM core: C = A @ (Bh+Bl)^T + bias.
// CTA 128x64, warp 32x32, K chunk 64, 3-stage. Stage 32KB: A 16K | Bh 8K | Bl 8K.
// outfmt: -1 = fp32, 3 = fp16 single.
// ---------------------------------------------------------------------------
#define OCH 16
#define OST 3
#define OSTAGE 32768u
#define GEMMO_SMEM (OST*OSTAGE)

__device__ __forceinline__ void gemm_f16_core(
    const __half* __restrict__ A,
    const __half* __restrict__ Bh, const __half* __restrict__ Bl,
    const float* __restrict__ bias, float* __restrict__ Cf,
    __half* __restrict__ Ch, int outfmt, float cscale, char* smem)
{
    const uint32_t sb = smem_u32(smem);
    const int t = threadIdx.x, lane = t & 31, wid = t >> 5;
    const int m0 = blockIdx.y * 128, n0 = blockIdx.x * 64;
    const int mw = (wid & 3) * 32, nw = (wid >> 2) * 32;
    const int g = lane >> 3, r8 = lane & 7;

    auto issue = [&](int ch) {
        const int k0 = ch * 64;
        const uint32_t abase = sb + (uint32_t)(ch % OST) * OSTAGE;
        #pragma unroll
        for (int i = 0; i < 4; i++) {
            const int idx = t + i * 256;
            const int row = idx >> 3, sub = idx & 7;
            cp16(abase + sw128((uint32_t)row * 128 + (uint32_t)sub * 16),
                 A + (size_t)(m0 + row) * GK + k0 + sub * 8);
        }
        #pragma unroll
        for (int i = 0; i < 2; i++) {
            const int idx = t + i * 256;
            const int row = idx >> 3, sub = idx & 7;
            const uint32_t doff = sw128((uint32_t)row * 128 + (uint32_t)sub * 16);
            cp16(abase + 16384u + doff,
                 Bh + (size_t)(n0 + row) * GK + k0 + sub * 8);
            cp16(abase + 24576u + doff,
                 Bl + (size_t)(n0 + row) * GK + k0 + sub * 8);
        }
        CP_COMMIT();
    };

    issue(0); issue(1);

    const uint32_t baseA_off = (uint32_t)(mw + (g & 1) * 8 + r8) * 128
                             + (uint32_t)(g >> 1) * 16;
    const uint32_t baseB_off = (uint32_t)(nw + (g >> 1) * 8 + r8) * 128
                             + (uint32_t)(g & 1) * 16;

    float acc[2][4][4];
    #pragma unroll
    for (int mt = 0; mt < 2; mt++)
        #pragma unroll
        for (int nt = 0; nt < 4; nt++)
            #pragma unroll
            for (int c = 0; c < 4; c++) acc[mt][nt][c] = 0.0f;

    for (int ch = 0; ch < OCH; ch++) {
        CP_WAIT(1);
        __syncthreads();
        if (ch + 2 < OCH) issue(ch + 2);

        const uint32_t sA = sb + (uint32_t)(ch % OST) * OSTAGE;
        const uint32_t sBh = sA + 16384u, sBl = sA + 24576u;

        #pragma unroll
        for (int ks = 0; ks < 4; ks++) {
            uint32_t af[2][4];
            #pragma unroll
            for (int mt = 0; mt < 2; mt++)
                ldsm4(af[mt], sA + sw128(baseA_off + (uint32_t)mt*2048
                                         + (uint32_t)ks*32));
            uint32_t bfh[4][2], bfl[4][2];
            #pragma unroll
            for (int np = 0; np < 2; np++) {
                uint32_t q[4];
                const uint32_t off = baseB_off + (uint32_t)np*2048 + (uint32_t)ks*32;
                ldsm4(q, sBh + sw128(off));
                bfh[np*2][0] = q[0]; bfh[np*2][1] = q[1];
                bfh[np*2+1][0] = q[2]; bfh[np*2+1][1] = q[3];
                ldsm4(q, sBl + sw128(off));
                bfl[np*2][0] = q[0]; bfl[np*2][1] = q[1];
                bfl[np*2+1][0] = q[2]; bfl[np*2+1][1] = q[3];
            }
            #pragma unroll
            for (int mt = 0; mt < 2; mt++)
                #pragma unroll
                for (int nt = 0; nt < 4; nt++) {
                    mma_f16(acc[mt][nt], af[mt], bfh[nt]);
                    mma_f16(acc[mt][nt], af[mt], bfl[nt]);
                }
        }
        __syncthreads();
    }

    float bb[4][2];
    #pragma unroll
    for (int nt = 0; nt < 4; nt++) {
        const int col = n0 + nw + nt * 8 + (lane & 3) * 2;
        bb[nt][0] = bias[col];
        bb[nt][1] = bias[col + 1];
    }
    #pragma unroll
    for (int mt = 0; mt < 2; mt++) {
        const int row0 = m0 + mw + mt * 16 + (lane >> 2);
        #pragma unroll
        for (int nt = 0; nt < 4; nt++) {
            const int col = n0 + nw + nt * 8 + (lane & 3) * 2;
            float v0 = (acc[mt][nt][0] + bb[nt][0]) * cscale;
            float v1 = (acc[mt][nt][1] + bb[nt][1]) * cscale;
            float v2 = (acc[mt][nt][2] + bb[nt][0]) * cscale;
            float v3 = (acc[mt][nt][3] + bb[nt][1]) * cscale;
            const size_t i0 = (size_t)row0 * DD + col;
            const size_t i1 = (size_t)(row0 + 8) * DD + col;
            if (outfmt < 0) {
                *(float2*)&Cf[i0] = float2{v0, v1};
                *(float2*)&Cf[i1] = float2{v2, v3};
            } else {
                *(uint32_t*)&Ch[i0] = cvt_f16x2(v0, v1);
                *(uint32_t*)&Ch[i1] = cvt_f16x2(v2, v3);
            }
        }
    }
}

// Output projection (fp32 out)
__global__ __launch_bounds__(256, 2) void gemm_o(
    const __half* __restrict__ A,
    const __half* __restrict__ Bh, const __half* __restrict__ Bl,
    const float* __restrict__ bias, float* __restrict__ Cf)
{
    extern __shared__ char smem[];
    gemm_f16_core(A, Bh, Bl, bias, Cf, nullptr, -1, 1.0f, smem);
}

// Fused Q/K/V projections: blockIdx.z = job; all emit fp16 single.
struct GemmJobsP {
    const __half *A[3], *Bh[3], *Bl[3];
    const float* bias[3];
    __half* Ch[3];
    float scale[3];
};
__global__ __launch_bounds__(256, 2) void gemm_p3(GemmJobsP j)
{
    extern __shared__ char smem[];
    const int z = blockIdx.z;
    gemm_f16_core(j.A[z], j.Bh[z], j.Bl[z], j.bias[z],
                  nullptr, j.Ch[z], 3, j.scale[z], smem);
}

// ---------------------------------------------------------------------------
// Tensor flash attention v4: all-fp16-single operands.
// 128-thread CTAs (4 warps x 32 rows), occ 2. Q pre-scaled 0.125.
// QK^T: 1-term fp16; PV: 1-term fp16 (P fp16, V fp16). Oh = fp16(O).
// Q region 16KB; stage = K 8K | V 8K | mask 256 -> 16640B, 2 stages.
// ---------------------------------------------------------------------------
#define AST 2
#define ASTAGE 16640u
#define AQ_SZ 16384u
#define AT_SMEM (AQ_SZ + AST*ASTAGE)   // 49664

__global__ __launch_bounds__(128, 2) void attn_mma(
    const float* __restrict__ madd,
    const __half* __restrict__ Q_g, const __half* __restrict__ K_g,
    const __half* __restrict__ V_g, __half* __restrict__ Oh_g)
{
    extern __shared__ char smem[];
    const uint32_t sb = smem_u32(smem);
    const int t = threadIdx.x, lane = t & 31, wid = t >> 5;
    const int b = blockIdx.z, h = blockIdx.y, q0 = blockIdx.x * 128;
    const int g = lane >> 3, r8 = lane & 7;

    const size_t boff = (size_t)b * SS * DD + (size_t)h * DHD;
    const __half* Qb = Q_g + boff;
    const __half* Kb = K_g + boff;
    const __half* Vb = V_g + boff;

    // Q load: 128 rows x 64 f16 = 16KB
    #pragma unroll
    for (int i = 0; i < 8; i++) {
        const int idx = t + i * 128;
        const int row = idx >> 3, sub = idx & 7;
        cp16(sb + sw128((uint32_t)row * 128 + (uint32_t)sub * 16),
             Qb + (size_t)(q0 + row) * DD + sub * 8);
    }
    CP_COMMIT();

    auto issue_kv = [&](int ch) {
        const int j0 = ch * 64;
        const uint32_t base = sb + AQ_SZ + (uint32_t)(ch % AST) * ASTAGE;
        #pragma unroll
        for (int i = 0; i < 8; i++) {
            const int tile = i >> 2;
            const int idx = t + (i & 3) * 128;
            const int row = idx >> 3, sub = idx & 7;
            const __half* src = (tile == 0 ? Kb : Vb)
                + (size_t)(j0 + row) * DD + sub * 8;
            cp16(base + (uint32_t)tile * 8192u
                      + sw128((uint32_t)row * 128 + (uint32_t)sub * 16), src);
        }
        if (t < 16)
            cp16(base + 16384u + (uint32_t)t * 16, madd + b * SS + j0 + t * 4);
        CP_COMMIT();
    };

    issue_kv(0);
    issue_kv(1);
    CP_WAIT(2);
    __syncthreads();

    uint32_t aoff[2];
    #pragma unroll
    for (int mt = 0; mt < 2; mt++)
        aoff[mt] = (uint32_t)(wid*32 + mt*16 + (g & 1)*8 + r8) * 128
                 + (uint32_t)(g >> 1) * 16;

    uint32_t qf[2][4][4];
    #pragma unroll
    for (int mt = 0; mt < 2; mt++)
        #pragma unroll
        for (int ks = 0; ks < 4; ks++)
            ldsm4(qf[mt][ks], sb + sw128(aoff[mt] + ks*32));

    float o[2][8][4];
    #pragma unroll
    for (int mt = 0; mt < 2; mt++)
        #pragma unroll
        for (int nt = 0; nt < 8; nt++)
            #pragma unroll
            for (int c = 0; c < 4; c++) o[mt][nt][c] = 0.0f;
    float mA[2] = {-1e30f, -1e30f}, mB[2] = {-1e30f, -1e30f};
    float lA[2] = {0.0f, 0.0f},     lB[2] = {0.0f, 0.0f};

    const uint32_t kboff = (uint32_t)((g >> 1)*8 + r8) * 128 + (uint32_t)(g & 1)*16;
    const uint32_t vboff = (uint32_t)((g & 1)*8 + r8) * 128 + (uint32_t)(g >> 1)*16;

    const int NKT = SS / 64;   // 32
    for (int ch = 0; ch < NKT; ch++) {
        CP_WAIT(1);
        __syncthreads();

        const uint32_t base = sb + AQ_SZ + (uint32_t)(ch % AST) * ASTAGE;
        const uint32_t sK = base, sV = base + 8192u;
        const float* maskS = (const float*)(smem + AQ_SZ
                             + (uint32_t)(ch % AST) * ASTAGE + 16384u);

        // ---- QK^T: fp16 single x single
        float s[2][8][4];
        #pragma unroll
        for (int mt = 0; mt < 2; mt++)
            #pragma unroll
            for (int nt = 0; nt < 8; nt++)
                #pragma unroll
                for (int c = 0; c < 4; c++) s[mt][nt][c] = 0.0f;

        #pragma unroll
        for (int ks = 0; ks < 4; ks++) {
            #pragma unroll
            for (int nq = 0; nq < 4; nq++) {
                uint32_t kf[4];
                ldsm4(kf, sK + sw128(kboff + (uint32_t)nq*2048 + (uint32_t)ks*32));
                #pragma unroll
                for (int mt = 0; mt < 2; mt++) {
                    mma_f16(s[mt][nq*2],   qf[mt][ks], kf);
                    mma_f16(s[mt][nq*2+1], qf[mt][ks], kf + 2);
                }
            }
        }

        // ---- mask + online softmax
        const int mbase = (lane & 3) * 2;
        #pragma unroll
        for (int mt = 0; mt < 2; mt++) {
            #pragma unroll
            for (int nt = 0; nt < 8; nt++) {
                float2 mk = *(float2*)&maskS[mbase + nt*8];
                s[mt][nt][0] += mk.x;
                s[mt][nt][1] += mk.y;
                s[mt][nt][2] += mk.x;
                s[mt][nt][3] += mk.y;
            }

            float mxA = s[mt][0][0], mxB = s[mt][0][2];
            #pragma unroll
            for (int nt = 0; nt < 8; nt++) {
                mxA = fmaxf(mxA, fmaxf(s[mt][nt][0], s[mt][nt][1]));
                mxB = fmaxf(mxB, fmaxf(s[mt][nt][2], s[mt][nt][3]));
            }
            mxA = fmaxf(mxA, __shfl_xor_sync(0xffffffffu, mxA, 1));
            mxA = fmaxf(mxA, __shfl_xor_sync(0xffffffffu, mxA, 2));
            mxB = fmaxf(mxB, __shfl_xor_sync(0xffffffffu, mxB, 1));
            mxB = fmaxf(mxB, __shfl_xor_sync(0xffffffffu, mxB, 2));
            const float mnA = fmaxf(mA[mt], mxA), mnB = fmaxf(mB[mt], mxB);
            const float scA = __expf(mA[mt] - mnA), scB = __expf(mB[mt] - mnB);
            mA[mt] = mnA; mB[mt] = mnB;

            float sumA = 0.0f, sumB = 0.0f;
            #pragma unroll
            for (int nt = 0; nt < 8; nt++) {
                s[mt][nt][0] = __expf(s[mt][nt][0] - mnA);
                s[mt][nt][1] = __expf(s[mt][nt][1] - mnA);
                s[mt][nt][2] = __expf(s[mt][nt][2] - mnB);
                s[mt][nt][3] = __expf(s[mt][nt][3] - mnB);
                sumA += s[mt][nt][0] + s[mt][nt][1];
                sumB += s[mt][nt][2] + s[mt][nt][3];
            }
            sumA += __shfl_xor_sync(0xffffffffu, sumA, 1);
            sumA += __shfl_xor_sync(0xffffffffu, sumA, 2);
            sumB += __shfl_xor_sync(0xffffffffu, sumB, 1);
            sumB += __shfl_xor_sync(0xffffffffu, sumB, 2);
            lA[mt] = lA[mt] * scA + sumA;
            lB[mt] = lB[mt] * scB + sumB;
            #pragma unroll
            for (int nt = 0; nt < 8; nt++) {
                o[mt][nt][0] *= scA; o[mt][nt][1] *= scA;
                o[mt][nt][2] *= scB; o[mt][nt][3] *= scB;
            }
        }

        // ---- PV: fp16 single x single
        #pragma unroll
        for (int ks = 0; ks < 4; ks++) {
            uint32_t ph[2][4];
            #pragma unroll
            for (int mt = 0; mt < 2; mt++)
                #pragma unroll
                for (int half = 0; half < 2; half++) {
                    const int nt = ks*2 + half;
                    ph[mt][half*2]   = cvt_f16x2(s[mt][nt][0], s[mt][nt][1]);
                    ph[mt][half*2+1] = cvt_f16x2(s[mt][nt][2], s[mt][nt][3]);
                }
            #pragma unroll
            for (int nq = 0; nq < 4; nq++) {
                uint32_t vf[4];
                ldsm4t(vf, sV + sw128(vboff + (uint32_t)ks*2048 + (uint32_t)nq*32));
                #pragma unroll
                for (int mt = 0; mt < 2; mt++) {
                    mma_f16(o[mt][nq*2],   ph[mt], vf);
                    mma_f16(o[mt][nq*2+1], ph[mt], vf + 2);
                }
            }
        }

        __syncthreads();
        if (ch + 2 < NKT) issue_kv(ch + 2);
    }

    // ---- epilogue
    #pragma unroll
    for (int mt = 0; mt < 2; mt++) {
        const float invA = 1.0f / lA[mt], invB = 1.0f / lB[mt];
        const int rowA = q0 + wid*32 + mt*16 + (lane >> 2);
        #pragma unroll
        for (int nt = 0; nt < 8; nt++) {
            const int col = h*DHD + nt*8 + (lane & 3)*2;
            const size_t r0 = ((size_t)b*SS + rowA) * DD + col;
            const size_t r1 = ((size_t)b*SS + rowA + 8) * DD + col;
            *(uint32_t*)&Oh_g[r0] = cvt_f16x2(o[mt][nt][0]*invA, o[mt][nt][1]*invA);
            *(uint32_t*)&Oh_g[r1] = cvt_f16x2(o[mt][nt][2]*invB, o[mt][nt][3]*invB);
        }
    }
}

// ---------------------------------------------------------------------------
// Launch
// ---------------------------------------------------------------------------
extern "C" void kernel_launch(void* const* d_in, const int* in_sizes, int n_in,
                              void* d_out, int out_size)
{
    const float* x_q = (const float*)d_in[0];
    const float* x_k = (const float*)d_in[1];
    const float* x_v = (const float*)d_in[2];
    const void*  mask = d_in[3];
    const float* Wq = (const float*)d_in[4];
    const float* bq = (const float*)d_in[5];
    const float* Wk = (const float*)d_in[6];
    const float* bk = (const float*)d_in[7];
    const float* Wv = (const float*)d_in[8];
    const float* bv = (const float*)d_in[9];
    const float* Wo = (const float*)d_in[10];
    const float* bo = (const float*)d_in[11];
    float* out = (float*)d_out;

    float* Mp;
    __half *Xq,*Xk,*Xv;
    __half *Wqh,*Wql,*Wkh,*Wkl,*Wvh,*Wvl,*Woh,*Wol;
    __half *Qp,*Kp,*Vp,*Oh;
    cudaGetSymbolAddress((void**)&Mp, g_maskadd);
    cudaGetSymbolAddress((void**)&Xq, g_Xq);
    cudaGetSymbolAddress((void**)&Xk, g_Xk);
    cudaGetSymbolAddress((void**)&Xv, g_Xv);
    cudaGetSymbolAddress((void**)&Wqh, g_Wqh); cudaGetSymbolAddress((void**)&Wql, g_Wql);
    cudaGetSymbolAddress((void**)&Wkh, g_Wkh); cudaGetSymbolAddress((void**)&Wkl, g_Wkl);
    cudaGetSymbolAddress((void**)&Wvh, g_Wvh); cudaGetSymbolAddress((void**)&Wvl, g_Wvl);
    cudaGetSymbolAddress((void**)&Woh, g_Woh); cudaGetSymbolAddress((void**)&Wol, g_Wol);
    cudaGetSymbolAddress((void**)&Qp, g_Q);
    cudaGetSymbolAddress((void**)&Kp, g_K);
    cudaGetSymbolAddress((void**)&Vp, g_V);
    cudaGetSymbolAddress((void**)&Oh, g_Oh);

    SplitJobs7 jobs;
    jobs.src[0] = x_q; jobs.hi[0] = Xq;  jobs.lo[0] = nullptr;
    jobs.src[1] = x_k; jobs.hi[1] = Xk;  jobs.lo[1] = nullptr;
    jobs.src[2] = x_v; jobs.hi[2] = Xv;  jobs.lo[2] = nullptr;
    jobs.src[3] = Wq;  jobs.hi[3] = Wqh; jobs.lo[3] = Wql;
    jobs.src[4] = Wk;  jobs.hi[4] = Wkh; jobs.lo[4] = Wkl;
    jobs.src[5] = Wv;  jobs.hi[5] = Wvh; jobs.lo[5] = Wvl;
    jobs.src[6] = Wo;  jobs.hi[6] = Woh; jobs.lo[6] = Wol;
    jobs.mask_raw = mask; jobs.madd = Mp;

    GemmJobsP gj;
    gj.A[0] = Xq; gj.Bh[0] = Wqh; gj.Bl[0] = Wql;
    gj.bias[0] = bq; gj.Ch[0] = Qp; gj.scale[0] = 0.125f;
    gj.A[1] = Xk; gj.Bh[1] = Wkh; gj.Bl[1] = Wkl;
    gj.bias[1] = bk; gj.Ch[1] = Kp; gj.scale[1] = 1.0f;
    gj.A[2] = Xv; gj.Bh[2] = Wvh; gj.Bl[2] = Wvl;
    gj.bias[2] = bv; gj.Ch[2] = Vp; gj.scale[2] = 1.0f;

    cudaFuncSetAttribute(attn_mma,
                         cudaFuncAttributeMaxDynamicSharedMemorySize, AT_SMEM);
    cudaFuncSetAttribute(gemm_p3,
                         cudaFuncAttributeMaxDynamicSharedMemorySize, GEMMO_SMEM);
    cudaFuncSetAttribute(gemm_o,
                         cudaFuncAttributeMaxDynamicSharedMemorySize, GEMMO_SMEM);

    split_all<<<(NTOT + 255)/256, 256>>>(jobs);

    gemm_p3<<<dim3(DD/64, MTOT/128, 3), 256, GEMMO_SMEM>>>(gj);

    attn_mma<<<dim3(SS/128, HH, BB), 128, AT_SMEM>>>(Mp, Qp, Kp, Vp, Oh);

    gemm_o<<<dim3(DD/64, MTOT/128), 256, GEMMO_SMEM>>>(Oh, Woh, Wol, bo, out);
}